// round 6
// baseline (speedup 1.0000x reference)
#include <cuda_runtime.h>
#include <cuda_bf16.h>
#include <cstdint>

#define KB 16
#define KC 512
#define KCI 256
#define KN 1024

typedef __nv_bfloat16 bf16;
typedef __nv_bfloat162 bf162;

// ---------------- scratch (no allocs allowed -> __device__ globals) ----------
__device__ bf16 g_rgbT_h[(size_t)KB * KN * KC];   // [b][n][c] hi
__device__ bf16 g_rgbT_l[(size_t)KB * KN * KC];
__device__ bf16 g_flowT_h[(size_t)KB * KN * KC];
__device__ bf16 g_flowT_l[(size_t)KB * KN * KC];
__device__ bf16 g_wgr_h[KCI * KC], g_wgr_l[KCI * KC];
__device__ bf16 g_wgf_h[KCI * KC], g_wgf_l[KCI * KC];
__device__ bf16 g_wwr_h[KC * KCI], g_wwr_l[KC * KCI];
__device__ bf16 g_wwf_h[KC * KCI], g_wwf_l[KC * KCI];
__device__ bf16 g_re_h[(size_t)KB * KCI * KN], g_re_l[(size_t)KB * KCI * KN];
__device__ bf16 g_fe_h[(size_t)KB * KCI * KN], g_fe_l[(size_t)KB * KCI * KN];
__device__ bf16 g_reT_h[(size_t)KB * KN * KCI], g_reT_l[(size_t)KB * KN * KCI];
__device__ bf16 g_feT_h[(size_t)KB * KN * KCI], g_feT_l[(size_t)KB * KN * KCI];
__device__ float g_S[(size_t)KB * KN * KN];       // [b][n][m]
__device__ float g_S2[(size_t)KB * KN * KN];      // [b][m][n] = S^T
__device__ bf16 g_P_h[(size_t)KB * KN * KN], g_P_l[(size_t)KB * KN * KN];
__device__ bf16 g_P2_h[(size_t)KB * KN * KN], g_P2_l[(size_t)KB * KN * KN];
__device__ bf16 g_yrT_h[(size_t)KB * KN * KCI], g_yrT_l[(size_t)KB * KN * KCI];
__device__ bf16 g_yfT_h[(size_t)KB * KN * KCI], g_yfT_l[(size_t)KB * KN * KCI];
__device__ float g_t[2 * (size_t)KB * KC * KN];
__device__ float g_mean[2 * KC];
__device__ float g_rstd[2 * KC];
__device__ float g_rmax[KB * KN], g_rsum[KB * KN];
__device__ float g_cmax[KB * KN], g_csum[KB * KN];
__device__ float g_prm[KB * KN * 16], g_prs[KB * KN * 16];
__device__ float g_pcm[KB * KN * 8], g_pcs[KB * KN * 8];
__device__ float g_pbs[2 * KC * KB * 16], g_pbs2[2 * KC * KB * 16];

// ============================ helpers ========================================
__device__ __forceinline__ uint32_t smem_u32(const void* p) {
  uint32_t a;
  asm("{ .reg .u64 t; cvta.to.shared.u64 t, %1; cvt.u32.u64 %0, t; }"
      : "=r"(a) : "l"(p));
  return a;
}

#define CP16(dst, src)                                                         \
  asm volatile("cp.async.cg.shared.global [%0], [%1], 16;" ::"r"(dst),         \
               "l"(src))
#define CP_COMMIT() asm volatile("cp.async.commit_group;")
#define CP_WAIT1() asm volatile("cp.async.wait_group 1;")

__device__ __forceinline__ void ldm_x4(uint32_t addr, uint32_t& r0,
                                       uint32_t& r1, uint32_t& r2,
                                       uint32_t& r3) {
  asm volatile(
      "ldmatrix.sync.aligned.m8n8.x4.shared.b16 {%0,%1,%2,%3}, [%4];"
      : "=r"(r0), "=r"(r1), "=r"(r2), "=r"(r3) : "r"(addr));
}

__device__ __forceinline__ void mma_bf16(float* d, const uint32_t* a,
                                         const uint32_t* b) {
  asm volatile(
      "mma.sync.aligned.m16n8k16.row.col.f32.bf16.bf16.f32 "
      "{%0,%1,%2,%3}, {%4,%5,%6,%7}, {%8,%9}, {%0,%1,%2,%3};"
      : "+f"(d[0]), "+f"(d[1]), "+f"(d[2]), "+f"(d[3])
      : "r"(a[0]), "r"(a[1]), "r"(a[2]), "r"(a[3]), "r"(b[0]), "r"(b[1]));
}

__device__ __forceinline__ uint32_t sw_off(int row, int cb) {
  uint32_t off = (uint32_t)(row * 128 + cb);
  return off ^ ((off >> 3) & 0x70);
}

// split two fp32 -> (hi bf162, lo bf162)
__device__ __forceinline__ void split2(float x, float y, uint32_t& h,
                                       uint32_t& l) {
  bf162 hh = __floats2bfloat162_rn(x, y);
  bf162 ll = __floats2bfloat162_rn(x - __low2float(hh), y - __high2float(hh));
  h = *(uint32_t*)&hh;
  l = *(uint32_t*)&ll;
}

// smem: two 48KB buffers
#define BUF_STRIDE 49152
#define OFF_AHI 0
#define OFF_ALO 16384
#define OFF_BHI 32768
#define OFF_BLO 40960
#define SMEM_DYN (2 * BUF_STRIDE + 1024)

// stage one K=64 chunk: A 128 rows, B 64 rows, hi+lo -> swizzled smem
__device__ __forceinline__ void stage64(uint32_t sA_h, uint32_t sA_l,
                                        uint32_t sB_h, uint32_t sB_l,
                                        const bf16* Ah, const bf16* Al,
                                        int lda, const bf16* Bh,
                                        const bf16* Bl, int ldb, int tid,
                                        int k0) {
#pragma unroll
  for (int t = 0; t < 4; t++) {
    int g = tid + (t << 8);
    int r = g >> 3, q = g & 7;
    uint32_t o = sw_off(r, q << 4);
    const bf16* sa = Ah + (size_t)r * lda + k0 + (q << 3);
    const bf16* sb = Al + (size_t)r * lda + k0 + (q << 3);
    CP16(sA_h + o, sa);
    CP16(sA_l + o, sb);
  }
#pragma unroll
  for (int t = 0; t < 2; t++) {
    int g = tid + (t << 8);
    int r = g >> 3, q = g & 7;
    uint32_t o = sw_off(r, q << 4);
    const bf16* sa = Bh + (size_t)r * ldb + k0 + (q << 3);
    const bf16* sb = Bl + (size_t)r * ldb + k0 + (q << 3);
    CP16(sB_h + o, sa);
    CP16(sB_l + o, sb);
  }
}

// =============================================================================
// Pure bf16-pair HMMA GEMM: out tile [128 rows][64 cols].
//   D[r][c] = sum_k (Ah+Al)[r][k] * (Bh+Bl)[c][k]   (3-term split product)
//   v = D + (bias ? bias[r] : 0)
// Emitters: oNf (fp32 [r][c]), oTf (fp32 [c][r]), oN pair, oT pair,
//           softmax partials, BN partials.
// =============================================================================
__global__ __launch_bounds__(256, 2) void gemm_bf16(
    const bf16* __restrict__ Ahi, const bf16* __restrict__ Alo,
    unsigned long long sA, int lda,
    const bf16* __restrict__ Bhi, const bf16* __restrict__ Blo,
    unsigned long long sB, int ldb,
    const float* __restrict__ bias,
    float* __restrict__ oNf, unsigned long long soNf, int ldoNf,
    float* __restrict__ oTf, unsigned long long soTf, int ldoTf,
    bf16* __restrict__ oNhi, bf16* __restrict__ oNlo,
    unsigned long long soN, int ldoN,
    bf16* __restrict__ oThi, bf16* __restrict__ oTlo,
    unsigned long long soT, int ldoT,
    float* __restrict__ prm, float* __restrict__ prs,
    float* __restrict__ pcm, float* __restrict__ pcs,
    float* __restrict__ pbs, float* __restrict__ pbs2, int K) {
  extern __shared__ char s_dyn[];
  char* sb = (char*)(((uintptr_t)s_dyn + 1023) & ~(uintptr_t)1023);
  float* s_f32 = (float*)sb;  // epilogue staging [128][65]

  uint32_t uA_h[2], uA_l[2], uB_h[2], uB_l[2];
#pragma unroll
  for (int k = 0; k < 2; k++) {
    uA_h[k] = smem_u32(sb + k * BUF_STRIDE + OFF_AHI);
    uA_l[k] = smem_u32(sb + k * BUF_STRIDE + OFF_ALO);
    uB_h[k] = smem_u32(sb + k * BUF_STRIDE + OFF_BHI);
    uB_l[k] = smem_u32(sb + k * BUF_STRIDE + OFF_BLO);
  }

  int tid = threadIdx.x;
  int wid = tid >> 5, lane = tid & 31;
  int wr = wid & 3, wc = wid >> 2;
  int b = blockIdx.z;
  int i0 = blockIdx.y * 128;
  int n0 = blockIdx.x * 64;

  const bf16* Ah = Ahi + (size_t)b * sA + (size_t)i0 * lda;
  const bf16* Al = Alo + (size_t)b * sA + (size_t)i0 * lda;
  const bf16* Bh = Bhi + (size_t)b * sB + (size_t)n0 * ldb;
  const bf16* Bl = Blo + (size_t)b * sB + (size_t)n0 * ldb;

  int aRow = lane & 15, aCb = (lane >> 4) * 16;
  int bRow = ((lane >> 4) & 1) * 8 + (lane & 7);
  int bCb = ((lane >> 3) & 1) * 16;

  float acc[2][4][4];
#pragma unroll
  for (int mi = 0; mi < 2; mi++)
#pragma unroll
    for (int ni = 0; ni < 4; ni++)
#pragma unroll
      for (int e = 0; e < 4; e++) acc[mi][ni][e] = 0.f;

  int NC = K >> 6;
  // prologue: chunks 0,1
  stage64(uA_h[0], uA_l[0], uB_h[0], uB_l[0], Ah, Al, lda, Bh, Bl, ldb, tid, 0);
  CP_COMMIT();
  stage64(uA_h[1], uA_l[1], uB_h[1], uB_l[1], Ah, Al, lda, Bh, Bl, ldb, tid,
          64);
  CP_COMMIT();

  for (int ch = 0; ch < NC; ch++) {
    int cur = ch & 1;
    CP_WAIT1();
    __syncthreads();
#pragma unroll
    for (int ks = 0; ks < 4; ks++) {
      int kb = ks * 32;
      uint32_t ah[2][4], al[2][4], bh[2][4], bl[2][4];
#pragma unroll
      for (int mi = 0; mi < 2; mi++) {
        int r = wr * 32 + mi * 16 + aRow;
        uint32_t o = sw_off(r, kb + aCb);
        ldm_x4(uA_h[cur] + o, ah[mi][0], ah[mi][1], ah[mi][2], ah[mi][3]);
        ldm_x4(uA_l[cur] + o, al[mi][0], al[mi][1], al[mi][2], al[mi][3]);
      }
#pragma unroll
      for (int ng = 0; ng < 2; ng++) {
        int r = wc * 32 + ng * 16 + bRow;
        uint32_t o = sw_off(r, kb + bCb);
        ldm_x4(uB_h[cur] + o, bh[ng][0], bh[ng][1], bh[ng][2], bh[ng][3]);
        ldm_x4(uB_l[cur] + o, bl[ng][0], bl[ng][1], bl[ng][2], bl[ng][3]);
      }
#pragma unroll
      for (int mi = 0; mi < 2; mi++)
#pragma unroll
        for (int ni = 0; ni < 4; ni++) {
          float* d = acc[mi][ni];
          const uint32_t* bhp = &bh[ni >> 1][(ni & 1) * 2];
          const uint32_t* blp = &bl[ni >> 1][(ni & 1) * 2];
          mma_bf16(d, ah[mi], bhp);
          mma_bf16(d, ah[mi], blp);
          mma_bf16(d, al[mi], bhp);
        }
    }
    __syncthreads();
    if (ch + 2 < NC)
      stage64(uA_h[cur], uA_l[cur], uB_h[cur], uB_l[cur], Ah, Al, lda, Bh, Bl,
              ldb, tid, (ch + 2) << 6);
    CP_COMMIT();
  }

  // --------------------------- epilogue --------------------------------------
#pragma unroll
  for (int mi = 0; mi < 2; mi++) {
    int rl = wr * 32 + mi * 16 + (lane >> 2);
    float bv0 = bias ? __ldg(bias + i0 + rl) : 0.f;
    float bv1 = bias ? __ldg(bias + i0 + rl + 8) : 0.f;
#pragma unroll
    for (int ni = 0; ni < 4; ni++) {
      int c = wc * 32 + ni * 8 + 2 * (lane & 3);
      s_f32[rl * 65 + c] = acc[mi][ni][0] + bv0;
      s_f32[rl * 65 + c + 1] = acc[mi][ni][1] + bv0;
      s_f32[(rl + 8) * 65 + c] = acc[mi][ni][2] + bv1;
      s_f32[(rl + 8) * 65 + c + 1] = acc[mi][ni][3] + bv1;
    }
  }
  __syncthreads();

  if (oNf) {
    float* on = oNf + (size_t)b * soNf;
#pragma unroll
    for (int t = 0; t < 8; t++) {
      int idx = tid + (t << 8);
      int rr = idx >> 4, q = idx & 15;
      float4 v;
      v.x = s_f32[rr * 65 + q * 4 + 0];
      v.y = s_f32[rr * 65 + q * 4 + 1];
      v.z = s_f32[rr * 65 + q * 4 + 2];
      v.w = s_f32[rr * 65 + q * 4 + 3];
      *(float4*)(on + (size_t)(i0 + rr) * ldoNf + n0 + (q << 2)) = v;
    }
  }
  if (oTf) {
    float* ot = oTf + (size_t)b * soTf;
#pragma unroll
    for (int t = 0; t < 32; t++) {
      int idx = tid + (t << 8);
      int c = idx >> 7, rr = idx & 127;
      ot[(size_t)(n0 + c) * ldoTf + i0 + rr] = s_f32[rr * 65 + c];
    }
  }
  if (oNhi) {
    bf16* oh = oNhi + (size_t)b * soN;
    bf16* ol = oNlo + (size_t)b * soN;
#pragma unroll
    for (int t = 0; t < 8; t++) {
      int idx = tid + (t << 8);
      int rr = idx >> 4, q = idx & 15;
      uint32_t h0, l0, h1, l1;
      split2(s_f32[rr * 65 + q * 4 + 0], s_f32[rr * 65 + q * 4 + 1], h0, l0);
      split2(s_f32[rr * 65 + q * 4 + 2], s_f32[rr * 65 + q * 4 + 3], h1, l1);
      size_t base = (size_t)(i0 + rr) * ldoN + n0 + (q << 2);
      *(uint32_t*)(oh + base) = h0;
      *(uint32_t*)(oh + base + 2) = h1;
      *(uint32_t*)(ol + base) = l0;
      *(uint32_t*)(ol + base + 2) = l1;
    }
  }
  if (oThi) {
    bf16* oh = oThi + (size_t)b * soT;
    bf16* ol = oTlo + (size_t)b * soT;
#pragma unroll
    for (int t = 0; t < 8; t++) {
      int idx = tid + (t << 8);  // 2048: c = idx>>5, rq = (idx&31)*4
      int c = idx >> 5, rq = (idx & 31) << 2;
      uint32_t h0, l0, h1, l1;
      split2(s_f32[(rq + 0) * 65 + c], s_f32[(rq + 1) * 65 + c], h0, l0);
      split2(s_f32[(rq + 2) * 65 + c], s_f32[(rq + 3) * 65 + c], h1, l1);
      size_t base = (size_t)(n0 + c) * ldoT + i0 + rq;
      *(uint32_t*)(oh + base) = h0;
      *(uint32_t*)(oh + base + 2) = h1;
      *(uint32_t*)(ol + base) = l0;
      *(uint32_t*)(ol + base + 2) = l1;
    }
  }
  if (prm) {
    if (tid < 128) {
      int r = tid;
      float pm = -1e30f;
#pragma unroll 8
      for (int c = 0; c < 64; c++) pm = fmaxf(pm, s_f32[r * 65 + c]);
      float ps = 0.f;
#pragma unroll 8
      for (int c = 0; c < 64; c++) ps += __expf(s_f32[r * 65 + c] - pm);
      size_t o = (size_t)(b * KN + i0 + r) * gridDim.x + blockIdx.x;
      prm[o] = pm;
      prs[o] = ps;
    } else if (tid < 192) {
      int c = tid - 128;
      float pm = -1e30f;
#pragma unroll 8
      for (int r = 0; r < 128; r++) pm = fmaxf(pm, s_f32[r * 65 + c]);
      float ps = 0.f;
#pragma unroll 8
      for (int r = 0; r < 128; r++) ps += __expf(s_f32[r * 65 + c] - pm);
      size_t o = (size_t)(b * KN + n0 + c) * gridDim.y + blockIdx.y;
      pcm[o] = pm;
      pcs[o] = ps;
    }
  }
  if (pbs && tid < 128) {
    int r = tid;
    float s = 0.f, s2 = 0.f;
#pragma unroll 8
    for (int c = 0; c < 64; c++) {
      float v = s_f32[r * 65 + c];
      s += v;
      s2 += v * v;
    }
    size_t o = ((size_t)(i0 + r) * KB + b) * gridDim.x + blockIdx.x;
    pbs[o] = s;
    pbs2[o] = s2;
  }
}

// =============================================================================
// transpose + split: [C][N] fp32 -> [N][C] bf16 hi/lo
// =============================================================================
__global__ __launch_bounds__(256) void transpose_split(
    const float* __restrict__ in, bf16* __restrict__ oh,
    bf16* __restrict__ ol) {
  __shared__ float t[32][33];
  int b = blockIdx.z;
  const float* ib = in + (size_t)b * KC * KN;
  bf16* ohb = oh + (size_t)b * KC * KN;
  bf16* olb = ol + (size_t)b * KC * KN;
  int n0 = blockIdx.x * 32, c0 = blockIdx.y * 32;
  int x = threadIdx.x, y = threadIdx.y;
#pragma unroll
  for (int j = 0; j < 4; j++)
    t[y + 8 * j][x] = ib[(size_t)(c0 + y + 8 * j) * KN + n0 + x];
  __syncthreads();
#pragma unroll
  for (int j = 0; j < 4; j++) {
    float v = t[x][y + 8 * j];
    bf16 h = __float2bfloat16_rn(v);
    size_t o = (size_t)(n0 + y + 8 * j) * KC + c0 + x;
    ohb[o] = h;
    olb[o] = __float2bfloat16_rn(v - __bfloat162float(h));
  }
}

// =============================================================================
// convert 4 weight matrices (each 131072 elems) to hi/lo
// =============================================================================
__global__ __launch_bounds__(256) void convert_w(
    const float* __restrict__ s0, const float* __restrict__ s1,
    const float* __restrict__ s2, const float* __restrict__ s3) {
  int idx = blockIdx.x * 256 + threadIdx.x;
  int sel = idx >> 17, w = idx & 131071;
  const float* s = sel == 0 ? s0 : sel == 1 ? s1 : sel == 2 ? s2 : s3;
  bf16* h = sel == 0 ? g_wgr_h : sel == 1 ? g_wgf_h : sel == 2 ? g_wwr_h
                                                               : g_wwf_h;
  bf16* l = sel == 0 ? g_wgr_l : sel == 1 ? g_wgf_l : sel == 2 ? g_wwr_l
                                                               : g_wwf_l;
  float v = s[w];
  bf16 hh = __float2bfloat16_rn(v);
  h[w] = hh;
  l[w] = __float2bfloat16_rn(v - __bfloat162float(hh));
}

// =============================================================================
// combine softmax partials
// =============================================================================
__global__ __launch_bounds__(256) void softmax_combine() {
  int t = blockIdx.x * 256 + threadIdx.x;
  const int total = KB * KN;
  if (t < total) {
    float m = -1e30f;
#pragma unroll
    for (int j = 0; j < 16; j++) m = fmaxf(m, g_prm[t * 16 + j]);
    float s = 0.f;
#pragma unroll
    for (int j = 0; j < 16; j++)
      s += g_prs[t * 16 + j] * __expf(g_prm[t * 16 + j] - m);
    g_rmax[t] = m;
    g_rsum[t] = s;
  } else if (t < 2 * total) {
    int u = t - total;
    float m = -1e30f;
#pragma unroll
    for (int j = 0; j < 8; j++) m = fmaxf(m, g_pcm[u * 8 + j]);
    float s = 0.f;
#pragma unroll
    for (int j = 0; j < 8; j++)
      s += g_pcs[u * 8 + j] * __expf(g_pcm[u * 8 + j] - m);
    g_cmax[u] = m;
    g_csum[u] = s;
  }
}

// =============================================================================
// pexp: P[row][m] = exp(S[row][m]-mx[row]) / sum[row]  -> bf16 hi/lo
// =============================================================================
__global__ __launch_bounds__(256) void pexp_kernel(
    const float* __restrict__ S, const float* __restrict__ mxv,
    const float* __restrict__ sv, bf16* __restrict__ Ph,
    bf16* __restrict__ Pl) {
  int row = blockIdx.x;
  float mx = mxv[row];
  float inv = 1.0f / sv[row];
  const float4* src = (const float4*)(S + (size_t)row * KN);
  int tid = threadIdx.x;
  float4 v = src[tid];
  float e0 = __expf(v.x - mx) * inv;
  float e1 = __expf(v.y - mx) * inv;
  float e2 = __expf(v.z - mx) * inv;
  float e3 = __expf(v.w - mx) * inv;
  uint32_t h0, l0, h1, l1;
  split2(e0, e1, h0, l0);
  split2(e2, e3, h1, l1);
  size_t base = (size_t)row * KN + tid * 4;
  *(uint32_t*)(Ph + base) = h0;
  *(uint32_t*)(Ph + base + 2) = h1;
  *(uint32_t*)(Pl + base) = l0;
  *(uint32_t*)(Pl + base + 2) = l1;
}

// =============================================================================
// BN combine + finalize
// =============================================================================
__global__ __launch_bounds__(256) void bnfinal_kernel() {
  int t = blockIdx.x * 256 + threadIdx.x;
  if (t >= 2 * KC) return;
  float s = 0.f, s2 = 0.f;
  for (int j = 0; j < KB * 16; j++) {
    s += g_pbs[(size_t)t * (KB * 16) + j];
    s2 += g_pbs2[(size_t)t * (KB * 16) + j];
  }
  float m = s / (float)(KB * KN);
  float var = s2 / (float)(KB * KN) - m * m;
  g_mean[t] = m;
  g_rstd[t] = rsqrtf(var + 1e-5f);
}

__global__ __launch_bounds__(256) void finalize_kernel(
    const float* __restrict__ X, const float* __restrict__ gamma,
    const float* __restrict__ beta, float* __restrict__ Z, int sel) {
  size_t idx = (size_t)blockIdx.x * 256 + threadIdx.x;
  const float* T = g_t + (size_t)sel * KB * KC * KN;
  int c = (int)((idx >> 10) & (KC - 1));
  float m = g_mean[sel * KC + c];
  float r = g_rstd[sel * KC + c];
  Z[idx] = (T[idx] - m) * r * gamma[c] + beta[c] + X[idx];
}

// =============================================================================
extern "C" void kernel_launch(void* const* d_in, const int* in_sizes, int n_in,
                              void* d_out, int out_size) {
  const float* rgb        = (const float*)d_in[0];
  const float* flow       = (const float*)d_in[1];
  const float* wg_rgb     = (const float*)d_in[2];
  const float* bg_rgb     = (const float*)d_in[3];
  const float* wg_flow    = (const float*)d_in[4];
  const float* bg_flow    = (const float*)d_in[5];
  const float* ww_rgb     = (const float*)d_in[6];
  const float* bw_rgb     = (const float*)d_in[7];
  const float* gamma_rgb  = (const float*)d_in[8];
  const float* beta_rgb   = (const float*)d_in[9];
  const float* ww_flow    = (const float*)d_in[10];
  const float* bw_flow    = (const float*)d_in[11];
  const float* gamma_flow = (const float*)d_in[12];
  const float* beta_flow  = (const float*)d_in[13];
  float* out = (float*)d_out;

#define SYM(p, g) cudaGetSymbolAddress((void**)&p, g)
  bf16 *rgbT_h, *rgbT_l, *flowT_h, *flowT_l;
  bf16 *wgr_h, *wgr_l, *wgf_h, *wgf_l, *wwr_h, *wwr_l, *wwf_h, *wwf_l;
  bf16 *re_h, *re_l, *fe_h, *fe_l, *reT_h, *reT_l, *feT_h, *feT_l;
  bf16 *P_h, *P_l, *P2_h, *P2_l, *yrT_h, *yrT_l, *yfT_h, *yfT_l;
  float *pS, *pS2, *prmax, *prsum, *pcmax, *pcsum, *pt;
  float *pprm, *pprs, *ppcm, *ppcs, *ppbs, *ppbs2;
  SYM(rgbT_h, g_rgbT_h); SYM(rgbT_l, g_rgbT_l);
  SYM(flowT_h, g_flowT_h); SYM(flowT_l, g_flowT_l);
  SYM(wgr_h, g_wgr_h); SYM(wgr_l, g_wgr_l);
  SYM(wgf_h, g_wgf_h); SYM(wgf_l, g_wgf_l);
  SYM(wwr_h, g_wwr_h); SYM(wwr_l, g_wwr_l);
  SYM(wwf_h, g_wwf_h); SYM(wwf_l, g_wwf_l);
  SYM(re_h, g_re_h); SYM(re_l, g_re_l);
  SYM(fe_h, g_fe_h); SYM(fe_l, g_fe_l);
  SYM(reT_h, g_reT_h); SYM(reT_l, g_reT_l);
  SYM(feT_h, g_feT_h); SYM(feT_l, g_feT_l);
  SYM(P_h, g_P_h); SYM(P_l, g_P_l);
  SYM(P2_h, g_P2_h); SYM(P2_l, g_P2_l);
  SYM(yrT_h, g_yrT_h); SYM(yrT_l, g_yrT_l);
  SYM(yfT_h, g_yfT_h); SYM(yfT_l, g_yfT_l);
  SYM(pS, g_S); SYM(pS2, g_S2);
  SYM(prmax, g_rmax); SYM(prsum, g_rsum);
  SYM(pcmax, g_cmax); SYM(pcsum, g_csum);
  SYM(pt, g_t);
  SYM(pprm, g_prm); SYM(pprs, g_prs);
  SYM(ppcm, g_pcm); SYM(ppcs, g_pcs);
  SYM(ppbs, g_pbs); SYM(ppbs2, g_pbs2);
#undef SYM

  cudaFuncSetAttribute(gemm_bf16, cudaFuncAttributeMaxDynamicSharedMemorySize,
                       SMEM_DYN);
  dim3 thr(256);
  const unsigned long long sEN = (unsigned long long)KCI * KN;  // embed normal
  const unsigned long long sET = (unsigned long long)KN * KCI;  // embed transp
  const unsigned long long sXT = (unsigned long long)KN * KC;
  const unsigned long long sSS = (unsigned long long)KN * KN;
  const unsigned long long sT = (unsigned long long)KC * KN;

  // 1) input transposes + splits; weight conversion
  transpose_split<<<dim3(KN / 32, KC / 32, KB), dim3(32, 8)>>>(rgb, rgbT_h,
                                                               rgbT_l);
  transpose_split<<<dim3(KN / 32, KC / 32, KB), dim3(32, 8)>>>(flow, flowT_h,
                                                               flowT_l);
  convert_w<<<2048, thr>>>(wg_rgb, wg_flow, ww_rgb, ww_flow);

  // 2) embeds: E = W @ XT^T -> normal pair + transposed pair
  gemm_bf16<<<dim3(16, 2, KB), thr, SMEM_DYN>>>(
      wgr_h, wgr_l, 0ull, KC, rgbT_h, rgbT_l, sXT, KC, bg_rgb,
      nullptr, 0ull, 0, nullptr, 0ull, 0,
      re_h, re_l, sEN, KN, reT_h, reT_l, sET, KCI,
      nullptr, nullptr, nullptr, nullptr, nullptr, nullptr, KC);
  gemm_bf16<<<dim3(16, 2, KB), thr, SMEM_DYN>>>(
      wgf_h, wgf_l, 0ull, KC, flowT_h, flowT_l, sXT, KC, bg_flow,
      nullptr, 0ull, 0, nullptr, 0ull, 0,
      fe_h, fe_l, sEN, KN, feT_h, feT_l, sET, KCI,
      nullptr, nullptr, nullptr, nullptr, nullptr, nullptr, KC);

  // 3) scores: S fp32 + S2 fp32 + softmax partials
  gemm_bf16<<<dim3(16, 8, KB), thr, SMEM_DYN>>>(
      reT_h, reT_l, sET, KCI, feT_h, feT_l, sET, KCI, nullptr,
      pS, sSS, KN, pS2, sSS, KN,
      nullptr, nullptr, 0ull, 0, nullptr, nullptr, 0ull, 0,
      pprm, pprs, ppcm, ppcs, nullptr, nullptr, KCI);

  // 4) stats combine + P materialization
  softmax_combine<<<(2 * KB * KN) / 256, thr>>>();
  pexp_kernel<<<KB * KN, thr>>>(pS, prmax, prsum, P_h, P_l);
  pexp_kernel<<<KB * KN, thr>>>(pS2, pcmax, pcsum, P2_h, P2_l);

  // 5) applies (pure GEMM): rgb_y = fe @ P^T -> yrT pair ; flow_y = re @ P2^T
  gemm_bf16<<<dim3(16, 2, KB), thr, SMEM_DYN>>>(
      fe_h, fe_l, sEN, KN, P_h, P_l, sSS, KN, nullptr,
      nullptr, 0ull, 0, nullptr, 0ull, 0,
      nullptr, nullptr, 0ull, 0, yrT_h, yrT_l, sET, KCI,
      nullptr, nullptr, nullptr, nullptr, nullptr, nullptr, KN);
  gemm_bf16<<<dim3(16, 2, KB), thr, SMEM_DYN>>>(
      re_h, re_l, sEN, KN, P2_h, P2_l, sSS, KN, nullptr,
      nullptr, 0ull, 0, nullptr, 0ull, 0,
      nullptr, nullptr, 0ull, 0, yfT_h, yfT_l, sET, KCI,
      nullptr, nullptr, nullptr, nullptr, nullptr, nullptr, KN);

  // 6) conv2: T = W @ YT^T + bias (fp32 out) + BN partials
  gemm_bf16<<<dim3(16, 4, KB), thr, SMEM_DYN>>>(
      wwr_h, wwr_l, 0ull, KCI, yrT_h, yrT_l, sET, KCI, bw_rgb,
      pt, sT, KN, nullptr, 0ull, 0,
      nullptr, nullptr, 0ull, 0, nullptr, nullptr, 0ull, 0,
      nullptr, nullptr, nullptr, nullptr, ppbs, ppbs2, KCI);
  gemm_bf16<<<dim3(16, 4, KB), thr, SMEM_DYN>>>(
      wwf_h, wwf_l, 0ull, KCI, yfT_h, yfT_l, sET, KCI, bw_flow,
      pt + (size_t)KB * KC * KN, sT, KN, nullptr, 0ull, 0,
      nullptr, nullptr, 0ull, 0, nullptr, nullptr, 0ull, 0,
      nullptr, nullptr, nullptr, nullptr,
      ppbs + (size_t)KC * KB * 16, ppbs2 + (size_t)KC * KB * 16, KCI);

  // 7) BN combine + finalize
  bnfinal_kernel<<<4, thr>>>();
  finalize_kernel<<<(KB * KC * KN) / 256, thr>>>(rgb, gamma_rgb, beta_rgb,
                                                 out, 0);
  finalize_kernel<<<(KB * KC * KN) / 256, thr>>>(
      flow, gamma_flow, beta_flow, out + (size_t)KB * KC * KN, 1);
}

// round 7
// speedup vs baseline: 1.5138x; 1.5138x over previous
#include <cuda_runtime.h>
#include <cuda_bf16.h>
#include <cstdint>

#define KB 16
#define KC 512
#define KCI 256
#define KN 1024

typedef __nv_bfloat16 bf16;
typedef __nv_bfloat162 bf162;

// ---------------- scratch (no allocs allowed -> __device__ globals) ----------
__device__ bf16 g_rgbT_h[(size_t)KB * KN * KC];   // [b][n][c] hi
__device__ bf16 g_rgbT_l[(size_t)KB * KN * KC];
__device__ bf16 g_flowT_h[(size_t)KB * KN * KC];
__device__ bf16 g_flowT_l[(size_t)KB * KN * KC];
__device__ bf16 g_wgr_h[KCI * KC], g_wgr_l[KCI * KC];
__device__ bf16 g_wgf_h[KCI * KC], g_wgf_l[KCI * KC];
__device__ bf16 g_wwr_h[KC * KCI], g_wwr_l[KC * KCI];
__device__ bf16 g_wwf_h[KC * KCI], g_wwf_l[KC * KCI];
__device__ bf16 g_re_h[(size_t)KB * KCI * KN], g_re_l[(size_t)KB * KCI * KN];
__device__ bf16 g_fe_h[(size_t)KB * KCI * KN], g_fe_l[(size_t)KB * KCI * KN];
__device__ bf16 g_reT_h[(size_t)KB * KN * KCI], g_reT_l[(size_t)KB * KN * KCI];
__device__ bf16 g_feT_h[(size_t)KB * KN * KCI], g_feT_l[(size_t)KB * KN * KCI];
__device__ float g_S[(size_t)KB * KN * KN];       // [b][n][m]
__device__ float g_S2[(size_t)KB * KN * KN];      // [b][m][n] = S^T
__device__ bf16 g_yrT_h[(size_t)KB * KN * KCI], g_yrT_l[(size_t)KB * KN * KCI];
__device__ bf16 g_yfT_h[(size_t)KB * KN * KCI], g_yfT_l[(size_t)KB * KN * KCI];
__device__ float g_t[2 * (size_t)KB * KC * KN];
__device__ float g_mean[2 * KC];
__device__ float g_rstd[2 * KC];
__device__ float g_rmax[KB * KN], g_rsum[KB * KN];
__device__ float g_cmax[KB * KN], g_csum[KB * KN];
__device__ float g_prm[KB * KN * 16], g_prs[KB * KN * 16];
__device__ float g_pcm[KB * KN * 8], g_pcs[KB * KN * 8];
__device__ float g_pbs[2 * KC * KB * 16], g_pbs2[2 * KC * KB * 16];

// ============================ helpers ========================================
__device__ __forceinline__ uint32_t smem_u32(const void* p) {
  uint32_t a;
  asm("{ .reg .u64 t; cvta.to.shared.u64 t, %1; cvt.u32.u64 %0, t; }"
      : "=r"(a) : "l"(p));
  return a;
}

#define CP16(dst, src)                                                         \
  asm volatile("cp.async.cg.shared.global [%0], [%1], 16;" ::"r"(dst),         \
               "l"(src))
#define CP_COMMIT() asm volatile("cp.async.commit_group;")
#define CP_WAIT2() asm volatile("cp.async.wait_group 2;")
#define CP_WAIT0() asm volatile("cp.async.wait_group 0;")

__device__ __forceinline__ void ldm_x4(uint32_t addr, uint32_t& r0,
                                       uint32_t& r1, uint32_t& r2,
                                       uint32_t& r3) {
  asm volatile(
      "ldmatrix.sync.aligned.m8n8.x4.shared.b16 {%0,%1,%2,%3}, [%4];"
      : "=r"(r0), "=r"(r1), "=r"(r2), "=r"(r3) : "r"(addr));
}

__device__ __forceinline__ void mma_bf16(float* d, const uint32_t* a,
                                         const uint32_t* b) {
  asm volatile(
      "mma.sync.aligned.m16n8k16.row.col.f32.bf16.bf16.f32 "
      "{%0,%1,%2,%3}, {%4,%5,%6,%7}, {%8,%9}, {%0,%1,%2,%3};"
      : "+f"(d[0]), "+f"(d[1]), "+f"(d[2]), "+f"(d[3])
      : "r"(a[0]), "r"(a[1]), "r"(a[2]), "r"(a[3]), "r"(b[0]), "r"(b[1]));
}

// fold swizzle: two 64B logical rows per 128B phys row, SW128 on phys rows.
// byte in [0,64). Verified conflict-free for ldmatrix 8-row groups.
__device__ __forceinline__ uint32_t fold_off(int r, int byte) {
  uint32_t off = (uint32_t)(((r >> 1) << 7) + ((r & 1) << 6) + byte);
  return off ^ ((off >> 3) & 0x70);
}

__device__ __forceinline__ void split2(float x, float y, uint32_t& h,
                                       uint32_t& l) {
  bf162 hh = __floats2bfloat162_rn(x, y);
  bf162 ll = __floats2bfloat162_rn(x - __low2float(hh), y - __high2float(hh));
  h = *(uint32_t*)&hh;
  l = *(uint32_t*)&ll;
}

__device__ __forceinline__ float4 lds128(uint32_t a) {
  float4 v;
  asm volatile("ld.shared.v4.f32 {%0,%1,%2,%3}, [%4];"
               : "=f"(v.x), "=f"(v.y), "=f"(v.z), "=f"(v.w) : "r"(a));
  return v;
}
__device__ __forceinline__ void sts64(uint32_t a, uint32_t x, uint32_t y) {
  asm volatile("st.shared.v2.b32 [%0], {%1,%2};" ::"r"(a), "r"(x), "r"(y));
}

// stage layout: per stage 24KB: A_hi 8KB, A_lo 8KB, B 8KB
// (pair mode: B hi 4KB + lo 4KB; exp mode: B fp32 8KB, plain 128B rows)
#define STG_STRIDE 24576
#define OFF_A_LO 8192
#define OFF_B 16384
#define OFF_PAIR 73728  // exp mode: bf16-pair ping-pong 2x8KB
#define SMEM_DYN (4 * STG_STRIDE + 1024)

// stage one K=32 chunk
__device__ __forceinline__ void stage32(uint32_t base, const bf16* Ah,
                                        const bf16* Al, int lda,
                                        const bf16* Bh, const bf16* Bl,
                                        const float* Bf, int ldb, int tid,
                                        int k0, bool expm) {
#pragma unroll
  for (int t = 0; t < 2; t++) {
    int idx = tid + (t << 8);
    int r = idx >> 2, q = idx & 3;
    uint32_t o = fold_off(r, q << 4);
    CP16(base + o, Ah + (size_t)r * lda + k0 + (q << 3));
    CP16(base + OFF_A_LO + o, Al + (size_t)r * lda + k0 + (q << 3));
  }
  if (expm) {
#pragma unroll
    for (int t = 0; t < 2; t++) {
      int idx = tid + (t << 8);
      int r = idx >> 3, q = idx & 7;
      CP16(base + OFF_B + (r << 7) + (q << 4),
           Bf + (size_t)r * ldb + k0 + (q << 2));
    }
  } else {
    int r = tid >> 2, q = tid & 3;
    uint32_t o = fold_off(r, q << 4);
    CP16(base + OFF_B + o, Bh + (size_t)r * ldb + k0 + (q << 3));
    CP16(base + OFF_B + 4096 + o, Bl + (size_t)r * ldb + k0 + (q << 3));
  }
}

// =============================================================================
// bf16-pair HMMA GEMM, K=32 chunks, fold-swizzled smem, pipelined cp.async.
// pair mode  (mxv==0): NSTG=4 buffers, 1 sync/chunk.
// exp  mode  (mxv!=0): NSTG=3, B = fp32 src; in-smem convert
//                      exp(x-mx)*inv -> bf16 pair ping-pong.
// =============================================================================
__global__ __launch_bounds__(256, 2) void gemm_bf16(
    const bf16* __restrict__ Ahi, const bf16* __restrict__ Alo,
    unsigned long long sA, int lda,
    const bf16* __restrict__ Bhi, const bf16* __restrict__ Blo,
    const float* __restrict__ Bf32, unsigned long long sB, int ldb,
    const float* __restrict__ mxv, const float* __restrict__ sumv,
    const float* __restrict__ bias,
    float* __restrict__ oNf, unsigned long long soNf, int ldoNf,
    float* __restrict__ oTf, unsigned long long soTf, int ldoTf,
    bf16* __restrict__ oNhi, bf16* __restrict__ oNlo,
    unsigned long long soN, int ldoN,
    bf16* __restrict__ oThi, bf16* __restrict__ oTlo,
    unsigned long long soT, int ldoT,
    float* __restrict__ prm, float* __restrict__ prs,
    float* __restrict__ pcm, float* __restrict__ pcs,
    float* __restrict__ pbs, float* __restrict__ pbs2, int K, int NSTG) {
  extern __shared__ char s_dyn[];
  char* sb = (char*)(((uintptr_t)s_dyn + 1023) & ~(uintptr_t)1023);
  float* s_f32 = (float*)sb;  // epilogue staging [128][65]
  uint32_t u_sb = smem_u32(sb);

  int tid = threadIdx.x;
  int wid = tid >> 5, lane = tid & 31;
  int wr = wid & 3, wc = wid >> 2;
  int b = blockIdx.z;
  int i0 = blockIdx.y * 128;
  int n0 = blockIdx.x * 64;
  bool expm = (mxv != nullptr);

  const bf16* Ah = Ahi + (size_t)b * sA + (size_t)i0 * lda;
  const bf16* Al = Alo + (size_t)b * sA + (size_t)i0 * lda;
  const bf16* Bh = expm ? nullptr : Bhi + (size_t)b * sB + (size_t)n0 * ldb;
  const bf16* Bl = expm ? nullptr : Blo + (size_t)b * sB + (size_t)n0 * ldb;
  const float* Bf = expm ? Bf32 + (size_t)b * sB + (size_t)n0 * ldb : nullptr;

  // exp-mode per-thread row constants (convert handles rows r0 and r0+32)
  float mx0 = 0.f, iv0 = 1.f, mx1 = 0.f, iv1 = 1.f;
  int cr0 = tid >> 3, cq = tid & 7;
  if (expm) {
    mx0 = mxv[b * KN + n0 + cr0];
    iv0 = 1.0f / sumv[b * KN + n0 + cr0];
    mx1 = mxv[b * KN + n0 + cr0 + 32];
    iv1 = 1.0f / sumv[b * KN + n0 + cr0 + 32];
  }

  int aRow = lane & 15, aCb = (lane >> 4) * 16;
  int bRow = ((lane >> 4) & 1) * 8 + (lane & 7);
  int bCb = ((lane >> 3) & 1) * 16;

  float acc[2][4][4];
#pragma unroll
  for (int mi = 0; mi < 2; mi++)
#pragma unroll
    for (int ni = 0; ni < 4; ni++)
#pragma unroll
      for (int e = 0; e < 4; e++) acc[mi][ni][e] = 0.f;

  int NC = K >> 5;
  // prologue: chunks 0..2
#pragma unroll
  for (int p = 0; p < 3; p++) {
    stage32(u_sb + p * STG_STRIDE, Ah, Al, lda, Bh, Bl, Bf, ldb, tid, p << 5,
            expm);
    CP_COMMIT();
  }

  for (int ch = 0; ch < NC; ch++) {
    int buf = (NSTG == 4) ? (ch & 3) : (ch % 3);
    uint32_t sbase = u_sb + buf * STG_STRIDE;
    CP_WAIT2();
    __syncthreads();
    if (NSTG == 4) {  // stage ch+3 into (ch+3)&3 (distinct from ch..ch+2)
      if (ch + 3 < NC)
        stage32(u_sb + ((ch + 3) & 3) * STG_STRIDE, Ah, Al, lda, Bh, Bl, Bf,
                ldb, tid, (ch + 3) << 5, expm);
      CP_COMMIT();
    }
    uint32_t bh_base, bl_base;
    if (expm) {
      // convert fp32 B chunk -> bf16 pair ping-pong
      uint32_t pb = u_sb + OFF_PAIR + ((ch & 1) << 13);
      uint32_t srcb = sbase + OFF_B;
      float4 v0 = lds128(srcb + (cr0 << 7) + (cq << 4));
      float4 v1 = lds128(srcb + ((cr0 + 32) << 7) + (cq << 4));
      float e0 = __expf(v0.x - mx0) * iv0, e1 = __expf(v0.y - mx0) * iv0;
      float e2 = __expf(v0.z - mx0) * iv0, e3 = __expf(v0.w - mx0) * iv0;
      float f0 = __expf(v1.x - mx1) * iv1, f1 = __expf(v1.y - mx1) * iv1;
      float f2 = __expf(v1.z - mx1) * iv1, f3 = __expf(v1.w - mx1) * iv1;
      uint32_t h0, l0, h1, l1;
      uint32_t du = ((cq >> 1) << 4) + ((cq & 1) << 3);
      split2(e0, e1, h0, l0);
      split2(e2, e3, h1, l1);
      uint32_t a0 = pb + fold_off(cr0, 0) ? 0 : 0;  // (no-op, keep regs tight)
      sts64(pb + fold_off(cr0, (cq >> 1) << 4) + ((cq & 1) << 3), h0, h1);
      sts64(pb + 4096 + fold_off(cr0, (cq >> 1) << 4) + ((cq & 1) << 3), l0,
            l1);
      split2(f0, f1, h0, l0);
      split2(f2, f3, h1, l1);
      sts64(pb + fold_off(cr0 + 32, (cq >> 1) << 4) + ((cq & 1) << 3), h0, h1);
      sts64(pb + 4096 + fold_off(cr0 + 32, (cq >> 1) << 4) + ((cq & 1) << 3),
            l0, l1);
      (void)du; (void)a0;
      __syncthreads();
      bh_base = pb;
      bl_base = pb + 4096;
    } else {
      bh_base = sbase + OFF_B;
      bl_base = sbase + OFF_B + 4096;
    }
#pragma unroll
    for (int ks = 0; ks < 2; ks++) {
      int kb = ks << 5;  // 32 bytes = 16 elems
      uint32_t ah[2][4], al[2][4], bh2[2][4], bl2[2][4];
#pragma unroll
      for (int mi = 0; mi < 2; mi++) {
        int r = wr * 32 + mi * 16 + aRow;
        uint32_t o = fold_off(r, kb + aCb);
        ldm_x4(sbase + o, ah[mi][0], ah[mi][1], ah[mi][2], ah[mi][3]);
        ldm_x4(sbase + OFF_A_LO + o, al[mi][0], al[mi][1], al[mi][2],
               al[mi][3]);
      }
#pragma unroll
      for (int ng = 0; ng < 2; ng++) {
        int r = wc * 32 + ng * 16 + bRow;
        uint32_t o = fold_off(r, kb + bCb);
        ldm_x4(bh_base + o, bh2[ng][0], bh2[ng][1], bh2[ng][2], bh2[ng][3]);
        ldm_x4(bl_base + o, bl2[ng][0], bl2[ng][1], bl2[ng][2], bl2[ng][3]);
      }
#pragma unroll
      for (int mi = 0; mi < 2; mi++)
#pragma unroll
        for (int ni = 0; ni < 4; ni++) {
          float* d = acc[mi][ni];
          const uint32_t* bhp = &bh2[ni >> 1][(ni & 1) * 2];
          const uint32_t* blp = &bl2[ni >> 1][(ni & 1) * 2];
          mma_bf16(d, ah[mi], bhp);
          mma_bf16(d, ah[mi], blp);
          mma_bf16(d, al[mi], bhp);
        }
    }
    if (NSTG == 3) {  // stage ch+3 into ch%3 after MMA done with it
      __syncthreads();
      if (ch + 3 < NC)
        stage32(sbase, Ah, Al, lda, Bh, Bl, Bf, ldb, tid, (ch + 3) << 5, expm);
      CP_COMMIT();
    }
  }
  CP_WAIT0();
  __syncthreads();

  // --------------------------- epilogue --------------------------------------
#pragma unroll
  for (int mi = 0; mi < 2; mi++) {
    int rl = wr * 32 + mi * 16 + (lane >> 2);
    float bv0 = bias ? __ldg(bias + i0 + rl) : 0.f;
    float bv1 = bias ? __ldg(bias + i0 + rl + 8) : 0.f;
#pragma unroll
    for (int ni = 0; ni < 4; ni++) {
      int c = wc * 32 + ni * 8 + 2 * (lane & 3);
      s_f32[rl * 65 + c] = acc[mi][ni][0] + bv0;
      s_f32[rl * 65 + c + 1] = acc[mi][ni][1] + bv0;
      s_f32[(rl + 8) * 65 + c] = acc[mi][ni][2] + bv1;
      s_f32[(rl + 8) * 65 + c + 1] = acc[mi][ni][3] + bv1;
    }
  }
  __syncthreads();

  if (oNf) {
    float* on = oNf + (size_t)b * soNf;
#pragma unroll
    for (int t = 0; t < 8; t++) {
      int idx = tid + (t << 8);
      int rr = idx >> 4, q = idx & 15;
      float4 v;
      v.x = s_f32[rr * 65 + q * 4 + 0];
      v.y = s_f32[rr * 65 + q * 4 + 1];
      v.z = s_f32[rr * 65 + q * 4 + 2];
      v.w = s_f32[rr * 65 + q * 4 + 3];
      *(float4*)(on + (size_t)(i0 + rr) * ldoNf + n0 + (q << 2)) = v;
    }
  }
  if (oTf) {
    float* ot = oTf + (size_t)b * soTf;
#pragma unroll
    for (int t = 0; t < 8; t++) {
      int idx = tid + (t << 8);  // 2048 float4s over r
      int c = idx >> 5, rq = (idx & 31) << 2;
      float4 v;
      v.x = s_f32[(rq + 0) * 65 + c];
      v.y = s_f32[(rq + 1) * 65 + c];
      v.z = s_f32[(rq + 2) * 65 + c];
      v.w = s_f32[(rq + 3) * 65 + c];
      *(float4*)(ot + (size_t)(n0 + c) * ldoTf + i0 + rq) = v;
    }
  }
  if (oNhi) {
    bf16* oh = oNhi + (size_t)b * soN;
    bf16* ol = oNlo + (size_t)b * soN;
#pragma unroll
    for (int t = 0; t < 8; t++) {
      int idx = tid + (t << 8);
      int rr = idx >> 4, q = idx & 15;
      uint32_t h0, l0, h1, l1;
      split2(s_f32[rr * 65 + q * 4 + 0], s_f32[rr * 65 + q * 4 + 1], h0, l0);
      split2(s_f32[rr * 65 + q * 4 + 2], s_f32[rr * 65 + q * 4 + 3], h1, l1);
      size_t base = (size_t)(i0 + rr) * ldoN + n0 + (q << 2);
      *(uint32_t*)(oh + base) = h0;
      *(uint32_t*)(oh + base + 2) = h1;
      *(uint32_t*)(ol + base) = l0;
      *(uint32_t*)(ol + base + 2) = l1;
    }
  }
  if (oThi) {
    bf16* oh = oThi + (size_t)b * soT;
    bf16* ol = oTlo + (size_t)b * soT;
#pragma unroll
    for (int t = 0; t < 8; t++) {
      int idx = tid + (t << 8);
      int c = idx >> 5, rq = (idx & 31) << 2;
      uint32_t h0, l0, h1, l1;
      split2(s_f32[(rq + 0) * 65 + c], s_f32[(rq + 1) * 65 + c], h0, l0);
      split2(s_f32[(rq + 2) * 65 + c], s_f32[(rq + 3) * 65 + c], h1, l1);
      size_t base = (size_t)(n0 + c) * ldoT + i0 + rq;
      *(uint32_t*)(oh + base) = h0;
      *(uint32_t*)(oh + base + 2) = h1;
      *(uint32_t*)(ol + base) = l0;
      *(uint32_t*)(ol + base + 2) = l1;
    }
  }
  if (prm) {
    if (tid < 128) {
      int r = tid;
      float pm = -1e30f;
#pragma unroll 8
      for (int c = 0; c < 64; c++) pm = fmaxf(pm, s_f32[r * 65 + c]);
      float ps = 0.f;
#pragma unroll 8
      for (int c = 0; c < 64; c++) ps += __expf(s_f32[r * 65 + c] - pm);
      size_t o = (size_t)(b * KN + i0 + r) * gridDim.x + blockIdx.x;
      prm[o] = pm;
      prs[o] = ps;
    } else if (tid < 192) {
      int c = tid - 128;
      float pm = -1e30f;
#pragma unroll 8
      for (int r = 0; r < 128; r++) pm = fmaxf(pm, s_f32[r * 65 + c]);
      float ps = 0.f;
#pragma unroll 8
      for (int r = 0; r < 128; r++) ps += __expf(s_f32[r * 65 + c] - pm);
      size_t o = (size_t)(b * KN + n0 + c) * gridDim.y + blockIdx.y;
      pcm[o] = pm;
      pcs[o] = ps;
    }
  }
  if (pbs && tid < 128) {
    int r = tid;
    float s = 0.f, s2 = 0.f;
#pragma unroll 8
    for (int c = 0; c < 64; c++) {
      float v = s_f32[r * 65 + c];
      s += v;
      s2 += v * v;
    }
    size_t o = ((size_t)(i0 + r) * KB + b) * gridDim.x + blockIdx.x;
    pbs[o] = s;
    pbs2[o] = s2;
  }
}

// =============================================================================
// transpose + split: [C][N] fp32 -> [N][C] bf16 hi/lo
// =============================================================================
__global__ __launch_bounds__(256) void transpose_split(
    const float* __restrict__ in, bf16* __restrict__ oh,
    bf16* __restrict__ ol) {
  __shared__ float t[32][33];
  int b = blockIdx.z;
  const float* ib = in + (size_t)b * KC * KN;
  bf16* ohb = oh + (size_t)b * KC * KN;
  bf16* olb = ol + (size_t)b * KC * KN;
  int n0 = blockIdx.x * 32, c0 = blockIdx.y * 32;
  int x = threadIdx.x, y = threadIdx.y;
#pragma unroll
  for (int j = 0; j < 4; j++)
    t[y + 8 * j][x] = ib[(size_t)(c0 + y + 8 * j) * KN + n0 + x];
  __syncthreads();
#pragma unroll
  for (int j = 0; j < 4; j++) {
    float v = t[x][y + 8 * j];
    bf16 h = __float2bfloat16_rn(v);
    size_t o = (size_t)(n0 + y + 8 * j) * KC + c0 + x;
    ohb[o] = h;
    olb[o] = __float2bfloat16_rn(v - __bfloat162float(h));
  }
}

// =============================================================================
// convert 4 weight matrices (each 131072 elems) to hi/lo
// =============================================================================
__global__ __launch_bounds__(256) void convert_w(
    const float* __restrict__ s0, const float* __restrict__ s1,
    const float* __restrict__ s2, const float* __restrict__ s3) {
  int idx = blockIdx.x * 256 + threadIdx.x;
  int sel = idx >> 17, w = idx & 131071;
  const float* s = sel == 0 ? s0 : sel == 1 ? s1 : sel == 2 ? s2 : s3;
  bf16* h = sel == 0 ? g_wgr_h : sel == 1 ? g_wgf_h : sel == 2 ? g_wwr_h
                                                               : g_wwf_h;
  bf16* l = sel == 0 ? g_wgr_l : sel == 1 ? g_wgf_l : sel == 2 ? g_wwr_l
                                                               : g_wwf_l;
  float v = s[w];
  bf16 hh = __float2bfloat16_rn(v);
  h[w] = hh;
  l[w] = __float2bfloat16_rn(v - __bfloat162float(hh));
}

// =============================================================================
// combine softmax partials
// =============================================================================
__global__ __launch_bounds__(256) void softmax_combine() {
  int t = blockIdx.x * 256 + threadIdx.x;
  const int total = KB * KN;
  if (t < total) {
    float m = -1e30f;
#pragma unroll
    for (int j = 0; j < 16; j++) m = fmaxf(m, g_prm[t * 16 + j]);
    float s = 0.f;
#pragma unroll
    for (int j = 0; j < 16; j++)
      s += g_prs[t * 16 + j] * __expf(g_prm[t * 16 + j] - m);
    g_rmax[t] = m;
    g_rsum[t] = s;
  } else if (t < 2 * total) {
    int u = t - total;
    float m = -1e30f;
#pragma unroll
    for (int j = 0; j < 8; j++) m = fmaxf(m, g_pcm[u * 8 + j]);
    float s = 0.f;
#pragma unroll
    for (int j = 0; j < 8; j++)
      s += g_pcs[u * 8 + j] * __expf(g_pcm[u * 8 + j] - m);
    g_cmax[u] = m;
    g_csum[u] = s;
  }
}

// =============================================================================
// BN combine + finalize
// =============================================================================
__global__ __launch_bounds__(256) void bnfinal_kernel() {
  int t = blockIdx.x * 256 + threadIdx.x;
  if (t >= 2 * KC) return;
  float s = 0.f, s2 = 0.f;
  for (int j = 0; j < KB * 16; j++) {
    s += g_pbs[(size_t)t * (KB * 16) + j];
    s2 += g_pbs2[(size_t)t * (KB * 16) + j];
  }
  float m = s / (float)(KB * KN);
  float var = s2 / (float)(KB * KN) - m * m;
  g_mean[t] = m;
  g_rstd[t] = rsqrtf(var + 1e-5f);
}

__global__ __launch_bounds__(256) void finalize_kernel(
    const float* __restrict__ X, const float* __restrict__ gamma,
    const float* __restrict__ beta, float* __restrict__ Z, int sel) {
  size_t idx = (size_t)blockIdx.x * 256 + threadIdx.x;
  const float* T = g_t + (size_t)sel * KB * KC * KN;
  int c = (int)((idx >> 10) & (KC - 1));
  float m = g_mean[sel * KC + c];
  float r = g_rstd[sel * KC + c];
  Z[idx] = (T[idx] - m) * r * gamma[c] + beta[c] + X[idx];
}

// =============================================================================
extern "C" void kernel_launch(void* const* d_in, const int* in_sizes, int n_in,
                              void* d_out, int out_size) {
  const float* rgb        = (const float*)d_in[0];
  const float* flow       = (const float*)d_in[1];
  const float* wg_rgb     = (const float*)d_in[2];
  const float* bg_rgb     = (const float*)d_in[3];
  const float* wg_flow    = (const float*)d_in[4];
  const float* bg_flow    = (const float*)d_in[5];
  const float* ww_rgb     = (const float*)d_in[6];
  const float* bw_rgb     = (const float*)d_in[7];
  const float* gamma_rgb  = (const float*)d_in[8];
  const float* beta_rgb   = (const float*)d_in[9];
  const float* ww_flow    = (const float*)d_in[10];
  const float* bw_flow    = (const float*)d_in[11];
  const float* gamma_flow = (const float*)d_in[12];
  const float* beta_flow  = (const float*)d_in[13];
  float* out = (float*)d_out;

#define SYM(p, g) cudaGetSymbolAddress((void**)&p, g)
  bf16 *rgbT_h, *rgbT_l, *flowT_h, *flowT_l;
  bf16 *wgr_h, *wgr_l, *wgf_h, *wgf_l, *wwr_h, *wwr_l, *wwf_h, *wwf_l;
  bf16 *re_h, *re_l, *fe_h, *fe_l, *reT_h, *reT_l, *feT_h, *feT_l;
  bf16 *yrT_h, *yrT_l, *yfT_h, *yfT_l;
  float *pS, *pS2, *prmax, *prsum, *pcmax, *pcsum, *pt;
  float *pprm, *pprs, *ppcm, *ppcs, *ppbs, *ppbs2;
  SYM(rgbT_h, g_rgbT_h); SYM(rgbT_l, g_rgbT_l);
  SYM(flowT_h, g_flowT_h); SYM(flowT_l, g_flowT_l);
  SYM(wgr_h, g_wgr_h); SYM(wgr_l, g_wgr_l);
  SYM(wgf_h, g_wgf_h); SYM(wgf_l, g_wgf_l);
  SYM(wwr_h, g_wwr_h); SYM(wwr_l, g_wwr_l);
  SYM(wwf_h, g_wwf_h); SYM(wwf_l, g_wwf_l);
  SYM(re_h, g_re_h); SYM(re_l, g_re_l);
  SYM(fe_h, g_fe_h); SYM(fe_l, g_fe_l);
  SYM(reT_h, g_reT_h); SYM(reT_l, g_reT_l);
  SYM(feT_h, g_feT_h); SYM(feT_l, g_feT_l);
  SYM(yrT_h, g_yrT_h); SYM(yrT_l, g_yrT_l);
  SYM(yfT_h, g_yfT_h); SYM(yfT_l, g_yfT_l);
  SYM(pS, g_S); SYM(pS2, g_S2);
  SYM(prmax, g_rmax); SYM(prsum, g_rsum);
  SYM(pcmax, g_cmax); SYM(pcsum, g_csum);
  SYM(pt, g_t);
  SYM(pprm, g_prm); SYM(pprs, g_prs);
  SYM(ppcm, g_pcm); SYM(ppcs, g_pcs);
  SYM(ppbs, g_pbs); SYM(ppbs2, g_pbs2);
#undef SYM

  cudaFuncSetAttribute(gemm_bf16, cudaFuncAttributeMaxDynamicSharedMemorySize,
                       SMEM_DYN);
  dim3 thr(256);
  const unsigned long long sEN = (unsigned long long)KCI * KN;
  const unsigned long long sET = (unsigned long long)KN * KCI;
  const unsigned long long sXT = (unsigned long long)KN * KC;
  const unsigned long long sSS = (unsigned long long)KN * KN;
  const unsigned long long sT = (unsigned long long)KC * KN;

  // 1) input transposes + splits; weight conversion
  transpose_split<<<dim3(KN / 32, KC / 32, KB), dim3(32, 8)>>>(rgb, rgbT_h,
                                                               rgbT_l);
  transpose_split<<<dim3(KN / 32, KC / 32, KB), dim3(32, 8)>>>(flow, flowT_h,
                                                               flowT_l);
  convert_w<<<2048, thr>>>(wg_rgb, wg_flow, ww_rgb, ww_flow);

  // 2) embeds: E = W @ XT^T -> normal pair + transposed pair
  gemm_bf16<<<dim3(16, 2, KB), thr, SMEM_DYN>>>(
      wgr_h, wgr_l, 0ull, KC, rgbT_h, rgbT_l, nullptr, sXT, KC,
      nullptr, nullptr, bg_rgb,
      nullptr, 0ull, 0, nullptr, 0ull, 0,
      re_h, re_l, sEN, KN, reT_h, reT_l, sET, KCI,
      nullptr, nullptr, nullptr, nullptr, nullptr, nullptr, KC, 4);
  gemm_bf16<<<dim3(16, 2, KB), thr, SMEM_DYN>>>(
      wgf_h, wgf_l, 0ull, KC, flowT_h, flowT_l, nullptr, sXT, KC,
      nullptr, nullptr, bg_flow,
      nullptr, 0ull, 0, nullptr, 0ull, 0,
      fe_h, fe_l, sEN, KN, feT_h, feT_l, sET, KCI,
      nullptr, nullptr, nullptr, nullptr, nullptr, nullptr, KC, 4);

  // 3) scores: S fp32 + S2 fp32 + softmax partials
  gemm_bf16<<<dim3(16, 8, KB), thr, SMEM_DYN>>>(
      reT_h, reT_l, sET, KCI, feT_h, feT_l, nullptr, sET, KCI,
      nullptr, nullptr, nullptr,
      pS, sSS, KN, pS2, sSS, KN,
      nullptr, nullptr, 0ull, 0, nullptr, nullptr, 0ull, 0,
      pprm, pprs, ppcm, ppcs, nullptr, nullptr, KCI, 4);

  // 4) stats combine
  softmax_combine<<<(2 * KB * KN) / 256, thr>>>();

  // 5) applies: exp fused into B staging (smem convert), output = y^T pair
  gemm_bf16<<<dim3(16, 2, KB), thr, SMEM_DYN>>>(
      fe_h, fe_l, sEN, KN, nullptr, nullptr, pS, sSS, KN,
      prmax, prsum, nullptr,
      nullptr, 0ull, 0, nullptr, 0ull, 0,
      nullptr, nullptr, 0ull, 0, yrT_h, yrT_l, sET, KCI,
      nullptr, nullptr, nullptr, nullptr, nullptr, nullptr, KN, 3);
  gemm_bf16<<<dim3(16, 2, KB), thr, SMEM_DYN>>>(
      re_h, re_l, sEN, KN, nullptr, nullptr, pS2, sSS, KN,
      pcmax, pcsum, nullptr,
      nullptr, 0ull, 0, nullptr, 0ull, 0,
      nullptr, nullptr, 0ull, 0, yfT_h, yfT_l, sET, KCI,
      nullptr, nullptr, nullptr, nullptr, nullptr, nullptr, KN, 3);

  // 6) conv2: T = W @ YT^T + bias (fp32 out) + BN partials
  gemm_bf16<<<dim3(16, 4, KB), thr, SMEM_DYN>>>(
      wwr_h, wwr_l, 0ull, KCI, yrT_h, yrT_l, nullptr, sET, KCI,
      nullptr, nullptr, bw_rgb,
      pt, sT, KN, nullptr, 0ull, 0,
      nullptr, nullptr, 0ull, 0, nullptr, nullptr, 0ull, 0,
      nullptr, nullptr, nullptr, nullptr, ppbs, ppbs2, KCI, 4);
  gemm_bf16<<<dim3(16, 4, KB), thr, SMEM_DYN>>>(
      wwf_h, wwf_l, 0ull, KCI, yfT_h, yfT_l, nullptr, sET, KCI,
      nullptr, nullptr, bw_flow,
      pt + (size_t)KB * KC * KN, sT, KN, nullptr, 0ull, 0,
      nullptr, nullptr, 0ull, 0, nullptr, nullptr, 0ull, 0,
      nullptr, nullptr, nullptr, nullptr,
      ppbs + (size_t)KC * KB * 16, ppbs2 + (size_t)KC * KB * 16, KCI, 4);

  // 7) BN combine + finalize
  bnfinal_kernel<<<4, thr>>>();
  finalize_kernel<<<(KB * KC * KN) / 256, thr>>>(rgb, gamma_rgb, beta_rgb,
                                                 out, 0);
  finalize_kernel<<<(KB * KC * KN) / 256, thr>>>(
      flow, gamma_flow, beta_flow, out + (size_t)KB * KC * KN, 1);
}

// round 8
// speedup vs baseline: 1.5937x; 1.0527x over previous
#include <cuda_runtime.h>
#include <cuda_bf16.h>
#include <cstdint>

#define KB 16
#define KC 512
#define KCI 256
#define KN 1024

typedef __nv_bfloat16 bf16;
typedef __nv_bfloat162 bf162;

// ---------------- scratch (no allocs allowed -> __device__ globals) ----------
__device__ bf16 g_rgbT_h[(size_t)KB * KN * KC];
__device__ bf16 g_rgbT_l[(size_t)KB * KN * KC];
__device__ bf16 g_flowT_h[(size_t)KB * KN * KC];
__device__ bf16 g_flowT_l[(size_t)KB * KN * KC];
__device__ bf16 g_wgr_h[KCI * KC], g_wgr_l[KCI * KC];
__device__ bf16 g_wgf_h[KCI * KC], g_wgf_l[KCI * KC];
__device__ bf16 g_wwr_h[KC * KCI], g_wwr_l[KC * KCI];
__device__ bf16 g_wwf_h[KC * KCI], g_wwf_l[KC * KCI];
__device__ bf16 g_re_h[(size_t)KB * KCI * KN], g_re_l[(size_t)KB * KCI * KN];
__device__ bf16 g_fe_h[(size_t)KB * KCI * KN], g_fe_l[(size_t)KB * KCI * KN];
__device__ bf16 g_reT_h[(size_t)KB * KN * KCI], g_reT_l[(size_t)KB * KN * KCI];
__device__ bf16 g_feT_h[(size_t)KB * KN * KCI], g_feT_l[(size_t)KB * KN * KCI];
__device__ float g_S[(size_t)KB * KN * KN];
__device__ float g_S2[(size_t)KB * KN * KN];
__device__ bf16 g_yrT_h[(size_t)KB * KN * KCI], g_yrT_l[(size_t)KB * KN * KCI];
__device__ bf16 g_yfT_h[(size_t)KB * KN * KCI], g_yfT_l[(size_t)KB * KN * KCI];
__device__ float g_t[2 * (size_t)KB * KC * KN];
__device__ float g_mean[2 * KC];
__device__ float g_rstd[2 * KC];
__device__ float g_rmax[KB * KN], g_rsum[KB * KN];
__device__ float g_cmax[KB * KN], g_csum[KB * KN];
__device__ float g_prm[KB * KN * 16], g_prs[KB * KN * 16];
__device__ float g_pcm[KB * KN * 8], g_pcs[KB * KN * 8];
__device__ float g_pbs[2 * KC * KB * 16], g_pbs2[2 * KC * KB * 16];

// ============================ helpers ========================================
__device__ __forceinline__ uint32_t smem_u32(const void* p) {
  uint32_t a;
  asm("{ .reg .u64 t; cvta.to.shared.u64 t, %1; cvt.u32.u64 %0, t; }"
      : "=r"(a) : "l"(p));
  return a;
}

#define CP16(dst, src)                                                         \
  asm volatile("cp.async.cg.shared.global [%0], [%1], 16;" ::"r"(dst),         \
               "l"(src))
#define CP_COMMIT() asm volatile("cp.async.commit_group;")
#define CP_WAIT1() asm volatile("cp.async.wait_group 1;")
#define CP_WAIT2() asm volatile("cp.async.wait_group 2;")
#define CP_WAIT0() asm volatile("cp.async.wait_group 0;")

__device__ __forceinline__ void ldm_x4(uint32_t addr, uint32_t& r0,
                                       uint32_t& r1, uint32_t& r2,
                                       uint32_t& r3) {
  asm volatile(
      "ldmatrix.sync.aligned.m8n8.x4.shared.b16 {%0,%1,%2,%3}, [%4];"
      : "=r"(r0), "=r"(r1), "=r"(r2), "=r"(r3) : "r"(addr));
}

__device__ __forceinline__ void mma_bf16(float* d, const uint32_t* a,
                                         const uint32_t* b) {
  asm volatile(
      "mma.sync.aligned.m16n8k16.row.col.f32.bf16.bf16.f32 "
      "{%0,%1,%2,%3}, {%4,%5,%6,%7}, {%8,%9}, {%0,%1,%2,%3};"
      : "+f"(d[0]), "+f"(d[1]), "+f"(d[2]), "+f"(d[3])
      : "r"(a[0]), "r"(a[1]), "r"(a[2]), "r"(a[3]), "r"(b[0]), "r"(b[1]));
}

// fold swizzle: two 64B logical rows per 128B phys row, SW128 on phys rows.
__device__ __forceinline__ uint32_t fold_off(int r, int byte) {
  uint32_t off = (uint32_t)(((r >> 1) << 7) + ((r & 1) << 6) + byte);
  return off ^ ((off >> 3) & 0x70);
}

__device__ __forceinline__ void split2(float x, float y, uint32_t& h,
                                       uint32_t& l) {
  bf162 hh = __floats2bfloat162_rn(x, y);
  bf162 ll = __floats2bfloat162_rn(x - __low2float(hh), y - __high2float(hh));
  h = *(uint32_t*)&hh;
  l = *(uint32_t*)&ll;
}

__device__ __forceinline__ float4 lds128(uint32_t a) {
  float4 v;
  asm volatile("ld.shared.v4.f32 {%0,%1,%2,%3}, [%4];"
               : "=f"(v.x), "=f"(v.y), "=f"(v.z), "=f"(v.w) : "r"(a));
  return v;
}
__device__ __forceinline__ void sts64(uint32_t a, uint32_t x, uint32_t y) {
  asm volatile("st.shared.v2.b32 [%0], {%1,%2};" ::"r"(a), "r"(x), "r"(y));
}

// smem layout: 4 A-stages (16KB: hi 8K + lo 8K), 4 B-stages (8KB),
// exp-mode bf16-pair ping-pong (2x8KB). total 112KB -> 2 CTAs/SM.
#define A_STG 16384
#define B_STG 8192
#define OFF_BSTG 65536
#define OFF_PAIR 98304
#define SMEM_DYN (114688 + 1024)

struct GArg {
  const bf16 *Ah, *Al, *Bh, *Bl;
  const float *Bf, *mxv, *sumv, *bias;
  float *oNf, *oTf;
  bf16 *oNh, *oNl, *oTh, *oTl;
  float *prm, *prs, *pcm, *pcs, *pbs, *pbs2;
};

// stage one K=32 chunk into stage slot s
__device__ __forceinline__ void stage32(uint32_t u_sb, int s, const bf16* Ah,
                                        const bf16* Al, int lda,
                                        const bf16* Bh, const bf16* Bl,
                                        const float* Bf, int ldb, int tid,
                                        int k0, bool expm) {
  uint32_t abase = u_sb + (uint32_t)s * A_STG;
  uint32_t bbase = u_sb + OFF_BSTG + (uint32_t)s * B_STG;
#pragma unroll
  for (int t = 0; t < 2; t++) {
    int idx = tid + (t << 8);
    int r = idx >> 2, q = idx & 3;
    uint32_t o = fold_off(r, q << 4);
    CP16(abase + o, Ah + (size_t)r * lda + k0 + (q << 3));
    CP16(abase + 8192 + o, Al + (size_t)r * lda + k0 + (q << 3));
  }
  if (expm) {
#pragma unroll
    for (int t = 0; t < 2; t++) {
      int idx = tid + (t << 8);
      int r = idx >> 3, q = idx & 7;
      CP16(bbase + (r << 7) + (q << 4), Bf + (size_t)r * ldb + k0 + (q << 2));
    }
  } else {
    int r = tid >> 2, q = tid & 3;
    uint32_t o = fold_off(r, q << 4);
    CP16(bbase + o, Bh + (size_t)r * ldb + k0 + (q << 3));
    CP16(bbase + 4096 + o, Bl + (size_t)r * ldb + k0 + (q << 3));
  }
}

// convert fp32 B chunk c -> bf16 pair ping-pong (rows cr0, cr0+32)
__device__ __forceinline__ void convert_chunk(uint32_t u_sb, int c, int cr0,
                                              int cq, float mx0, float iv0,
                                              float mx1, float iv1) {
  uint32_t srcb = u_sb + OFF_BSTG + (uint32_t)(c & 3) * B_STG;
  uint32_t pb = u_sb + OFF_PAIR + ((c & 1) << 13);
  float4 v0 = lds128(srcb + (cr0 << 7) + (cq << 4));
  float4 v1 = lds128(srcb + ((cr0 + 32) << 7) + (cq << 4));
  float e0 = __expf(v0.x - mx0) * iv0, e1 = __expf(v0.y - mx0) * iv0;
  float e2 = __expf(v0.z - mx0) * iv0, e3 = __expf(v0.w - mx0) * iv0;
  float f0 = __expf(v1.x - mx1) * iv1, f1 = __expf(v1.y - mx1) * iv1;
  float f2 = __expf(v1.z - mx1) * iv1, f3 = __expf(v1.w - mx1) * iv1;
  uint32_t o0 = fold_off(cr0, (cq >> 1) << 4) + ((cq & 1) << 3);
  uint32_t o1 = fold_off(cr0 + 32, (cq >> 1) << 4) + ((cq & 1) << 3);
  uint32_t h0, l0, h1, l1;
  split2(e0, e1, h0, l0);
  split2(e2, e3, h1, l1);
  sts64(pb + o0, h0, h1);
  sts64(pb + 4096 + o0, l0, l1);
  split2(f0, f1, h0, l0);
  split2(f2, f3, h1, l1);
  sts64(pb + o1, h0, h1);
  sts64(pb + 4096 + o1, l0, l1);
}

// =============================================================================
// bf16-pair HMMA GEMM, K=32 chunks, 4-stage cp.async pipeline, 1 sync/chunk.
// Dual-half: blockIdx.z >> 4 selects arg set (merged rgb/flow launches).
// =============================================================================
__global__ __launch_bounds__(256, 2) void gemm_bf16(
    GArg a0, GArg a1,
    unsigned long long sA, int lda, unsigned long long sB, int ldb,
    unsigned long long soNf, int ldoNf, unsigned long long soTf, int ldoTf,
    unsigned long long soN, int ldoN, unsigned long long soT, int ldoT,
    int K) {
  extern __shared__ char s_dyn[];
  char* sb = (char*)(((uintptr_t)s_dyn + 1023) & ~(uintptr_t)1023);
  float* s_f32 = (float*)sb;  // epilogue staging [128][65]
  uint32_t u_sb = smem_u32(sb);

  int tid = threadIdx.x;
  int wid = tid >> 5, lane = tid & 31;
  int wr = wid & 3, wc = wid >> 2;
  int half = blockIdx.z >> 4;
  int b = blockIdx.z & (KB - 1);
  int i0 = blockIdx.y * 128;
  int n0 = blockIdx.x * 64;
#define SEL(f) (half ? a1.f : a0.f)
  const float* mxv = SEL(mxv);
  bool expm = (mxv != nullptr);

  const bf16* Ah = SEL(Ah) + (size_t)b * sA + (size_t)i0 * lda;
  const bf16* Al = SEL(Al) + (size_t)b * sA + (size_t)i0 * lda;
  const bf16* Bh = expm ? nullptr : SEL(Bh) + (size_t)b * sB + (size_t)n0 * ldb;
  const bf16* Bl = expm ? nullptr : SEL(Bl) + (size_t)b * sB + (size_t)n0 * ldb;
  const float* Bf = expm ? SEL(Bf) + (size_t)b * sB + (size_t)n0 * ldb
                         : nullptr;

  float mx0 = 0.f, iv0 = 1.f, mx1 = 0.f, iv1 = 1.f;
  int cr0 = tid >> 3, cq = tid & 7;
  if (expm) {
    const float* sumv = SEL(sumv);
    mx0 = mxv[b * KN + n0 + cr0];
    iv0 = 1.0f / sumv[b * KN + n0 + cr0];
    mx1 = mxv[b * KN + n0 + cr0 + 32];
    iv1 = 1.0f / sumv[b * KN + n0 + cr0 + 32];
  }

  int aRow = lane & 15, aCb = (lane >> 4) * 16;
  int bRow = ((lane >> 4) & 1) * 8 + (lane & 7);
  int bCb = ((lane >> 3) & 1) * 16;

  float acc[2][4][4];
#pragma unroll
  for (int mi = 0; mi < 2; mi++)
#pragma unroll
    for (int ni = 0; ni < 4; ni++)
#pragma unroll
      for (int e = 0; e < 4; e++) acc[mi][ni][e] = 0.f;

  int NC = K >> 5;
  // prologue: stage chunks 0..2
#pragma unroll
  for (int p = 0; p < 3; p++) {
    stage32(u_sb, p, Ah, Al, lda, Bh, Bl, Bf, ldb, tid, p << 5, expm);
    CP_COMMIT();
  }
  if (expm) {
    CP_WAIT2();  // chunk 0 staged
    __syncthreads();
    convert_chunk(u_sb, 0, cr0, cq, mx0, iv0, mx1, iv1);
  }

  for (int ch = 0; ch < NC; ch++) {
    if (expm) CP_WAIT1(); else CP_WAIT2();
    __syncthreads();  // chunk data + pair[ch&1] visible; prev MMA reads done
    if (ch + 3 < NC)
      stage32(u_sb, (ch + 3) & 3, Ah, Al, lda, Bh, Bl, Bf, ldb, tid,
              (ch + 3) << 5, expm);
    CP_COMMIT();
    if (expm && ch + 1 < NC)
      convert_chunk(u_sb, ch + 1, cr0, cq, mx0, iv0, mx1, iv1);

    uint32_t sA_base = u_sb + (uint32_t)(ch & 3) * A_STG;
    uint32_t bh_base, bl_base;
    if (expm) {
      uint32_t pb = u_sb + OFF_PAIR + ((ch & 1) << 13);
      bh_base = pb;
      bl_base = pb + 4096;
    } else {
      uint32_t bb = u_sb + OFF_BSTG + (uint32_t)(ch & 3) * B_STG;
      bh_base = bb;
      bl_base = bb + 4096;
    }
#pragma unroll
    for (int ks = 0; ks < 2; ks++) {
      int kb = ks << 5;
      uint32_t ah[2][4], al[2][4], bh2[2][4], bl2[2][4];
#pragma unroll
      for (int mi = 0; mi < 2; mi++) {
        int r = wr * 32 + mi * 16 + aRow;
        uint32_t o = fold_off(r, kb + aCb);
        ldm_x4(sA_base + o, ah[mi][0], ah[mi][1], ah[mi][2], ah[mi][3]);
        ldm_x4(sA_base + 8192 + o, al[mi][0], al[mi][1], al[mi][2], al[mi][3]);
      }
#pragma unroll
      for (int ng = 0; ng < 2; ng++) {
        int r = wc * 32 + ng * 16 + bRow;
        uint32_t o = fold_off(r, kb + bCb);
        ldm_x4(bh_base + o, bh2[ng][0], bh2[ng][1], bh2[ng][2], bh2[ng][3]);
        ldm_x4(bl_base + o, bl2[ng][0], bl2[ng][1], bl2[ng][2], bl2[ng][3]);
      }
#pragma unroll
      for (int mi = 0; mi < 2; mi++)
#pragma unroll
        for (int ni = 0; ni < 4; ni++) {
          float* d = acc[mi][ni];
          const uint32_t* bhp = &bh2[ni >> 1][(ni & 1) * 2];
          const uint32_t* blp = &bl2[ni >> 1][(ni & 1) * 2];
          mma_bf16(d, ah[mi], bhp);
          mma_bf16(d, ah[mi], blp);
          mma_bf16(d, al[mi], bhp);
        }
    }
  }
  CP_WAIT0();
  __syncthreads();

  // --------------------------- epilogue --------------------------------------
  const float* bias = SEL(bias);
#pragma unroll
  for (int mi = 0; mi < 2; mi++) {
    int rl = wr * 32 + mi * 16 + (lane >> 2);
    float bv0 = bias ? __ldg(bias + i0 + rl) : 0.f;
    float bv1 = bias ? __ldg(bias + i0 + rl + 8) : 0.f;
#pragma unroll
    for (int ni = 0; ni < 4; ni++) {
      int c = wc * 32 + ni * 8 + 2 * (lane & 3);
      s_f32[rl * 65 + c] = acc[mi][ni][0] + bv0;
      s_f32[rl * 65 + c + 1] = acc[mi][ni][1] + bv0;
      s_f32[(rl + 8) * 65 + c] = acc[mi][ni][2] + bv1;
      s_f32[(rl + 8) * 65 + c + 1] = acc[mi][ni][3] + bv1;
    }
  }
  __syncthreads();

  if (float* oNf = SEL(oNf)) {
    float* on = oNf + (size_t)b * soNf;
#pragma unroll
    for (int t = 0; t < 8; t++) {
      int idx = tid + (t << 8);
      int rr = idx >> 4, q = idx & 15;
      float4 v;
      v.x = s_f32[rr * 65 + q * 4 + 0];
      v.y = s_f32[rr * 65 + q * 4 + 1];
      v.z = s_f32[rr * 65 + q * 4 + 2];
      v.w = s_f32[rr * 65 + q * 4 + 3];
      *(float4*)(on + (size_t)(i0 + rr) * ldoNf + n0 + (q << 2)) = v;
    }
  }
  if (float* oTf = SEL(oTf)) {
    float* ot = oTf + (size_t)b * soTf;
#pragma unroll
    for (int t = 0; t < 8; t++) {
      int idx = tid + (t << 8);
      int c = idx >> 5, rq = (idx & 31) << 2;
      float4 v;
      v.x = s_f32[(rq + 0) * 65 + c];
      v.y = s_f32[(rq + 1) * 65 + c];
      v.z = s_f32[(rq + 2) * 65 + c];
      v.w = s_f32[(rq + 3) * 65 + c];
      *(float4*)(ot + (size_t)(n0 + c) * ldoTf + i0 + rq) = v;
    }
  }
  if (bf16* oNh = SEL(oNh)) {
    bf16* oh = oNh + (size_t)b * soN;
    bf16* ol = SEL(oNl) + (size_t)b * soN;
#pragma unroll
    for (int t = 0; t < 8; t++) {
      int idx = tid + (t << 8);
      int rr = idx >> 4, q = idx & 15;
      uint32_t h0, l0, h1, l1;
      split2(s_f32[rr * 65 + q * 4 + 0], s_f32[rr * 65 + q * 4 + 1], h0, l0);
      split2(s_f32[rr * 65 + q * 4 + 2], s_f32[rr * 65 + q * 4 + 3], h1, l1);
      size_t base = (size_t)(i0 + rr) * ldoN + n0 + (q << 2);
      *(uint32_t*)(oh + base) = h0;
      *(uint32_t*)(oh + base + 2) = h1;
      *(uint32_t*)(ol + base) = l0;
      *(uint32_t*)(ol + base + 2) = l1;
    }
  }
  if (bf16* oTh = SEL(oTh)) {
    bf16* oh = oTh + (size_t)b * soT;
    bf16* ol = SEL(oTl) + (size_t)b * soT;
#pragma unroll
    for (int t = 0; t < 8; t++) {
      int idx = tid + (t << 8);
      int c = idx >> 5, rq = (idx & 31) << 2;
      uint32_t h0, l0, h1, l1;
      split2(s_f32[(rq + 0) * 65 + c], s_f32[(rq + 1) * 65 + c], h0, l0);
      split2(s_f32[(rq + 2) * 65 + c], s_f32[(rq + 3) * 65 + c], h1, l1);
      size_t base = (size_t)(n0 + c) * ldoT + i0 + rq;
      *(uint32_t*)(oh + base) = h0;
      *(uint32_t*)(oh + base + 2) = h1;
      *(uint32_t*)(ol + base) = l0;
      *(uint32_t*)(ol + base + 2) = l1;
    }
  }
  if (float* prm = SEL(prm)) {
    if (tid < 128) {
      int r = tid;
      float pm = -1e30f;
#pragma unroll 8
      for (int c = 0; c < 64; c++) pm = fmaxf(pm, s_f32[r * 65 + c]);
      float ps = 0.f;
#pragma unroll 8
      for (int c = 0; c < 64; c++) ps += __expf(s_f32[r * 65 + c] - pm);
      size_t o = (size_t)(b * KN + i0 + r) * gridDim.x + blockIdx.x;
      prm[o] = pm;
      SEL(prs)[o] = ps;
    } else if (tid < 192) {
      int c = tid - 128;
      float pm = -1e30f;
#pragma unroll 8
      for (int r = 0; r < 128; r++) pm = fmaxf(pm, s_f32[r * 65 + c]);
      float ps = 0.f;
#pragma unroll 8
      for (int r = 0; r < 128; r++) ps += __expf(s_f32[r * 65 + c] - pm);
      size_t o = (size_t)(b * KN + n0 + c) * gridDim.y + blockIdx.y;
      SEL(pcm)[o] = pm;
      SEL(pcs)[o] = ps;
    }
  }
  if (float* pbs = SEL(pbs)) {
    if (tid < 128) {
      int r = tid;
      float s = 0.f, s2 = 0.f;
#pragma unroll 8
      for (int c = 0; c < 64; c++) {
        float v = s_f32[r * 65 + c];
        s += v;
        s2 += v * v;
      }
      size_t o = ((size_t)(i0 + r) * KB + b) * gridDim.x + blockIdx.x;
      pbs[o] = s;
      SEL(pbs2)[o] = s2;
    }
  }
#undef SEL
}

// =============================================================================
// merged transpose + split: [C][N] fp32 -> [N][C] bf16 hi/lo, both halves
// =============================================================================
__global__ __launch_bounds__(256) void transpose_split(
    const float* __restrict__ in0, const float* __restrict__ in1,
    bf16* __restrict__ oh0, bf16* __restrict__ ol0, bf16* __restrict__ oh1,
    bf16* __restrict__ ol1) {
  __shared__ float t[32][33];
  int z = blockIdx.z;
  int half = z >> 4, b = z & (KB - 1);
  const float* ib = (half ? in1 : in0) + (size_t)b * KC * KN;
  bf16* ohb = (half ? oh1 : oh0) + (size_t)b * KC * KN;
  bf16* olb = (half ? ol1 : ol0) + (size_t)b * KC * KN;
  int n0 = blockIdx.x * 32, c0 = blockIdx.y * 32;
  int x = threadIdx.x, y = threadIdx.y;
#pragma unroll
  for (int j = 0; j < 4; j++)
    t[y + 8 * j][x] = ib[(size_t)(c0 + y + 8 * j) * KN + n0 + x];
  __syncthreads();
#pragma unroll
  for (int j = 0; j < 4; j++) {
    float v = t[x][y + 8 * j];
    bf16 h = __float2bfloat16_rn(v);
    size_t o = (size_t)(n0 + y + 8 * j) * KC + c0 + x;
    ohb[o] = h;
    olb[o] = __float2bfloat16_rn(v - __bfloat162float(h));
  }
}

// =============================================================================
// convert 4 weight matrices (each 131072 elems) to hi/lo
// =============================================================================
__global__ __launch_bounds__(256) void convert_w(
    const float* __restrict__ s0, const float* __restrict__ s1,
    const float* __restrict__ s2, const float* __restrict__ s3) {
  int idx = blockIdx.x * 256 + threadIdx.x;
  int sel = idx >> 17, w = idx & 131071;
  const float* s = sel == 0 ? s0 : sel == 1 ? s1 : sel == 2 ? s2 : s3;
  bf16* h = sel == 0 ? g_wgr_h : sel == 1 ? g_wgf_h : sel == 2 ? g_wwr_h
                                                               : g_wwf_h;
  bf16* l = sel == 0 ? g_wgr_l : sel == 1 ? g_wgf_l : sel == 2 ? g_wwr_l
                                                               : g_wwf_l;
  float v = s[w];
  bf16 hh = __float2bfloat16_rn(v);
  h[w] = hh;
  l[w] = __float2bfloat16_rn(v - __bfloat162float(hh));
}

// =============================================================================
// combine softmax partials
// =============================================================================
__global__ __launch_bounds__(256) void softmax_combine() {
  int t = blockIdx.x * 256 + threadIdx.x;
  const int total = KB * KN;
  if (t < total) {
    float m = -1e30f;
#pragma unroll
    for (int j = 0; j < 16; j++) m = fmaxf(m, g_prm[t * 16 + j]);
    float s = 0.f;
#pragma unroll
    for (int j = 0; j < 16; j++)
      s += g_prs[t * 16 + j] * __expf(g_prm[t * 16 + j] - m);
    g_rmax[t] = m;
    g_rsum[t] = s;
  } else if (t < 2 * total) {
    int u = t - total;
    float m = -1e30f;
#pragma unroll
    for (int j = 0; j < 8; j++) m = fmaxf(m, g_pcm[u * 8 + j]);
    float s = 0.f;
#pragma unroll
    for (int j = 0; j < 8; j++)
      s += g_pcs[u * 8 + j] * __expf(g_pcm[u * 8 + j] - m);
    g_cmax[u] = m;
    g_csum[u] = s;
  }
}

// =============================================================================
// BN combine + merged finalize
// =============================================================================
__global__ __launch_bounds__(256) void bnfinal_kernel() {
  int t = blockIdx.x * 256 + threadIdx.x;
  if (t >= 2 * KC) return;
  float s = 0.f, s2 = 0.f;
  for (int j = 0; j < KB * 16; j++) {
    s += g_pbs[(size_t)t * (KB * 16) + j];
    s2 += g_pbs2[(size_t)t * (KB * 16) + j];
  }
  float m = s / (float)(KB * KN);
  float var = s2 / (float)(KB * KN) - m * m;
  g_mean[t] = m;
  g_rstd[t] = rsqrtf(var + 1e-5f);
}

__global__ __launch_bounds__(256) void finalize_kernel(
    const float* __restrict__ X0, const float* __restrict__ X1,
    const float* __restrict__ gamma0, const float* __restrict__ beta0,
    const float* __restrict__ gamma1, const float* __restrict__ beta1,
    float* __restrict__ Z) {
  size_t idx = (size_t)blockIdx.x * 256 + threadIdx.x;
  int sel = (int)(idx >> 23);  // KB*KC*KN = 2^23
  size_t li = idx & ((1ull << 23) - 1);
  int c = (int)((idx >> 10) & (KC - 1));
  float m = g_mean[sel * KC + c];
  float r = g_rstd[sel * KC + c];
  float g = sel ? gamma1[c] : gamma0[c];
  float be = sel ? beta1[c] : beta0[c];
  float x = sel ? X1[li] : X0[li];
  Z[idx] = (g_t[idx] - m) * r * g + be + x;
}

// =============================================================================
extern "C" void kernel_launch(void* const* d_in, const int* in_sizes, int n_in,
                              void* d_out, int out_size) {
  const float* rgb        = (const float*)d_in[0];
  const float* flow       = (const float*)d_in[1];
  const float* wg_rgb     = (const float*)d_in[2];
  const float* bg_rgb     = (const float*)d_in[3];
  const float* wg_flow    = (const float*)d_in[4];
  const float* bg_flow    = (const float*)d_in[5];
  const float* ww_rgb     = (const float*)d_in[6];
  const float* bw_rgb     = (const float*)d_in[7];
  const float* gamma_rgb  = (const float*)d_in[8];
  const float* beta_rgb   = (const float*)d_in[9];
  const float* ww_flow    = (const float*)d_in[10];
  const float* bw_flow    = (const float*)d_in[11];
  const float* gamma_flow = (const float*)d_in[12];
  const float* beta_flow  = (const float*)d_in[13];
  float* out = (float*)d_out;

#define SYM(p, g) cudaGetSymbolAddress((void**)&p, g)
  bf16 *rgbT_h, *rgbT_l, *flowT_h, *flowT_l;
  bf16 *wgr_h, *wgr_l, *wgf_h, *wgf_l, *wwr_h, *wwr_l, *wwf_h, *wwf_l;
  bf16 *re_h, *re_l, *fe_h, *fe_l, *reT_h, *reT_l, *feT_h, *feT_l;
  bf16 *yrT_h, *yrT_l, *yfT_h, *yfT_l;
  float *pS, *pS2, *prmax, *prsum, *pcmax, *pcsum, *pt;
  float *pprm, *pprs, *ppcm, *ppcs, *ppbs, *ppbs2;
  SYM(rgbT_h, g_rgbT_h); SYM(rgbT_l, g_rgbT_l);
  SYM(flowT_h, g_flowT_h); SYM(flowT_l, g_flowT_l);
  SYM(wgr_h, g_wgr_h); SYM(wgr_l, g_wgr_l);
  SYM(wgf_h, g_wgf_h); SYM(wgf_l, g_wgf_l);
  SYM(wwr_h, g_wwr_h); SYM(wwr_l, g_wwr_l);
  SYM(wwf_h, g_wwf_h); SYM(wwf_l, g_wwf_l);
  SYM(re_h, g_re_h); SYM(re_l, g_re_l);
  SYM(fe_h, g_fe_h); SYM(fe_l, g_fe_l);
  SYM(reT_h, g_reT_h); SYM(reT_l, g_reT_l);
  SYM(feT_h, g_feT_h); SYM(feT_l, g_feT_l);
  SYM(yrT_h, g_yrT_h); SYM(yrT_l, g_yrT_l);
  SYM(yfT_h, g_yfT_h); SYM(yfT_l, g_yfT_l);
  SYM(pS, g_S); SYM(pS2, g_S2);
  SYM(prmax, g_rmax); SYM(prsum, g_rsum);
  SYM(pcmax, g_cmax); SYM(pcsum, g_csum);
  SYM(pt, g_t);
  SYM(pprm, g_prm); SYM(pprs, g_prs);
  SYM(ppcm, g_pcm); SYM(ppcs, g_pcs);
  SYM(ppbs, g_pbs); SYM(ppbs2, g_pbs2);
#undef SYM

  cudaFuncSetAttribute(gemm_bf16, cudaFuncAttributeMaxDynamicSharedMemorySize,
                       SMEM_DYN);
  dim3 thr(256);
  const unsigned long long sEN = (unsigned long long)KCI * KN;
  const unsigned long long sET = (unsigned long long)KN * KCI;
  const unsigned long long sXT = (unsigned long long)KN * KC;
  const unsigned long long sSS = (unsigned long long)KN * KN;
  const unsigned long long sT = (unsigned long long)KC * KN;

  GArg z{};  // all-null template

  // 1) merged input transpose+split; weight conversion
  transpose_split<<<dim3(KN / 32, KC / 32, 2 * KB), dim3(32, 8)>>>(
      rgb, flow, rgbT_h, rgbT_l, flowT_h, flowT_l);
  convert_w<<<2048, thr>>>(wg_rgb, wg_flow, ww_rgb, ww_flow);

  // 2) merged embeds: E = W @ XT^T -> normal pair + transposed pair
  {
    GArg a0 = z, a1 = z;
    a0.Ah = wgr_h; a0.Al = wgr_l; a0.Bh = rgbT_h; a0.Bl = rgbT_l;
    a0.bias = bg_rgb; a0.oNh = re_h; a0.oNl = re_l; a0.oTh = reT_h;
    a0.oTl = reT_l;
    a1.Ah = wgf_h; a1.Al = wgf_l; a1.Bh = flowT_h; a1.Bl = flowT_l;
    a1.bias = bg_flow; a1.oNh = fe_h; a1.oNl = fe_l; a1.oTh = feT_h;
    a1.oTl = feT_l;
    gemm_bf16<<<dim3(16, 2, 2 * KB), thr, SMEM_DYN>>>(
        a0, a1, 0ull, KC, sXT, KC, 0ull, 0, 0ull, 0, sEN, KN, sET, KCI, KC);
  }

  // 3) scores: S fp32 + S2 fp32 + softmax partials
  {
    GArg a0 = z;
    a0.Ah = reT_h; a0.Al = reT_l; a0.Bh = feT_h; a0.Bl = feT_l;
    a0.oNf = pS; a0.oTf = pS2;
    a0.prm = pprm; a0.prs = pprs; a0.pcm = ppcm; a0.pcs = ppcs;
    gemm_bf16<<<dim3(16, 8, KB), thr, SMEM_DYN>>>(
        a0, a0, sET, KCI, sET, KCI, sSS, KN, sSS, KN, 0ull, 0, 0ull, 0, KCI);
  }

  // 4) stats combine
  softmax_combine<<<(2 * KB * KN) / 256, thr>>>();

  // 5) merged applies: exp fused into B staging, output = y^T pair
  {
    GArg a0 = z, a1 = z;
    a0.Ah = fe_h; a0.Al = fe_l; a0.Bf = pS; a0.mxv = prmax; a0.sumv = prsum;
    a0.oTh = yrT_h; a0.oTl = yrT_l;
    a1.Ah = re_h; a1.Al = re_l; a1.Bf = pS2; a1.mxv = pcmax; a1.sumv = pcsum;
    a1.oTh = yfT_h; a1.oTl = yfT_l;
    gemm_bf16<<<dim3(16, 2, 2 * KB), thr, SMEM_DYN>>>(
        a0, a1, sEN, KN, sSS, KN, 0ull, 0, 0ull, 0, 0ull, 0, sET, KCI, KN);
  }

  // 6) merged conv2: T = W @ YT^T + bias (fp32 out) + BN partials
  {
    GArg a0 = z, a1 = z;
    a0.Ah = wwr_h; a0.Al = wwr_l; a0.Bh = yrT_h; a0.Bl = yrT_l;
    a0.bias = bw_rgb; a0.oNf = pt; a0.pbs = ppbs; a0.pbs2 = ppbs2;
    a1.Ah = wwf_h; a1.Al = wwf_l; a1.Bh = yfT_h; a1.Bl = yfT_l;
    a1.bias = bw_flow; a1.oNf = pt + (size_t)KB * KC * KN;
    a1.pbs = ppbs + (size_t)KC * KB * 16;
    a1.pbs2 = ppbs2 + (size_t)KC * KB * 16;
    gemm_bf16<<<dim3(16, 4, 2 * KB), thr, SMEM_DYN>>>(
        a0, a1, 0ull, KCI, sET, KCI, sT, KN, 0ull, 0, 0ull, 0, 0ull, 0, KCI);
  }

  // 7) BN combine + merged finalize
  bnfinal_kernel<<<4, thr>>>();
  finalize_kernel<<<(2 * KB * KC * KN) / 256, thr>>>(
      rgb, flow, gamma_rgb, beta_rgb, gamma_flow, beta_flow, out);
}

// round 9
// speedup vs baseline: 1.6018x; 1.0051x over previous
#include <cuda_runtime.h>
#include <cuda_bf16.h>
#include <cstdint>

#define KB 16
#define KC 512
#define KCI 256
#define KN 1024

typedef __nv_bfloat16 bf16;
typedef __nv_bfloat162 bf162;

// ---------------- scratch (no allocs allowed -> __device__ globals) ----------
__device__ bf16 g_rgbT_h[(size_t)KB * KN * KC];
__device__ bf16 g_rgbT_l[(size_t)KB * KN * KC];
__device__ bf16 g_flowT_h[(size_t)KB * KN * KC];
__device__ bf16 g_flowT_l[(size_t)KB * KN * KC];
__device__ bf16 g_wgr_h[KCI * KC], g_wgr_l[KCI * KC];
__device__ bf16 g_wgf_h[KCI * KC], g_wgf_l[KCI * KC];
__device__ bf16 g_wwr_h[KC * KCI], g_wwr_l[KC * KCI];
__device__ bf16 g_wwf_h[KC * KCI], g_wwf_l[KC * KCI];
__device__ bf16 g_re_h[(size_t)KB * KCI * KN], g_re_l[(size_t)KB * KCI * KN];
__device__ bf16 g_fe_h[(size_t)KB * KCI * KN], g_fe_l[(size_t)KB * KCI * KN];
__device__ bf16 g_reT_h[(size_t)KB * KN * KCI], g_reT_l[(size_t)KB * KN * KCI];
__device__ bf16 g_feT_h[(size_t)KB * KN * KCI], g_feT_l[(size_t)KB * KN * KCI];
__device__ float g_S[(size_t)KB * KN * KN];
__device__ bf16 g_yrT_h[(size_t)KB * KN * KCI], g_yrT_l[(size_t)KB * KN * KCI];
__device__ bf16 g_yfT_h[(size_t)KB * KN * KCI], g_yfT_l[(size_t)KB * KN * KCI];
__device__ float g_t[2 * (size_t)KB * KC * KN];
__device__ float g_mean[2 * KC];
__device__ float g_rstd[2 * KC];
__device__ float g_rmax[KB * KN], g_rsum[KB * KN];
__device__ float g_cmax[KB * KN], g_csum[KB * KN];
__device__ float g_prm[KB * KN * 16], g_prs[KB * KN * 16];
__device__ float g_pcm[KB * KN * 8], g_pcs[KB * KN * 8];
__device__ float g_pbs[2 * KC * KB * 16], g_pbs2[2 * KC * KB * 16];

// ============================ helpers ========================================
__device__ __forceinline__ uint32_t smem_u32(const void* p) {
  uint32_t a;
  asm("{ .reg .u64 t; cvta.to.shared.u64 t, %1; cvt.u32.u64 %0, t; }"
      : "=r"(a) : "l"(p));
  return a;
}

#define CP16(dst, src)                                                         \
  asm volatile("cp.async.cg.shared.global [%0], [%1], 16;" ::"r"(dst),         \
               "l"(src))
#define CP_COMMIT() asm volatile("cp.async.commit_group;")
#define CP_WAIT1() asm volatile("cp.async.wait_group 1;")
#define CP_WAIT2() asm volatile("cp.async.wait_group 2;")
#define CP_WAIT0() asm volatile("cp.async.wait_group 0;")

__device__ __forceinline__ void ldm_x4(uint32_t addr, uint32_t& r0,
                                       uint32_t& r1, uint32_t& r2,
                                       uint32_t& r3) {
  asm volatile(
      "ldmatrix.sync.aligned.m8n8.x4.shared.b16 {%0,%1,%2,%3}, [%4];"
      : "=r"(r0), "=r"(r1), "=r"(r2), "=r"(r3) : "r"(addr));
}

__device__ __forceinline__ void mma_bf16(float* d, const uint32_t* a,
                                         const uint32_t* b) {
  asm volatile(
      "mma.sync.aligned.m16n8k16.row.col.f32.bf16.bf16.f32 "
      "{%0,%1,%2,%3}, {%4,%5,%6,%7}, {%8,%9}, {%0,%1,%2,%3};"
      : "+f"(d[0]), "+f"(d[1]), "+f"(d[2]), "+f"(d[3])
      : "r"(a[0]), "r"(a[1]), "r"(a[2]), "r"(a[3]), "r"(b[0]), "r"(b[1]));
}

// fold swizzle: two 64B logical rows per 128B phys row, SW128 on phys rows.
__device__ __forceinline__ uint32_t fold_off(int r, int byte) {
  uint32_t off = (uint32_t)(((r >> 1) << 7) + ((r & 1) << 6) + byte);
  return off ^ ((off >> 3) & 0x70);
}

__device__ __forceinline__ void split2(float x, float y, uint32_t& h,
                                       uint32_t& l) {
  bf162 hh = __floats2bfloat162_rn(x, y);
  bf162 ll = __floats2bfloat162_rn(x - __low2float(hh), y - __high2float(hh));
  h = *(uint32_t*)&hh;
  l = *(uint32_t*)&ll;
}

__device__ __forceinline__ float4 lds128(uint32_t a) {
  float4 v;
  asm volatile("ld.shared.v4.f32 {%0,%1,%2,%3}, [%4];"
               : "=f"(v.x), "=f"(v.y), "=f"(v.z), "=f"(v.w) : "r"(a));
  return v;
}
__device__ __forceinline__ void sts64(uint32_t a, uint32_t x, uint32_t y) {
  asm volatile("st.shared.v2.b32 [%0], {%1,%2};" ::"r"(a), "r"(x), "r"(y));
}
__device__ __forceinline__ void sts128(uint32_t a, uint32_t x, uint32_t y,
                                       uint32_t z, uint32_t w) {
  asm volatile("st.shared.v4.b32 [%0], {%1,%2,%3,%4};" ::"r"(a), "r"(x),
               "r"(y), "r"(z), "r"(w));
}

// smem layout: 4 A-stages (16KB), 4 B-stages (8KB), exp pair ping-pong 16KB.
#define A_STG 16384
#define B_STG 8192
#define OFF_BSTG 65536
#define OFF_PAIR 98304
#define SMEM_DYN (114688 + 1024)

struct GArg {
  const bf16 *Ah, *Al, *Bh, *Bl;
  const float *Bf, *mxv, *sumv, *bias;
  float *oNf;
  bf16 *oNh, *oNl, *oTh, *oTl;
  float *prm, *prs, *pcm, *pcs, *pbs, *pbs2;
  int trans;
};

// stage one K=32 chunk into stage slot s
__device__ __forceinline__ void stage32(uint32_t u_sb, int s, const bf16* Ah,
                                        const bf16* Al, int lda,
                                        const bf16* Bh, const bf16* Bl,
                                        const float* Bf, int ldb, int tid,
                                        int k0, bool expm, int trans) {
  uint32_t abase = u_sb + (uint32_t)s * A_STG;
  uint32_t bbase = u_sb + OFF_BSTG + (uint32_t)s * B_STG;
#pragma unroll
  for (int t = 0; t < 2; t++) {
    int idx = tid + (t << 8);
    int r = idx >> 2, q = idx & 3;
    uint32_t o = fold_off(r, q << 4);
    CP16(abase + o, Ah + (size_t)r * lda + k0 + (q << 3));
    CP16(abase + 8192 + o, Al + (size_t)r * lda + k0 + (q << 3));
  }
  if (expm) {
    if (trans) {
      // rows = k (32 of them, stride ldb), cols = m (64 floats = 256B rows)
#pragma unroll
      for (int t = 0; t < 2; t++) {
        int idx = tid + (t << 8);
        int r = idx >> 4, q = idx & 15;
        CP16(bbase + (r << 8) + (q << 4),
             Bf + (size_t)(k0 + r) * ldb + (q << 2));
      }
    } else {
#pragma unroll
      for (int t = 0; t < 2; t++) {
        int idx = tid + (t << 8);
        int r = idx >> 3, q = idx & 7;
        CP16(bbase + (r << 7) + (q << 4), Bf + (size_t)r * ldb + k0 + (q << 2));
      }
    }
  } else {
    int r = tid >> 2, q = tid & 3;
    uint32_t o = fold_off(r, q << 4);
    CP16(bbase + o, Bh + (size_t)r * ldb + k0 + (q << 3));
    CP16(bbase + 4096 + o, Bl + (size_t)r * ldb + k0 + (q << 3));
  }
}

// convert fp32 B chunk -> bf16 pair (row-major source: rows m, cols k)
__device__ __forceinline__ void convert_chunk(uint32_t u_sb, int c, int cr0,
                                              int cq, float mx0, float iv0,
                                              float mx1, float iv1) {
  uint32_t srcb = u_sb + OFF_BSTG + (uint32_t)(c & 3) * B_STG;
  uint32_t pb = u_sb + OFF_PAIR + ((c & 1) << 13);
  float4 v0 = lds128(srcb + (cr0 << 7) + (cq << 4));
  float4 v1 = lds128(srcb + ((cr0 + 32) << 7) + (cq << 4));
  float e0 = __expf(v0.x - mx0) * iv0, e1 = __expf(v0.y - mx0) * iv0;
  float e2 = __expf(v0.z - mx0) * iv0, e3 = __expf(v0.w - mx0) * iv0;
  float f0 = __expf(v1.x - mx1) * iv1, f1 = __expf(v1.y - mx1) * iv1;
  float f2 = __expf(v1.z - mx1) * iv1, f3 = __expf(v1.w - mx1) * iv1;
  uint32_t o0 = fold_off(cr0, (cq >> 1) << 4) + ((cq & 1) << 3);
  uint32_t o1 = fold_off(cr0 + 32, (cq >> 1) << 4) + ((cq & 1) << 3);
  uint32_t h0, l0, h1, l1;
  split2(e0, e1, h0, l0);
  split2(e2, e3, h1, l1);
  sts64(pb + o0, h0, h1);
  sts64(pb + 4096 + o0, l0, l1);
  split2(f0, f1, h0, l0);
  split2(f2, f3, h1, l1);
  sts64(pb + o1, h0, h1);
  sts64(pb + 4096 + o1, l0, l1);
}

// transposed convert: source rows = k (32 x 256B), output pair rows = m
__device__ __forceinline__ void convert_chunk_T(uint32_t u_sb, int c, int tid,
                                                float mxT, float ivT) {
  uint32_t srcb = u_sb + OFF_BSTG + (uint32_t)(c & 3) * B_STG;
  uint32_t pb = u_sb + OFF_PAIR + ((c & 1) << 13);
  int m = tid & 63;
  int kg = (tid >> 6) << 3;  // 0,8,16,24
  float v[8];
#pragma unroll
  for (int j = 0; j < 8; j++) {
    float x;
    asm volatile("ld.shared.f32 %0, [%1];"
                 : "=f"(x)
                 : "r"(srcb + (uint32_t)((kg + j) << 8) + (uint32_t)(m << 2)));
    v[j] = __expf(x - mxT) * ivT;
  }
  uint32_t h[4], l[4];
#pragma unroll
  for (int j = 0; j < 4; j++) split2(v[2 * j], v[2 * j + 1], h[j], l[j]);
  uint32_t o = fold_off(m, kg << 1);
  sts128(pb + o, h[0], h[1], h[2], h[3]);
  sts128(pb + 4096 + o, l[0], l[1], l[2], l[3]);
}

// =============================================================================
// bf16-pair HMMA GEMM, K=32 chunks, 4-stage cp.async pipeline, 1 sync/chunk.
// =============================================================================
__global__ __launch_bounds__(256, 2) void gemm_bf16(
    GArg a0, GArg a1,
    unsigned long long sA, int lda, unsigned long long sB, int ldb,
    unsigned long long soNf, int ldoNf,
    unsigned long long soN, int ldoN, unsigned long long soT, int ldoT,
    int K) {
  extern __shared__ char s_dyn[];
  char* sb = (char*)(((uintptr_t)s_dyn + 1023) & ~(uintptr_t)1023);
  float* s_f32 = (float*)sb;  // epilogue staging [128][65]
  uint32_t u_sb = smem_u32(sb);

  int tid = threadIdx.x;
  int wid = tid >> 5, lane = tid & 31;
  int wr = wid & 3, wc = wid >> 2;
  int half = blockIdx.z >> 4;
  int b = blockIdx.z & (KB - 1);
  int i0 = blockIdx.y * 128;
  int n0 = blockIdx.x * 64;
#define SEL(f) (half ? a1.f : a0.f)
  const float* mxv = SEL(mxv);
  bool expm = (mxv != nullptr);
  int trans = SEL(trans);

  const bf16* Ah = SEL(Ah) + (size_t)b * sA + (size_t)i0 * lda;
  const bf16* Al = SEL(Al) + (size_t)b * sA + (size_t)i0 * lda;
  const bf16* Bh = expm ? nullptr : SEL(Bh) + (size_t)b * sB + (size_t)n0 * ldb;
  const bf16* Bl = expm ? nullptr : SEL(Bl) + (size_t)b * sB + (size_t)n0 * ldb;
  const float* Bf = nullptr;
  if (expm) {
    Bf = SEL(Bf) + (size_t)b * sB;
    if (trans) Bf += n0;
    else Bf += (size_t)n0 * ldb;
  }

  float mx0 = 0.f, iv0 = 1.f, mx1 = 0.f, iv1 = 1.f;
  int cr0 = tid >> 3, cq = tid & 7;
  if (expm) {
    const float* sumv = SEL(sumv);
    if (trans) {
      mx0 = mxv[b * KN + n0 + (tid & 63)];
      iv0 = 1.0f / sumv[b * KN + n0 + (tid & 63)];
    } else {
      mx0 = mxv[b * KN + n0 + cr0];
      iv0 = 1.0f / sumv[b * KN + n0 + cr0];
      mx1 = mxv[b * KN + n0 + cr0 + 32];
      iv1 = 1.0f / sumv[b * KN + n0 + cr0 + 32];
    }
  }

  int aRow = lane & 15, aCb = (lane >> 4) * 16;
  int bRow = ((lane >> 4) & 1) * 8 + (lane & 7);
  int bCb = ((lane >> 3) & 1) * 16;

  float acc[2][4][4];
#pragma unroll
  for (int mi = 0; mi < 2; mi++)
#pragma unroll
    for (int ni = 0; ni < 4; ni++)
#pragma unroll
      for (int e = 0; e < 4; e++) acc[mi][ni][e] = 0.f;

  int NC = K >> 5;
#pragma unroll
  for (int p = 0; p < 3; p++) {
    stage32(u_sb, p, Ah, Al, lda, Bh, Bl, Bf, ldb, tid, p << 5, expm, trans);
    CP_COMMIT();
  }
  if (expm) {
    CP_WAIT2();
    __syncthreads();
    if (trans) convert_chunk_T(u_sb, 0, tid, mx0, iv0);
    else convert_chunk(u_sb, 0, cr0, cq, mx0, iv0, mx1, iv1);
  }

  for (int ch = 0; ch < NC; ch++) {
    if (expm) CP_WAIT1(); else CP_WAIT2();
    __syncthreads();
    if (ch + 3 < NC)
      stage32(u_sb, (ch + 3) & 3, Ah, Al, lda, Bh, Bl, Bf, ldb, tid,
              (ch + 3) << 5, expm, trans);
    CP_COMMIT();
    if (expm && ch + 1 < NC) {
      if (trans) convert_chunk_T(u_sb, ch + 1, tid, mx0, iv0);
      else convert_chunk(u_sb, ch + 1, cr0, cq, mx0, iv0, mx1, iv1);
    }

    uint32_t sA_base = u_sb + (uint32_t)(ch & 3) * A_STG;
    uint32_t bh_base, bl_base;
    if (expm) {
      uint32_t pb = u_sb + OFF_PAIR + ((ch & 1) << 13);
      bh_base = pb;
      bl_base = pb + 4096;
    } else {
      uint32_t bb = u_sb + OFF_BSTG + (uint32_t)(ch & 3) * B_STG;
      bh_base = bb;
      bl_base = bb + 4096;
    }
#pragma unroll
    for (int ks = 0; ks < 2; ks++) {
      int kb = ks << 5;
      uint32_t ah[2][4], al[2][4], bh2[2][4], bl2[2][4];
#pragma unroll
      for (int mi = 0; mi < 2; mi++) {
        int r = wr * 32 + mi * 16 + aRow;
        uint32_t o = fold_off(r, kb + aCb);
        ldm_x4(sA_base + o, ah[mi][0], ah[mi][1], ah[mi][2], ah[mi][3]);
        ldm_x4(sA_base + 8192 + o, al[mi][0], al[mi][1], al[mi][2], al[mi][3]);
      }
#pragma unroll
      for (int ng = 0; ng < 2; ng++) {
        int r = wc * 32 + ng * 16 + bRow;
        uint32_t o = fold_off(r, kb + bCb);
        ldm_x4(bh_base + o, bh2[ng][0], bh2[ng][1], bh2[ng][2], bh2[ng][3]);
        ldm_x4(bl_base + o, bl2[ng][0], bl2[ng][1], bl2[ng][2], bl2[ng][3]);
      }
#pragma unroll
      for (int mi = 0; mi < 2; mi++)
#pragma unroll
        for (int ni = 0; ni < 4; ni++) {
          float* d = acc[mi][ni];
          const uint32_t* bhp = &bh2[ni >> 1][(ni & 1) * 2];
          const uint32_t* blp = &bl2[ni >> 1][(ni & 1) * 2];
          mma_bf16(d, ah[mi], bhp);
          mma_bf16(d, ah[mi], blp);
          mma_bf16(d, al[mi], bhp);
        }
    }
  }
  CP_WAIT0();
  __syncthreads();

  // --------------------------- epilogue --------------------------------------
  const float* bias = SEL(bias);
#pragma unroll
  for (int mi = 0; mi < 2; mi++) {
    int rl = wr * 32 + mi * 16 + (lane >> 2);
    float bv0 = bias ? __ldg(bias + i0 + rl) : 0.f;
    float bv1 = bias ? __ldg(bias + i0 + rl + 8) : 0.f;
#pragma unroll
    for (int ni = 0; ni < 4; ni++) {
      int c = wc * 32 + ni * 8 + 2 * (lane & 3);
      s_f32[rl * 65 + c] = acc[mi][ni][0] + bv0;
      s_f32[rl * 65 + c + 1] = acc[mi][ni][1] + bv0;
      s_f32[(rl + 8) * 65 + c] = acc[mi][ni][2] + bv1;
      s_f32[(rl + 8) * 65 + c + 1] = acc[mi][ni][3] + bv1;
    }
  }
  __syncthreads();

  if (float* oNf = SEL(oNf)) {
    float* on = oNf + (size_t)b * soNf;
#pragma unroll
    for (int t = 0; t < 8; t++) {
      int idx = tid + (t << 8);
      int rr = idx >> 4, q = idx & 15;
      float4 v;
      v.x = s_f32[rr * 65 + q * 4 + 0];
      v.y = s_f32[rr * 65 + q * 4 + 1];
      v.z = s_f32[rr * 65 + q * 4 + 2];
      v.w = s_f32[rr * 65 + q * 4 + 3];
      *(float4*)(on + (size_t)(i0 + rr) * ldoNf + n0 + (q << 2)) = v;
    }
  }
  if (bf16* oNh = SEL(oNh)) {
    bf16* oh = oNh + (size_t)b * soN;
    bf16* ol = SEL(oNl) + (size_t)b * soN;
#pragma unroll
    for (int t = 0; t < 8; t++) {
      int idx = tid + (t << 8);
      int rr = idx >> 4, q = idx & 15;
      uint32_t h0, l0, h1, l1;
      split2(s_f32[rr * 65 + q * 4 + 0], s_f32[rr * 65 + q * 4 + 1], h0, l0);
      split2(s_f32[rr * 65 + q * 4 + 2], s_f32[rr * 65 + q * 4 + 3], h1, l1);
      size_t base = (size_t)(i0 + rr) * ldoN + n0 + (q << 2);
      *(uint32_t*)(oh + base) = h0;
      *(uint32_t*)(oh + base + 2) = h1;
      *(uint32_t*)(ol + base) = l0;
      *(uint32_t*)(ol + base + 2) = l1;
    }
  }
  if (bf16* oTh = SEL(oTh)) {
    bf16* oh = oTh + (size_t)b * soT;
    bf16* ol = SEL(oTl) + (size_t)b * soT;
#pragma unroll
    for (int t = 0; t < 8; t++) {
      int idx = tid + (t << 8);
      int c = idx >> 5, rq = (idx & 31) << 2;
      uint32_t h0, l0, h1, l1;
      split2(s_f32[(rq + 0) * 65 + c], s_f32[(rq + 1) * 65 + c], h0, l0);
      split2(s_f32[(rq + 2) * 65 + c], s_f32[(rq + 3) * 65 + c], h1, l1);
      size_t base = (size_t)(n0 + c) * ldoT + i0 + rq;
      *(uint32_t*)(oh + base) = h0;
      *(uint32_t*)(oh + base + 2) = h1;
      *(uint32_t*)(ol + base) = l0;
      *(uint32_t*)(ol + base + 2) = l1;
    }
  }
  if (float* prm = SEL(prm)) {
    {  // row partials: 2 threads per row
      int r = tid >> 1, hh = tid & 1;
      float pm = -1e30f;
#pragma unroll 8
      for (int j = 0; j < 32; j++) {
        int c = hh * 32 + ((j + 16 * hh) & 31);
        pm = fmaxf(pm, s_f32[r * 65 + c]);
      }
      pm = fmaxf(pm, __shfl_xor_sync(0xffffffffu, pm, 1));
      float ps = 0.f;
#pragma unroll 8
      for (int j = 0; j < 32; j++) {
        int c = hh * 32 + ((j + 16 * hh) & 31);
        ps += __expf(s_f32[r * 65 + c] - pm);
      }
      ps += __shfl_xor_sync(0xffffffffu, ps, 1);
      if (hh == 0) {
        size_t o = (size_t)(b * KN + i0 + r) * gridDim.x + blockIdx.x;
        prm[o] = pm;
        SEL(prs)[o] = ps;
      }
    }
    {  // col partials: 4 threads per col
      int c = tid >> 2, qu = tid & 3;
      float pm = -1e30f;
#pragma unroll 8
      for (int j = 0; j < 32; j++) {
        int r = qu * 32 + ((j + 8 * qu) & 31);
        pm = fmaxf(pm, s_f32[r * 65 + c]);
      }
      pm = fmaxf(pm, __shfl_xor_sync(0xffffffffu, pm, 1));
      pm = fmaxf(pm, __shfl_xor_sync(0xffffffffu, pm, 2));
      float ps = 0.f;
#pragma unroll 8
      for (int j = 0; j < 32; j++) {
        int r = qu * 32 + ((j + 8 * qu) & 31);
        ps += __expf(s_f32[r * 65 + c] - pm);
      }
      ps += __shfl_xor_sync(0xffffffffu, ps, 1);
      ps += __shfl_xor_sync(0xffffffffu, ps, 2);
      if (qu == 0) {
        size_t o = (size_t)(b * KN + n0 + c) * gridDim.y + blockIdx.y;
        SEL(pcm)[o] = pm;
        SEL(pcs)[o] = ps;
      }
    }
  }
  if (float* pbs = SEL(pbs)) {  // BN partials: 2 threads per row
    int r = tid >> 1, hh = tid & 1;
    float s = 0.f, s2 = 0.f;
#pragma unroll 8
    for (int j = 0; j < 32; j++) {
      int c = hh * 32 + ((j + 16 * hh) & 31);
      float v = s_f32[r * 65 + c];
      s += v;
      s2 += v * v;
    }
    s += __shfl_xor_sync(0xffffffffu, s, 1);
    s2 += __shfl_xor_sync(0xffffffffu, s2, 1);
    if (hh == 0) {
      size_t o = ((size_t)(i0 + r) * KB + b) * gridDim.x + blockIdx.x;
      pbs[o] = s;
      SEL(pbs2)[o] = s2;
    }
  }
#undef SEL
}

// =============================================================================
// merged transpose + split: [C][N] fp32 -> [N][C] bf16 hi/lo, both halves
// =============================================================================
__global__ __launch_bounds__(256) void transpose_split(
    const float* __restrict__ in0, const float* __restrict__ in1,
    bf16* __restrict__ oh0, bf16* __restrict__ ol0, bf16* __restrict__ oh1,
    bf16* __restrict__ ol1) {
  __shared__ float t[32][33];
  int z = blockIdx.z;
  int half = z >> 4, b = z & (KB - 1);
  const float* ib = (half ? in1 : in0) + (size_t)b * KC * KN;
  bf16* ohb = (half ? oh1 : oh0) + (size_t)b * KC * KN;
  bf16* olb = (half ? ol1 : ol0) + (size_t)b * KC * KN;
  int n0 = blockIdx.x * 32, c0 = blockIdx.y * 32;
  int x = threadIdx.x, y = threadIdx.y;
#pragma unroll
  for (int j = 0; j < 4; j++)
    t[y + 8 * j][x] = ib[(size_t)(c0 + y + 8 * j) * KN + n0 + x];
  __syncthreads();
#pragma unroll
  for (int j = 0; j < 4; j++) {
    float v = t[x][y + 8 * j];
    bf16 h = __float2bfloat16_rn(v);
    size_t o = (size_t)(n0 + y + 8 * j) * KC + c0 + x;
    ohb[o] = h;
    olb[o] = __float2bfloat16_rn(v - __bfloat162float(h));
  }
}

// =============================================================================
// convert 4 weight matrices (each 131072 elems) to hi/lo
// =============================================================================
__global__ __launch_bounds__(256) void convert_w(
    const float* __restrict__ s0, const float* __restrict__ s1,
    const float* __restrict__ s2, const float* __restrict__ s3) {
  int idx = blockIdx.x * 256 + threadIdx.x;
  int sel = idx >> 17, w = idx & 131071;
  const float* s = sel == 0 ? s0 : sel == 1 ? s1 : sel == 2 ? s2 : s3;
  bf16* h = sel == 0 ? g_wgr_h : sel == 1 ? g_wgf_h : sel == 2 ? g_wwr_h
                                                               : g_wwf_h;
  bf16* l = sel == 0 ? g_wgr_l : sel == 1 ? g_wgf_l : sel == 2 ? g_wwr_l
                                                               : g_wwf_l;
  float v = s[w];
  bf16 hh = __float2bfloat16_rn(v);
  h[w] = hh;
  l[w] = __float2bfloat16_rn(v - __bfloat162float(hh));
}

// =============================================================================
// combine softmax partials
// =============================================================================
__global__ __launch_bounds__(256) void softmax_combine() {
  int t = blockIdx.x * 256 + threadIdx.x;
  const int total = KB * KN;
  if (t < total) {
    float m = -1e30f;
#pragma unroll
    for (int j = 0; j < 16; j++) m = fmaxf(m, g_prm[t * 16 + j]);
    float s = 0.f;
#pragma unroll
    for (int j = 0; j < 16; j++)
      s += g_prs[t * 16 + j] * __expf(g_prm[t * 16 + j] - m);
    g_rmax[t] = m;
    g_rsum[t] = s;
  } else if (t < 2 * total) {
    int u = t - total;
    float m = -1e30f;
#pragma unroll
    for (int j = 0; j < 8; j++) m = fmaxf(m, g_pcm[u * 8 + j]);
    float s = 0.f;
#pragma unroll
    for (int j = 0; j < 8; j++)
      s += g_pcs[u * 8 + j] * __expf(g_pcm[u * 8 + j] - m);
    g_cmax[u] = m;
    g_csum[u] = s;
  }
}

// =============================================================================
// BN combine + merged finalize
// =============================================================================
__global__ __launch_bounds__(256) void bnfinal_kernel() {
  int t = blockIdx.x * 256 + threadIdx.x;
  if (t >= 2 * KC) return;
  float s = 0.f, s2 = 0.f;
  for (int j = 0; j < KB * 16; j++) {
    s += g_pbs[(size_t)t * (KB * 16) + j];
    s2 += g_pbs2[(size_t)t * (KB * 16) + j];
  }
  float m = s / (float)(KB * KN);
  float var = s2 / (float)(KB * KN) - m * m;
  g_mean[t] = m;
  g_rstd[t] = rsqrtf(var + 1e-5f);
}

__global__ __launch_bounds__(256) void finalize_kernel(
    const float* __restrict__ X0, const float* __restrict__ X1,
    const float* __restrict__ gamma0, const float* __restrict__ beta0,
    const float* __restrict__ gamma1, const float* __restrict__ beta1,
    float* __restrict__ Z) {
  size_t idx = (size_t)blockIdx.x * 256 + threadIdx.x;
  int sel = (int)(idx >> 23);
  size_t li = idx & ((1ull << 23) - 1);
  int c = (int)((idx >> 10) & (KC - 1));
  float m = g_mean[sel * KC + c];
  float r = g_rstd[sel * KC + c];
  float g = sel ? gamma1[c] : gamma0[c];
  float be = sel ? beta1[c] : beta0[c];
  float x = sel ? X1[li] : X0[li];
  Z[idx] = (g_t[idx] - m) * r * g + be + x;
}

// =============================================================================
extern "C" void kernel_launch(void* const* d_in, const int* in_sizes, int n_in,
                              void* d_out, int out_size) {
  const float* rgb        = (const float*)d_in[0];
  const float* flow       = (const float*)d_in[1];
  const float* wg_rgb     = (const float*)d_in[2];
  const float* bg_rgb     = (const float*)d_in[3];
  const float* wg_flow    = (const float*)d_in[4];
  const float* bg_flow    = (const float*)d_in[5];
  const float* ww_rgb     = (const float*)d_in[6];
  const float* bw_rgb     = (const float*)d_in[7];
  const float* gamma_rgb  = (const float*)d_in[8];
  const float* beta_rgb   = (const float*)d_in[9];
  const float* ww_flow    = (const float*)d_in[10];
  const float* bw_flow    = (const float*)d_in[11];
  const float* gamma_flow = (const float*)d_in[12];
  const float* beta_flow  = (const float*)d_in[13];
  float* out = (float*)d_out;

#define SYM(p, g) cudaGetSymbolAddress((void**)&p, g)
  bf16 *rgbT_h, *rgbT_l, *flowT_h, *flowT_l;
  bf16 *wgr_h, *wgr_l, *wgf_h, *wgf_l, *wwr_h, *wwr_l, *wwf_h, *wwf_l;
  bf16 *re_h, *re_l, *fe_h, *fe_l, *reT_h, *reT_l, *feT_h, *feT_l;
  bf16 *yrT_h, *yrT_l, *yfT_h, *yfT_l;
  float *pS, *prmax, *prsum, *pcmax, *pcsum, *pt;
  float *pprm, *pprs, *ppcm, *ppcs, *ppbs, *ppbs2;
  SYM(rgbT_h, g_rgbT_h); SYM(rgbT_l, g_rgbT_l);
  SYM(flowT_h, g_flowT_h); SYM(flowT_l, g_flowT_l);
  SYM(wgr_h, g_wgr_h); SYM(wgr_l, g_wgr_l);
  SYM(wgf_h, g_wgf_h); SYM(wgf_l, g_wgf_l);
  SYM(wwr_h, g_wwr_h); SYM(wwr_l, g_wwr_l);
  SYM(wwf_h, g_wwf_h); SYM(wwf_l, g_wwf_l);
  SYM(re_h, g_re_h); SYM(re_l, g_re_l);
  SYM(fe_h, g_fe_h); SYM(fe_l, g_fe_l);
  SYM(reT_h, g_reT_h); SYM(reT_l, g_reT_l);
  SYM(feT_h, g_feT_h); SYM(feT_l, g_feT_l);
  SYM(yrT_h, g_yrT_h); SYM(yrT_l, g_yrT_l);
  SYM(yfT_h, g_yfT_h); SYM(yfT_l, g_yfT_l);
  SYM(pS, g_S);
  SYM(prmax, g_rmax); SYM(prsum, g_rsum);
  SYM(pcmax, g_cmax); SYM(pcsum, g_csum);
  SYM(pt, g_t);
  SYM(pprm, g_prm); SYM(pprs, g_prs);
  SYM(ppcm, g_pcm); SYM(ppcs, g_pcs);
  SYM(ppbs, g_pbs); SYM(ppbs2, g_pbs2);
#undef SYM

  cudaFuncSetAttribute(gemm_bf16, cudaFuncAttributeMaxDynamicSharedMemorySize,
                       SMEM_DYN);
  dim3 thr(256);
  const unsigned long long sEN = (unsigned long long)KCI * KN;
  const unsigned long long sET = (unsigned long long)KN * KCI;
  const unsigned long long sXT = (unsigned long long)KN * KC;
  const unsigned long long sSS = (unsigned long long)KN * KN;
  const unsigned long long sT = (unsigned long long)KC * KN;

  GArg z{};

  // 1) merged input transpose+split; weight conversion
  transpose_split<<<dim3(KN / 32, KC / 32, 2 * KB), dim3(32, 8)>>>(
      rgb, flow, rgbT_h, rgbT_l, flowT_h, flowT_l);
  convert_w<<<2048, thr>>>(wg_rgb, wg_flow, ww_rgb, ww_flow);

  // 2) merged embeds: E = W @ XT^T -> normal pair + transposed pair
  {
    GArg a0 = z, a1 = z;
    a0.Ah = wgr_h; a0.Al = wgr_l; a0.Bh = rgbT_h; a0.Bl = rgbT_l;
    a0.bias = bg_rgb; a0.oNh = re_h; a0.oNl = re_l; a0.oTh = reT_h;
    a0.oTl = reT_l;
    a1.Ah = wgf_h; a1.Al = wgf_l; a1.Bh = flowT_h; a1.Bl = flowT_l;
    a1.bias = bg_flow; a1.oNh = fe_h; a1.oNl = fe_l; a1.oTh = feT_h;
    a1.oTl = feT_l;
    gemm_bf16<<<dim3(16, 2, 2 * KB), thr, SMEM_DYN>>>(
        a0, a1, 0ull, KC, sXT, KC, 0ull, 0, sEN, KN, sET, KCI, KC);
  }

  // 3) scores: S fp32 + both softmax partial sets (no S2)
  {
    GArg a0 = z;
    a0.Ah = reT_h; a0.Al = reT_l; a0.Bh = feT_h; a0.Bl = feT_l;
    a0.oNf = pS;
    a0.prm = pprm; a0.prs = pprs; a0.pcm = ppcm; a0.pcs = ppcs;
    gemm_bf16<<<dim3(16, 8, KB), thr, SMEM_DYN>>>(
        a0, a0, sET, KCI, sET, KCI, sSS, KN, 0ull, 0, 0ull, 0, KCI);
  }

  // 4) stats combine
  softmax_combine<<<(2 * KB * KN) / 256, thr>>>();

  // 5) merged applies: rgb reads S row-wise; flow reads S transposed in-smem
  {
    GArg a0 = z, a1 = z;
    a0.Ah = fe_h; a0.Al = fe_l; a0.Bf = pS; a0.mxv = prmax; a0.sumv = prsum;
    a0.oTh = yrT_h; a0.oTl = yrT_l; a0.trans = 0;
    a1.Ah = re_h; a1.Al = re_l; a1.Bf = pS; a1.mxv = pcmax; a1.sumv = pcsum;
    a1.oTh = yfT_h; a1.oTl = yfT_l; a1.trans = 1;
    gemm_bf16<<<dim3(16, 2, 2 * KB), thr, SMEM_DYN>>>(
        a0, a1, sEN, KN, sSS, KN, 0ull, 0, 0ull, 0, sET, KCI, KN);
  }

  // 6) merged conv2: T = W @ YT^T + bias (fp32 out) + BN partials
  {
    GArg a0 = z, a1 = z;
    a0.Ah = wwr_h; a0.Al = wwr_l; a0.Bh = yrT_h; a0.Bl = yrT_l;
    a0.bias = bw_rgb; a0.oNf = pt; a0.pbs = ppbs; a0.pbs2 = ppbs2;
    a1.Ah = wwf_h; a1.Al = wwf_l; a1.Bh = yfT_h; a1.Bl = yfT_l;
    a1.bias = bw_flow; a1.oNf = pt + (size_t)KB * KC * KN;
    a1.pbs = ppbs + (size_t)KC * KB * 16;
    a1.pbs2 = ppbs2 + (size_t)KC * KB * 16;
    gemm_bf16<<<dim3(16, 4, 2 * KB), thr, SMEM_DYN>>>(
        a0, a1, 0ull, KCI, sET, KCI, sT, KN, 0ull, 0, 0ull, 0, KCI);
  }

  // 7) BN combine + merged finalize
  bnfinal_kernel<<<4, thr>>>();
  finalize_kernel<<<(2 * KB * KC * KN) / 256, thr>>>(
      rgb, flow, gamma_rgb, beta_rgb, gamma_flow, beta_flow, out);
}

// round 10
// speedup vs baseline: 1.7105x; 1.0678x over previous
#include <cuda_runtime.h>
#include <cuda_bf16.h>
#include <cstdint>

#define KB 16
#define KC 512
#define KCI 256
#define KN 1024

typedef __nv_bfloat16 bf16;
typedef __nv_bfloat162 bf162;

// ---------------- scratch (no allocs allowed -> __device__ globals) ----------
__device__ bf16 g_rgbT_h[(size_t)KB * KN * KC];
__device__ bf16 g_rgbT_l[(size_t)KB * KN * KC];
__device__ bf16 g_flowT_h[(size_t)KB * KN * KC];
__device__ bf16 g_flowT_l[(size_t)KB * KN * KC];
__device__ bf16 g_wgr_h[KCI * KC], g_wgr_l[KCI * KC];
__device__ bf16 g_wgf_h[KCI * KC], g_wgf_l[KCI * KC];
__device__ bf16 g_wwr_h[KC * KCI], g_wwr_l[KC * KCI];
__device__ bf16 g_wwf_h[KC * KCI], g_wwf_l[KC * KCI];
__device__ bf16 g_re_h[(size_t)KB * KCI * KN], g_re_l[(size_t)KB * KCI * KN];
__device__ bf16 g_fe_h[(size_t)KB * KCI * KN], g_fe_l[(size_t)KB * KCI * KN];
__device__ bf16 g_reT_h[(size_t)KB * KN * KCI], g_reT_l[(size_t)KB * KN * KCI];
__device__ bf16 g_feT_h[(size_t)KB * KN * KCI], g_feT_l[(size_t)KB * KN * KCI];
__device__ float g_S[(size_t)KB * KN * KN];
__device__ bf16 g_yrT_h[(size_t)KB * KN * KCI], g_yrT_l[(size_t)KB * KN * KCI];
__device__ bf16 g_yfT_h[(size_t)KB * KN * KCI], g_yfT_l[(size_t)KB * KN * KCI];
__device__ float g_t[2 * (size_t)KB * KC * KN];
__device__ float g_mean[2 * KC];
__device__ float g_rstd[2 * KC];
__device__ float g_rmax[KB * KN], g_rsum[KB * KN];
__device__ float g_cmax[KB * KN], g_csum[KB * KN];
__device__ float g_prm[KB * KN * 8], g_prs[KB * KN * 8];
__device__ float g_pcm[KB * KN * 8], g_pcs[KB * KN * 8];
__device__ float g_pbs[2 * KC * KB * 8], g_pbs2[2 * KC * KB * 8];

// ============================ helpers ========================================
__device__ __forceinline__ uint32_t smem_u32(const void* p) {
  uint32_t a;
  asm("{ .reg .u64 t; cvta.to.shared.u64 t, %1; cvt.u32.u64 %0, t; }"
      : "=r"(a) : "l"(p));
  return a;
}

#define CP16(dst, src)                                                         \
  asm volatile("cp.async.cg.shared.global [%0], [%1], 16;" ::"r"(dst),         \
               "l"(src))
#define CP_COMMIT() asm volatile("cp.async.commit_group;")
#define CP_WAIT1() asm volatile("cp.async.wait_group 1;")
#define CP_WAIT0() asm volatile("cp.async.wait_group 0;")

__device__ __forceinline__ void ldm_x4(uint32_t addr, uint32_t& r0,
                                       uint32_t& r1, uint32_t& r2,
                                       uint32_t& r3) {
  asm volatile(
      "ldmatrix.sync.aligned.m8n8.x4.shared.b16 {%0,%1,%2,%3}, [%4];"
      : "=r"(r0), "=r"(r1), "=r"(r2), "=r"(r3) : "r"(addr));
}

__device__ __forceinline__ void mma_bf16(float* d, const uint32_t* a,
                                         const uint32_t* b) {
  asm volatile(
      "mma.sync.aligned.m16n8k16.row.col.f32.bf16.bf16.f32 "
      "{%0,%1,%2,%3}, {%4,%5,%6,%7}, {%8,%9}, {%0,%1,%2,%3};"
      : "+f"(d[0]), "+f"(d[1]), "+f"(d[2]), "+f"(d[3])
      : "r"(a[0]), "r"(a[1]), "r"(a[2]), "r"(a[3]), "r"(b[0]), "r"(b[1]));
}

__device__ __forceinline__ uint32_t sw128(uint32_t o) {
  return o ^ ((o >> 3) & 0x70);
}
// fold swizzle: two 64B logical rows per 128B phys row, SW128 on phys rows.
__device__ __forceinline__ uint32_t fold_off(int r, int byte) {
  uint32_t off = (uint32_t)(((r >> 1) << 7) + ((r & 1) << 6) + byte);
  return off ^ ((off >> 3) & 0x70);
}

__device__ __forceinline__ void split2(float x, float y, uint32_t& h,
                                       uint32_t& l) {
  bf162 hh = __floats2bfloat162_rn(x, y);
  bf162 ll = __floats2bfloat162_rn(x - __low2float(hh), y - __high2float(hh));
  h = *(uint32_t*)&hh;
  l = *(uint32_t*)&ll;
}

__device__ __forceinline__ float4 lds128(uint32_t a) {
  float4 v;
  asm volatile("ld.shared.v4.f32 {%0,%1,%2,%3}, [%4];"
               : "=f"(v.x), "=f"(v.y), "=f"(v.z), "=f"(v.w) : "r"(a));
  return v;
}
__device__ __forceinline__ float lds32(uint32_t a) {
  float v;
  asm volatile("ld.shared.f32 %0, [%1];" : "=f"(v) : "r"(a));
  return v;
}
__device__ __forceinline__ void sts128(uint32_t a, uint32_t x, uint32_t y,
                                       uint32_t z, uint32_t w) {
  asm volatile("st.shared.v4.b32 [%0], {%1,%2,%3,%4};" ::"r"(a), "r"(x),
               "r"(y), "r"(z), "r"(w));
}

// smem: 3 stages x 32KB (A hi 8K, A lo 8K, B 16K), exp pair 16KB
#define STG_STRIDE 32768
#define OFF_A_LO 8192
#define OFF_B 16384
#define OFF_B_LO 24576
#define OFF_PAIR 98304
#define SMEM_DYN (114688 + 1024)
#define PITCH 129

struct GArg {
  const bf16 *Ah, *Al, *Bh, *Bl;
  const float *Bf, *mxv, *sumv, *bias;
  float *oNf;
  bf16 *oNh, *oNl, *oTh, *oTl;
  float *prm, *prs, *pcm, *pcs, *pbs, *pbs2;
  int trans;
};

// stage one K=32 chunk into stage slot s (tile 128 rows A, 128 rows B)
__device__ __forceinline__ void stage32(uint32_t u_sb, int s, const bf16* Ah,
                                        const bf16* Al, int lda,
                                        const bf16* Bh, const bf16* Bl,
                                        const float* Bf, int ldb, int tid,
                                        int k0, bool expm, int trans) {
  uint32_t abase = u_sb + (uint32_t)s * STG_STRIDE;
  uint32_t bbase = abase + OFF_B;
#pragma unroll
  for (int t = 0; t < 2; t++) {
    int idx = tid + (t << 8);
    int r = idx >> 2, q = idx & 3;
    uint32_t o = fold_off(r, q << 4);
    CP16(abase + o, Ah + (size_t)r * lda + k0 + (q << 3));
    CP16(abase + OFF_A_LO + o, Al + (size_t)r * lda + k0 + (q << 3));
  }
  if (expm) {
    if (trans) {
      // rows = k (32 x 512B), cols = 128 m floats
#pragma unroll
      for (int t = 0; t < 4; t++) {
        int idx = tid + (t << 8);
        int r = idx >> 5, q = idx & 31;
        CP16(bbase + (r << 9) + (q << 4),
             Bf + (size_t)(k0 + r) * ldb + (q << 2));
      }
    } else {
      // rows = m (128 x 128B fp32, SW128)
#pragma unroll
      for (int t = 0; t < 4; t++) {
        int idx = tid + (t << 8);
        int r = idx >> 3, q = idx & 7;
        CP16(bbase + sw128((r << 7) + (q << 4)),
             Bf + (size_t)r * ldb + k0 + (q << 2));
      }
    }
  } else {
#pragma unroll
    for (int t = 0; t < 2; t++) {
      int idx = tid + (t << 8);
      int r = idx >> 2, q = idx & 3;
      uint32_t o = fold_off(r, q << 4);
      CP16(bbase + o, Bh + (size_t)r * ldb + k0 + (q << 3));
      CP16(bbase + 8192 + o, Bl + (size_t)r * ldb + k0 + (q << 3));
    }
  }
}

// convert fp32 B chunk (row-major m x k) -> bf16 pair
__device__ __forceinline__ void convert128(uint32_t srcb, uint32_t pb, int tid,
                                           float mx, float iv) {
  int m = tid >> 1, h = tid & 1;
  float v[16];
#pragma unroll
  for (int j = 0; j < 4; j++) {
    float4 x = lds128(srcb + sw128((m << 7) + (h << 6) + (j << 4)));
    v[4 * j] = x.x; v[4 * j + 1] = x.y; v[4 * j + 2] = x.z; v[4 * j + 3] = x.w;
  }
#pragma unroll
  for (int j = 0; j < 16; j++) v[j] = __expf(v[j] - mx) * iv;
  uint32_t hw[8], lw[8];
#pragma unroll
  for (int j = 0; j < 8; j++) split2(v[2 * j], v[2 * j + 1], hw[j], lw[j]);
  uint32_t o0 = fold_off(m, h << 5);
  uint32_t o1 = fold_off(m, (h << 5) + 16);
  sts128(pb + o0, hw[0], hw[1], hw[2], hw[3]);
  sts128(pb + o1, hw[4], hw[5], hw[6], hw[7]);
  sts128(pb + 8192 + o0, lw[0], lw[1], lw[2], lw[3]);
  sts128(pb + 8192 + o1, lw[4], lw[5], lw[6], lw[7]);
}

// transposed convert: source rows = k (32 x 512B), output pair rows = m
__device__ __forceinline__ void convert128T(uint32_t srcb, uint32_t pb,
                                            int tid, float mx, float iv) {
  int m = tid & 127;
  int kg = (tid >> 7) << 4;  // 0 or 16
  float v[16];
#pragma unroll
  for (int j = 0; j < 16; j++)
    v[j] = lds32(srcb + (uint32_t)((kg + j) << 9) + (uint32_t)(m << 2));
#pragma unroll
  for (int j = 0; j < 16; j++) v[j] = __expf(v[j] - mx) * iv;
  uint32_t hw[8], lw[8];
#pragma unroll
  for (int j = 0; j < 8; j++) split2(v[2 * j], v[2 * j + 1], hw[j], lw[j]);
  uint32_t o0 = fold_off(m, kg << 1);
  uint32_t o1 = fold_off(m, (kg << 1) + 16);
  sts128(pb + o0, hw[0], hw[1], hw[2], hw[3]);
  sts128(pb + o1, hw[4], hw[5], hw[6], hw[7]);
  sts128(pb + 8192 + o0, lw[0], lw[1], lw[2], lw[3]);
  sts128(pb + 8192 + o1, lw[4], lw[5], lw[6], lw[7]);
}

// =============================================================================
// bf16-pair HMMA GEMM: block tile 128x128, warp tile 32x64, K=32 chunks,
// 3-stage cp.async pipeline + single exp-pair buffer.
// =============================================================================
__global__ __launch_bounds__(256, 2) void gemm_bf16(
    GArg a0, GArg a1,
    unsigned long long sA, int lda, unsigned long long sB, int ldb,
    unsigned long long soNf, int ldoNf,
    unsigned long long soN, int ldoN, unsigned long long soT, int ldoT,
    int K) {
  extern __shared__ __align__(1024) char s_dyn[];
  char* sb = (char*)(((uintptr_t)s_dyn + 1023) & ~(uintptr_t)1023);
  float* s_f32 = (float*)sb;  // epilogue staging [128][PITCH]
  uint32_t u_sb = smem_u32(sb);

  int tid = threadIdx.x;
  int wid = tid >> 5, lane = tid & 31;
  int wr = wid & 3, wc = wid >> 2;
  int half = blockIdx.z >> 4;
  int b = blockIdx.z & (KB - 1);
  int i0 = blockIdx.y * 128;
  int n0 = blockIdx.x * 128;
#define SEL(f) (half ? a1.f : a0.f)
  const float* mxv = SEL(mxv);
  bool expm = (mxv != nullptr);
  int trans = SEL(trans);

  const bf16* Ah = SEL(Ah) + (size_t)b * sA + (size_t)i0 * lda;
  const bf16* Al = SEL(Al) + (size_t)b * sA + (size_t)i0 * lda;
  const bf16* Bh = expm ? nullptr : SEL(Bh) + (size_t)b * sB + (size_t)n0 * ldb;
  const bf16* Bl = expm ? nullptr : SEL(Bl) + (size_t)b * sB + (size_t)n0 * ldb;
  const float* Bf = nullptr;
  if (expm) {
    Bf = SEL(Bf) + (size_t)b * sB;
    if (trans) Bf += n0;
    else Bf += (size_t)n0 * ldb;
  }

  float mxe = 0.f, ive = 1.f;
  if (expm) {
    const float* sumv = SEL(sumv);
    int mrow = trans ? (tid & 127) : (tid >> 1);
    mxe = mxv[b * KN + n0 + mrow];
    ive = 1.0f / sumv[b * KN + n0 + mrow];
  }

  int aRow = lane & 15, aCb = (lane >> 4) * 16;
  int bRow = ((lane >> 4) & 1) * 8 + (lane & 7);
  int bCb = ((lane >> 3) & 1) * 16;

  float acc[2][8][4];
#pragma unroll
  for (int mi = 0; mi < 2; mi++)
#pragma unroll
    for (int ni = 0; ni < 8; ni++)
#pragma unroll
      for (int e = 0; e < 4; e++) acc[mi][ni][e] = 0.f;

  int NC = K >> 5;
  stage32(u_sb, 0, Ah, Al, lda, Bh, Bl, Bf, ldb, tid, 0, expm, trans);
  CP_COMMIT();
  stage32(u_sb, 1, Ah, Al, lda, Bh, Bl, Bf, ldb, tid, 32, expm, trans);
  CP_COMMIT();

  int sl = 0;   // slot of current chunk
  int sl2 = 2;  // slot of chunk ch+2
  for (int ch = 0; ch < NC; ch++) {
    CP_WAIT1();
    __syncthreads();  // chunk ch staged; all prior MMA/convert reads done
    if (ch + 2 < NC)
      stage32(u_sb, sl2, Ah, Al, lda, Bh, Bl, Bf, ldb, tid, (ch + 2) << 5,
              expm, trans);
    CP_COMMIT();
    uint32_t sbase = u_sb + (uint32_t)sl * STG_STRIDE;
    uint32_t bh_base, bl_base;
    if (expm) {
      uint32_t pb = u_sb + OFF_PAIR;
      if (trans) convert128T(sbase + OFF_B, pb, tid, mxe, ive);
      else convert128(sbase + OFF_B, pb, tid, mxe, ive);
      __syncthreads();  // pair ready
      bh_base = pb;
      bl_base = pb + 8192;
    } else {
      bh_base = sbase + OFF_B;
      bl_base = sbase + OFF_B_LO;
    }
#pragma unroll
    for (int ks = 0; ks < 2; ks++) {
      int kb = ks << 5;
      uint32_t ah[2][4], al[2][4];
#pragma unroll
      for (int mi = 0; mi < 2; mi++) {
        int r = wr * 32 + mi * 16 + aRow;
        uint32_t o = fold_off(r, kb + aCb);
        ldm_x4(sbase + o, ah[mi][0], ah[mi][1], ah[mi][2], ah[mi][3]);
        ldm_x4(sbase + OFF_A_LO + o, al[mi][0], al[mi][1], al[mi][2],
               al[mi][3]);
      }
#pragma unroll
      for (int ng = 0; ng < 4; ng++) {
        uint32_t bh2[4], bl2[4];
        int r = wc * 64 + ng * 16 + bRow;
        uint32_t o = fold_off(r, kb + bCb);
        ldm_x4(bh_base + o, bh2[0], bh2[1], bh2[2], bh2[3]);
        ldm_x4(bl_base + o, bl2[0], bl2[1], bl2[2], bl2[3]);
#pragma unroll
        for (int mi = 0; mi < 2; mi++)
#pragma unroll
          for (int ns = 0; ns < 2; ns++) {
            float* d = acc[mi][ng * 2 + ns];
            mma_bf16(d, ah[mi], &bh2[ns * 2]);
            mma_bf16(d, ah[mi], &bl2[ns * 2]);
            mma_bf16(d, al[mi], &bh2[ns * 2]);
          }
      }
    }
    sl = (sl == 2) ? 0 : sl + 1;
    sl2 = (sl2 == 2) ? 0 : sl2 + 1;
  }
  CP_WAIT0();
  __syncthreads();

  // --------------------------- epilogue --------------------------------------
  const float* bias = SEL(bias);
#pragma unroll
  for (int mi = 0; mi < 2; mi++) {
    int rl = wr * 32 + mi * 16 + (lane >> 2);
    float bv0 = bias ? __ldg(bias + i0 + rl) : 0.f;
    float bv1 = bias ? __ldg(bias + i0 + rl + 8) : 0.f;
#pragma unroll
    for (int ni = 0; ni < 8; ni++) {
      int c = wc * 64 + ni * 8 + 2 * (lane & 3);
      s_f32[rl * PITCH + c] = acc[mi][ni][0] + bv0;
      s_f32[rl * PITCH + c + 1] = acc[mi][ni][1] + bv0;
      s_f32[(rl + 8) * PITCH + c] = acc[mi][ni][2] + bv1;
      s_f32[(rl + 8) * PITCH + c + 1] = acc[mi][ni][3] + bv1;
    }
  }
  __syncthreads();

  if (float* oNf = SEL(oNf)) {
    float* on = oNf + (size_t)b * soNf;
#pragma unroll
    for (int t = 0; t < 16; t++) {
      int idx = tid + (t << 8);
      int rr = idx >> 5, q = idx & 31;
      float4 v;
      v.x = s_f32[rr * PITCH + q * 4 + 0];
      v.y = s_f32[rr * PITCH + q * 4 + 1];
      v.z = s_f32[rr * PITCH + q * 4 + 2];
      v.w = s_f32[rr * PITCH + q * 4 + 3];
      *(float4*)(on + (size_t)(i0 + rr) * ldoNf + n0 + (q << 2)) = v;
    }
  }
  if (bf16* oNh = SEL(oNh)) {
    bf16* oh = oNh + (size_t)b * soN;
    bf16* ol = SEL(oNl) + (size_t)b * soN;
#pragma unroll
    for (int t = 0; t < 16; t++) {
      int idx = tid + (t << 8);
      int rr = idx >> 5, q = idx & 31;
      uint32_t h0, l0, h1, l1;
      split2(s_f32[rr * PITCH + q * 4 + 0], s_f32[rr * PITCH + q * 4 + 1], h0,
             l0);
      split2(s_f32[rr * PITCH + q * 4 + 2], s_f32[rr * PITCH + q * 4 + 3], h1,
             l1);
      size_t base = (size_t)(i0 + rr) * ldoN + n0 + (q << 2);
      *(uint32_t*)(oh + base) = h0;
      *(uint32_t*)(oh + base + 2) = h1;
      *(uint32_t*)(ol + base) = l0;
      *(uint32_t*)(ol + base + 2) = l1;
    }
  }
  if (bf16* oTh = SEL(oTh)) {
    bf16* oh = oTh + (size_t)b * soT;
    bf16* ol = SEL(oTl) + (size_t)b * soT;
#pragma unroll
    for (int t = 0; t < 16; t++) {
      int idx = tid + (t << 8);
      int c = idx >> 5, rq = (idx & 31) << 2;
      uint32_t h0, l0, h1, l1;
      split2(s_f32[(rq + 0) * PITCH + c], s_f32[(rq + 1) * PITCH + c], h0, l0);
      split2(s_f32[(rq + 2) * PITCH + c], s_f32[(rq + 3) * PITCH + c], h1, l1);
      size_t base = (size_t)(n0 + c) * ldoT + i0 + rq;
      *(uint32_t*)(oh + base) = h0;
      *(uint32_t*)(oh + base + 2) = h1;
      *(uint32_t*)(ol + base) = l0;
      *(uint32_t*)(ol + base + 2) = l1;
    }
  }
  if (float* prm = SEL(prm)) {
    {  // row partials: 2 threads per row, 64 cols each
      int r = tid >> 1, hh = tid & 1;
      float pm = -1e30f;
#pragma unroll 8
      for (int j = 0; j < 64; j++) {
        int c = hh * 64 + ((j + 16 * hh) & 63);
        pm = fmaxf(pm, s_f32[r * PITCH + c]);
      }
      pm = fmaxf(pm, __shfl_xor_sync(0xffffffffu, pm, 1));
      float ps = 0.f;
#pragma unroll 8
      for (int j = 0; j < 64; j++) {
        int c = hh * 64 + ((j + 16 * hh) & 63);
        ps += __expf(s_f32[r * PITCH + c] - pm);
      }
      ps += __shfl_xor_sync(0xffffffffu, ps, 1);
      if (hh == 0) {
        size_t o = (size_t)(b * KN + i0 + r) * gridDim.x + blockIdx.x;
        prm[o] = pm;
        SEL(prs)[o] = ps;
      }
    }
    {  // col partials: 2 threads per col, 64 rows each
      int c = tid >> 1, hh = tid & 1;
      float pm = -1e30f;
#pragma unroll 8
      for (int j = 0; j < 64; j++) {
        int r = hh * 64 + ((j + (c & 31)) & 63);
        pm = fmaxf(pm, s_f32[r * PITCH + c]);
      }
      pm = fmaxf(pm, __shfl_xor_sync(0xffffffffu, pm, 1));
      float ps = 0.f;
#pragma unroll 8
      for (int j = 0; j < 64; j++) {
        int r = hh * 64 + ((j + (c & 31)) & 63);
        ps += __expf(s_f32[r * PITCH + c] - pm);
      }
      ps += __shfl_xor_sync(0xffffffffu, ps, 1);
      if (hh == 0) {
        size_t o = (size_t)(b * KN + n0 + c) * gridDim.y + blockIdx.y;
        SEL(pcm)[o] = pm;
        SEL(pcs)[o] = ps;
      }
    }
  }
  if (float* pbs = SEL(pbs)) {  // BN partials: 2 threads per row
    int r = tid >> 1, hh = tid & 1;
    float s = 0.f, s2 = 0.f;
#pragma unroll 8
    for (int j = 0; j < 64; j++) {
      int c = hh * 64 + ((j + 16 * hh) & 63);
      float v = s_f32[r * PITCH + c];
      s += v;
      s2 += v * v;
    }
    s += __shfl_xor_sync(0xffffffffu, s, 1);
    s2 += __shfl_xor_sync(0xffffffffu, s2, 1);
    if (hh == 0) {
      size_t o = ((size_t)(i0 + r) * KB + b) * gridDim.x + blockIdx.x;
      pbs[o] = s;
      SEL(pbs2)[o] = s2;
    }
  }
#undef SEL
}

// =============================================================================
// merged transpose + split: [C][N] fp32 -> [N][C] bf16 hi/lo, both halves
// =============================================================================
__global__ __launch_bounds__(256) void transpose_split(
    const float* __restrict__ in0, const float* __restrict__ in1,
    bf16* __restrict__ oh0, bf16* __restrict__ ol0, bf16* __restrict__ oh1,
    bf16* __restrict__ ol1) {
  __shared__ float t[32][33];
  int z = blockIdx.z;
  int half = z >> 4, b = z & (KB - 1);
  const float* ib = (half ? in1 : in0) + (size_t)b * KC * KN;
  bf16* ohb = (half ? oh1 : oh0) + (size_t)b * KC * KN;
  bf16* olb = (half ? ol1 : ol0) + (size_t)b * KC * KN;
  int n0 = blockIdx.x * 32, c0 = blockIdx.y * 32;
  int x = threadIdx.x, y = threadIdx.y;
#pragma unroll
  for (int j = 0; j < 4; j++)
    t[y + 8 * j][x] = ib[(size_t)(c0 + y + 8 * j) * KN + n0 + x];
  __syncthreads();
#pragma unroll
  for (int j = 0; j < 4; j++) {
    float v = t[x][y + 8 * j];
    bf16 h = __float2bfloat16_rn(v);
    size_t o = (size_t)(n0 + y + 8 * j) * KC + c0 + x;
    ohb[o] = h;
    olb[o] = __float2bfloat16_rn(v - __bfloat162float(h));
  }
}

// =============================================================================
// convert 4 weight matrices (each 131072 elems) to hi/lo
// =============================================================================
__global__ __launch_bounds__(256) void convert_w(
    const float* __restrict__ s0, const float* __restrict__ s1,
    const float* __restrict__ s2, const float* __restrict__ s3) {
  int idx = blockIdx.x * 256 + threadIdx.x;
  int sel = idx >> 17, w = idx & 131071;
  const float* s = sel == 0 ? s0 : sel == 1 ? s1 : sel == 2 ? s2 : s3;
  bf16* h = sel == 0 ? g_wgr_h : sel == 1 ? g_wgf_h : sel == 2 ? g_wwr_h
                                                               : g_wwf_h;
  bf16* l = sel == 0 ? g_wgr_l : sel == 1 ? g_wgf_l : sel == 2 ? g_wwr_l
                                                               : g_wwf_l;
  float v = s[w];
  bf16 hh = __float2bfloat16_rn(v);
  h[w] = hh;
  l[w] = __float2bfloat16_rn(v - __bfloat162float(hh));
}

// =============================================================================
// combine softmax partials (8 per row, 8 per col)
// =============================================================================
__global__ __launch_bounds__(256) void softmax_combine() {
  int t = blockIdx.x * 256 + threadIdx.x;
  const int total = KB * KN;
  if (t < total) {
    float m = -1e30f;
#pragma unroll
    for (int j = 0; j < 8; j++) m = fmaxf(m, g_prm[t * 8 + j]);
    float s = 0.f;
#pragma unroll
    for (int j = 0; j < 8; j++)
      s += g_prs[t * 8 + j] * __expf(g_prm[t * 8 + j] - m);
    g_rmax[t] = m;
    g_rsum[t] = s;
  } else if (t < 2 * total) {
    int u = t - total;
    float m = -1e30f;
#pragma unroll
    for (int j = 0; j < 8; j++) m = fmaxf(m, g_pcm[u * 8 + j]);
    float s = 0.f;
#pragma unroll
    for (int j = 0; j < 8; j++)
      s += g_pcs[u * 8 + j] * __expf(g_pcm[u * 8 + j] - m);
    g_cmax[u] = m;
    g_csum[u] = s;
  }
}

// =============================================================================
// BN combine + merged finalize
// =============================================================================
__global__ __launch_bounds__(256) void bnfinal_kernel() {
  int t = blockIdx.x * 256 + threadIdx.x;
  if (t >= 2 * KC) return;
  float s = 0.f, s2 = 0.f;
  for (int j = 0; j < KB * 8; j++) {
    s += g_pbs[(size_t)t * (KB * 8) + j];
    s2 += g_pbs2[(size_t)t * (KB * 8) + j];
  }
  float m = s / (float)(KB * KN);
  float var = s2 / (float)(KB * KN) - m * m;
  g_mean[t] = m;
  g_rstd[t] = rsqrtf(var + 1e-5f);
}

__global__ __launch_bounds__(256) void finalize_kernel(
    const float* __restrict__ X0, const float* __restrict__ X1,
    const float* __restrict__ gamma0, const float* __restrict__ beta0,
    const float* __restrict__ gamma1, const float* __restrict__ beta1,
    float* __restrict__ Z) {
  size_t idx = (size_t)blockIdx.x * 256 + threadIdx.x;
  int sel = (int)(idx >> 23);
  size_t li = idx & ((1ull << 23) - 1);
  int c = (int)((idx >> 10) & (KC - 1));
  float m = g_mean[sel * KC + c];
  float r = g_rstd[sel * KC + c];
  float g = sel ? gamma1[c] : gamma0[c];
  float be = sel ? beta1[c] : beta0[c];
  float x = sel ? X1[li] : X0[li];
  Z[idx] = (g_t[idx] - m) * r * g + be + x;
}

// =============================================================================
extern "C" void kernel_launch(void* const* d_in, const int* in_sizes, int n_in,
                              void* d_out, int out_size) {
  const float* rgb        = (const float*)d_in[0];
  const float* flow       = (const float*)d_in[1];
  const float* wg_rgb     = (const float*)d_in[2];
  const float* bg_rgb     = (const float*)d_in[3];
  const float* wg_flow    = (const float*)d_in[4];
  const float* bg_flow    = (const float*)d_in[5];
  const float* ww_rgb     = (const float*)d_in[6];
  const float* bw_rgb     = (const float*)d_in[7];
  const float* gamma_rgb  = (const float*)d_in[8];
  const float* beta_rgb   = (const float*)d_in[9];
  const float* ww_flow    = (const float*)d_in[10];
  const float* bw_flow    = (const float*)d_in[11];
  const float* gamma_flow = (const float*)d_in[12];
  const float* beta_flow  = (const float*)d_in[13];
  float* out = (float*)d_out;

#define SYM(p, g) cudaGetSymbolAddress((void**)&p, g)
  bf16 *rgbT_h, *rgbT_l, *flowT_h, *flowT_l;
  bf16 *wgr_h, *wgr_l, *wgf_h, *wgf_l, *wwr_h, *wwr_l, *wwf_h, *wwf_l;
  bf16 *re_h, *re_l, *fe_h, *fe_l, *reT_h, *reT_l, *feT_h, *feT_l;
  bf16 *yrT_h, *yrT_l, *yfT_h, *yfT_l;
  float *pS, *prmax, *prsum, *pcmax, *pcsum, *pt;
  float *pprm, *pprs, *ppcm, *ppcs, *ppbs, *ppbs2;
  SYM(rgbT_h, g_rgbT_h); SYM(rgbT_l, g_rgbT_l);
  SYM(flowT_h, g_flowT_h); SYM(flowT_l, g_flowT_l);
  SYM(wgr_h, g_wgr_h); SYM(wgr_l, g_wgr_l);
  SYM(wgf_h, g_wgf_h); SYM(wgf_l, g_wgf_l);
  SYM(wwr_h, g_wwr_h); SYM(wwr_l, g_wwr_l);
  SYM(wwf_h, g_wwf_h); SYM(wwf_l, g_wwf_l);
  SYM(re_h, g_re_h); SYM(re_l, g_re_l);
  SYM(fe_h, g_fe_h); SYM(fe_l, g_fe_l);
  SYM(reT_h, g_reT_h); SYM(reT_l, g_reT_l);
  SYM(feT_h, g_feT_h); SYM(feT_l, g_feT_l);
  SYM(yrT_h, g_yrT_h); SYM(yrT_l, g_yrT_l);
  SYM(yfT_h, g_yfT_h); SYM(yfT_l, g_yfT_l);
  SYM(pS, g_S);
  SYM(prmax, g_rmax); SYM(prsum, g_rsum);
  SYM(pcmax, g_cmax); SYM(pcsum, g_csum);
  SYM(pt, g_t);
  SYM(pprm, g_prm); SYM(pprs, g_prs);
  SYM(ppcm, g_pcm); SYM(ppcs, g_pcs);
  SYM(ppbs, g_pbs); SYM(ppbs2, g_pbs2);
#undef SYM

  cudaFuncSetAttribute(gemm_bf16, cudaFuncAttributeMaxDynamicSharedMemorySize,
                       SMEM_DYN);
  dim3 thr(256);
  const unsigned long long sEN = (unsigned long long)KCI * KN;
  const unsigned long long sET = (unsigned long long)KN * KCI;
  const unsigned long long sXT = (unsigned long long)KN * KC;
  const unsigned long long sSS = (unsigned long long)KN * KN;
  const unsigned long long sT = (unsigned long long)KC * KN;

  GArg z{};

  // 1) merged input transpose+split; weight conversion
  transpose_split<<<dim3(KN / 32, KC / 32, 2 * KB), dim3(32, 8)>>>(
      rgb, flow, rgbT_h, rgbT_l, flowT_h, flowT_l);
  convert_w<<<2048, thr>>>(wg_rgb, wg_flow, ww_rgb, ww_flow);

  // 2) merged embeds: E = W @ XT^T -> normal pair + transposed pair
  {
    GArg a0 = z, a1 = z;
    a0.Ah = wgr_h; a0.Al = wgr_l; a0.Bh = rgbT_h; a0.Bl = rgbT_l;
    a0.bias = bg_rgb; a0.oNh = re_h; a0.oNl = re_l; a0.oTh = reT_h;
    a0.oTl = reT_l;
    a1.Ah = wgf_h; a1.Al = wgf_l; a1.Bh = flowT_h; a1.Bl = flowT_l;
    a1.bias = bg_flow; a1.oNh = fe_h; a1.oNl = fe_l; a1.oTh = feT_h;
    a1.oTl = feT_l;
    gemm_bf16<<<dim3(8, 2, 2 * KB), thr, SMEM_DYN>>>(
        a0, a1, 0ull, KC, sXT, KC, 0ull, 0, sEN, KN, sET, KCI, KC);
  }

  // 3) scores: S fp32 + both softmax partial sets
  {
    GArg a0 = z;
    a0.Ah = reT_h; a0.Al = reT_l; a0.Bh = feT_h; a0.Bl = feT_l;
    a0.oNf = pS;
    a0.prm = pprm; a0.prs = pprs; a0.pcm = ppcm; a0.pcs = ppcs;
    gemm_bf16<<<dim3(8, 8, KB), thr, SMEM_DYN>>>(
        a0, a0, sET, KCI, sET, KCI, sSS, KN, 0ull, 0, 0ull, 0, KCI);
  }

  // 4) stats combine
  softmax_combine<<<(2 * KB * KN) / 256, thr>>>();

  // 5) merged applies: rgb reads S row-wise; flow reads S transposed in-smem
  {
    GArg a0 = z, a1 = z;
    a0.Ah = fe_h; a0.Al = fe_l; a0.Bf = pS; a0.mxv = prmax; a0.sumv = prsum;
    a0.oTh = yrT_h; a0.oTl = yrT_l; a0.trans = 0;
    a1.Ah = re_h; a1.Al = re_l; a1.Bf = pS; a1.mxv = pcmax; a1.sumv = pcsum;
    a1.oTh = yfT_h; a1.oTl = yfT_l; a1.trans = 1;
    gemm_bf16<<<dim3(8, 2, 2 * KB), thr, SMEM_DYN>>>(
        a0, a1, sEN, KN, sSS, KN, 0ull, 0, 0ull, 0, sET, KCI, KN);
  }

  // 6) merged conv2: T = W @ YT^T + bias (fp32 out) + BN partials
  {
    GArg a0 = z, a1 = z;
    a0.Ah = wwr_h; a0.Al = wwr_l; a0.Bh = yrT_h; a0.Bl = yrT_l;
    a0.bias = bw_rgb; a0.oNf = pt; a0.pbs = ppbs; a0.pbs2 = ppbs2;
    a1.Ah = wwf_h; a1.Al = wwf_l; a1.Bh = yfT_h; a1.Bl = yfT_l;
    a1.bias = bw_flow; a1.oNf = pt + (size_t)KB * KC * KN;
    a1.pbs = ppbs + (size_t)KC * KB * 8;
    a1.pbs2 = ppbs2 + (size_t)KC * KB * 8;
    gemm_bf16<<<dim3(8, 4, 2 * KB), thr, SMEM_DYN>>>(
        a0, a1, 0ull, KCI, sET, KCI, sT, KN, 0ull, 0, 0ull, 0, KCI);
  }

  // 7) BN combine + merged finalize
  bnfinal_kernel<<<4, thr>>>();
  finalize_kernel<<<(2 * KB * KC * KN) / 256, thr>>>(
      rgb, flow, gamma_rgb, beta_rgb, gamma_flow, beta_flow, out);
}

// round 11
// speedup vs baseline: 1.7365x; 1.0152x over previous
#include <cuda_runtime.h>
#include <cuda_fp16.h>
#include <cstdint>

#define KB 16
#define KC 512
#define KCI 256
#define KN 1024

typedef __half hf;

// ---------------- scratch (no allocs allowed -> __device__ globals) ----------
__device__ hf g_rgbT_h[(size_t)KB * KN * KC];
__device__ hf g_rgbT_l[(size_t)KB * KN * KC];
__device__ hf g_flowT_h[(size_t)KB * KN * KC];
__device__ hf g_flowT_l[(size_t)KB * KN * KC];
__device__ hf g_wgr_h[KCI * KC], g_wgr_l[KCI * KC];
__device__ hf g_wgf_h[KCI * KC], g_wgf_l[KCI * KC];
__device__ hf g_wwr_h[KC * KCI], g_wwr_l[KC * KCI];
__device__ hf g_wwf_h[KC * KCI], g_wwf_l[KC * KCI];
__device__ hf g_re_h[(size_t)KB * KCI * KN], g_re_l[(size_t)KB * KCI * KN];
__device__ hf g_fe_h[(size_t)KB * KCI * KN], g_fe_l[(size_t)KB * KCI * KN];
__device__ hf g_reT_h[(size_t)KB * KN * KCI], g_reT_l[(size_t)KB * KN * KCI];
__device__ hf g_feT_h[(size_t)KB * KN * KCI], g_feT_l[(size_t)KB * KN * KCI];
__device__ float g_S[(size_t)KB * KN * KN];
__device__ hf g_yrT_h[(size_t)KB * KN * KCI], g_yrT_l[(size_t)KB * KN * KCI];
__device__ hf g_yfT_h[(size_t)KB * KN * KCI], g_yfT_l[(size_t)KB * KN * KCI];
__device__ float g_t[2 * (size_t)KB * KC * KN];
__device__ float g_mean[2 * KC];
__device__ float g_rstd[2 * KC];
__device__ float g_rmax[KB * KN], g_rsum[KB * KN];
__device__ float g_cmax[KB * KN], g_csum[KB * KN];
__device__ float g_prm[KB * KN * 8], g_prs[KB * KN * 8];
__device__ float g_pcm[KB * KN * 8], g_pcs[KB * KN * 8];
__device__ float g_pbs[2 * KC * KB * 8], g_pbs2[2 * KC * KB * 8];

// ============================ helpers ========================================
__device__ __forceinline__ uint32_t smem_u32(const void* p) {
  uint32_t a;
  asm("{ .reg .u64 t; cvta.to.shared.u64 t, %1; cvt.u32.u64 %0, t; }"
      : "=r"(a) : "l"(p));
  return a;
}

#define CP16(dst, src)                                                         \
  asm volatile("cp.async.cg.shared.global [%0], [%1], 16;" ::"r"(dst),         \
               "l"(src))
#define CP_COMMIT() asm volatile("cp.async.commit_group;")
#define CP_WAIT1() asm volatile("cp.async.wait_group 1;")
#define CP_WAIT0() asm volatile("cp.async.wait_group 0;")

__device__ __forceinline__ void ldm_x4(uint32_t addr, uint32_t& r0,
                                       uint32_t& r1, uint32_t& r2,
                                       uint32_t& r3) {
  asm volatile(
      "ldmatrix.sync.aligned.m8n8.x4.shared.b16 {%0,%1,%2,%3}, [%4];"
      : "=r"(r0), "=r"(r1), "=r"(r2), "=r"(r3) : "r"(addr));
}

__device__ __forceinline__ void mma_f16(float* d, const uint32_t* a,
                                        const uint32_t* b) {
  asm volatile(
      "mma.sync.aligned.m16n8k16.row.col.f32.f16.f16.f32 "
      "{%0,%1,%2,%3}, {%4,%5,%6,%7}, {%8,%9}, {%0,%1,%2,%3};"
      : "+f"(d[0]), "+f"(d[1]), "+f"(d[2]), "+f"(d[3])
      : "r"(a[0]), "r"(a[1]), "r"(a[2]), "r"(a[3]), "r"(b[0]), "r"(b[1]));
}

__device__ __forceinline__ uint32_t sw128(uint32_t o) {
  return o ^ ((o >> 3) & 0x70);
}
// fold swizzle: two 64B logical rows per 128B phys row, SW128 on phys rows.
__device__ __forceinline__ uint32_t fold_off(int r, int byte) {
  uint32_t off = (uint32_t)(((r >> 1) << 7) + ((r & 1) << 6) + byte);
  return off ^ ((off >> 3) & 0x70);
}

// split two fp32 -> (hi half2, lo half2)
__device__ __forceinline__ void split2(float x, float y, uint32_t& h,
                                       uint32_t& l) {
  __half2 hh = __floats2half2_rn(x, y);
  __half2 ll = __floats2half2_rn(x - __low2float(hh), y - __high2float(hh));
  h = *(uint32_t*)&hh;
  l = *(uint32_t*)&ll;
}
__device__ __forceinline__ uint32_t pack2h(float x, float y) {
  __half2 hh = __floats2half2_rn(x, y);
  return *(uint32_t*)&hh;
}

__device__ __forceinline__ float4 lds128(uint32_t a) {
  float4 v;
  asm volatile("ld.shared.v4.f32 {%0,%1,%2,%3}, [%4];"
               : "=f"(v.x), "=f"(v.y), "=f"(v.z), "=f"(v.w) : "r"(a));
  return v;
}
__device__ __forceinline__ float lds32(uint32_t a) {
  float v;
  asm volatile("ld.shared.f32 %0, [%1];" : "=f"(v) : "r"(a));
  return v;
}
__device__ __forceinline__ void sts128(uint32_t a, uint32_t x, uint32_t y,
                                       uint32_t z, uint32_t w) {
  asm volatile("st.shared.v4.b32 [%0], {%1,%2,%3,%4};" ::"r"(a), "r"(x),
               "r"(y), "r"(z), "r"(w));
}

// smem: 3 stages x 32KB (A hi 8K, A lo 8K, B 16K), exp P-single 8KB
#define STG_STRIDE 32768
#define OFF_A_LO 8192
#define OFF_B 16384
#define OFF_B_LO 24576
#define OFF_PAIR 98304
#define SMEM_DYN (114688 + 1024)
#define PITCH 129

struct GArg {
  const hf *Ah, *Al, *Bh, *Bl;
  const float *Bf, *mxv, *sumv, *bias;
  float *oNf;
  hf *oNh, *oNl, *oTh, *oTl;
  float *prm, *prs, *pcm, *pcs, *pbs, *pbs2;
  int trans;
};

// stage one K=32 chunk into stage slot s (tile 128 rows A, 128 rows B)
__device__ __forceinline__ void stage32(uint32_t u_sb, int s, const hf* Ah,
                                        const hf* Al, int lda, const hf* Bh,
                                        const hf* Bl, const float* Bf, int ldb,
                                        int tid, int k0, bool expm,
                                        int trans) {
  uint32_t abase = u_sb + (uint32_t)s * STG_STRIDE;
  uint32_t bbase = abase + OFF_B;
#pragma unroll
  for (int t = 0; t < 2; t++) {
    int idx = tid + (t << 8);
    int r = idx >> 2, q = idx & 3;
    uint32_t o = fold_off(r, q << 4);
    CP16(abase + o, Ah + (size_t)r * lda + k0 + (q << 3));
    CP16(abase + OFF_A_LO + o, Al + (size_t)r * lda + k0 + (q << 3));
  }
  if (expm) {
    if (trans) {
      // rows = k (32 x 512B), cols = 128 m floats
#pragma unroll
      for (int t = 0; t < 4; t++) {
        int idx = tid + (t << 8);
        int r = idx >> 5, q = idx & 31;
        CP16(bbase + (r << 9) + (q << 4),
             Bf + (size_t)(k0 + r) * ldb + (q << 2));
      }
    } else {
      // rows = m (128 x 128B fp32, SW128)
#pragma unroll
      for (int t = 0; t < 4; t++) {
        int idx = tid + (t << 8);
        int r = idx >> 3, q = idx & 7;
        CP16(bbase + sw128((r << 7) + (q << 4)),
             Bf + (size_t)r * ldb + k0 + (q << 2));
      }
    }
  } else {
#pragma unroll
    for (int t = 0; t < 2; t++) {
      int idx = tid + (t << 8);
      int r = idx >> 2, q = idx & 3;
      uint32_t o = fold_off(r, q << 4);
      CP16(bbase + o, Bh + (size_t)r * ldb + k0 + (q << 3));
      CP16(bbase + 8192 + o, Bl + (size_t)r * ldb + k0 + (q << 3));
    }
  }
}

// convert fp32 B chunk (row-major m x k) -> single fp16 P
__device__ __forceinline__ void convert128(uint32_t srcb, uint32_t pb, int tid,
                                           float mx, float iv) {
  int m = tid >> 1, h = tid & 1;
  float v[16];
#pragma unroll
  for (int j = 0; j < 4; j++) {
    float4 x = lds128(srcb + sw128((m << 7) + (h << 6) + (j << 4)));
    v[4 * j] = x.x; v[4 * j + 1] = x.y; v[4 * j + 2] = x.z; v[4 * j + 3] = x.w;
  }
#pragma unroll
  for (int j = 0; j < 16; j++) v[j] = __expf(v[j] - mx) * iv;
  uint32_t w[8];
#pragma unroll
  for (int j = 0; j < 8; j++) w[j] = pack2h(v[2 * j], v[2 * j + 1]);
  sts128(pb + fold_off(m, h << 5), w[0], w[1], w[2], w[3]);
  sts128(pb + fold_off(m, (h << 5) + 16), w[4], w[5], w[6], w[7]);
}

// transposed convert: source rows = k (32 x 512B), output P rows = m
__device__ __forceinline__ void convert128T(uint32_t srcb, uint32_t pb,
                                            int tid, float mx, float iv) {
  int m = tid & 127;
  int kg = (tid >> 7) << 4;  // 0 or 16
  float v[16];
#pragma unroll
  for (int j = 0; j < 16; j++)
    v[j] = lds32(srcb + (uint32_t)((kg + j) << 9) + (uint32_t)(m << 2));
#pragma unroll
  for (int j = 0; j < 16; j++) v[j] = __expf(v[j] - mx) * iv;
  uint32_t w[8];
#pragma unroll
  for (int j = 0; j < 8; j++) w[j] = pack2h(v[2 * j], v[2 * j + 1]);
  sts128(pb + fold_off(m, kg << 1), w[0], w[1], w[2], w[3]);
  sts128(pb + fold_off(m, (kg << 1) + 16), w[4], w[5], w[6], w[7]);
}

// =============================================================================
// fp16-pair HMMA GEMM: block tile 128x128, warp tile 32x64, K=32 chunks,
// 3-stage cp.async pipeline. exp mode: B = exp(S-mx)/sum as SINGLE fp16
// (2-term MMA); pair mode: B hi/lo (3-term MMA).
// =============================================================================
__global__ __launch_bounds__(256, 2) void gemm_f16(
    GArg a0, GArg a1,
    unsigned long long sA, int lda, unsigned long long sB, int ldb,
    unsigned long long soNf, int ldoNf,
    unsigned long long soN, int ldoN, unsigned long long soT, int ldoT,
    int K) {
  extern __shared__ __align__(1024) char s_dyn[];
  char* sb = (char*)(((uintptr_t)s_dyn + 1023) & ~(uintptr_t)1023);
  float* s_f32 = (float*)sb;  // epilogue staging [128][PITCH]
  uint32_t u_sb = smem_u32(sb);

  int tid = threadIdx.x;
  int wid = tid >> 5, lane = tid & 31;
  int wr = wid & 3, wc = wid >> 2;
  int half = blockIdx.z >> 4;
  int b = blockIdx.z & (KB - 1);
  int i0 = blockIdx.y * 128;
  int n0 = blockIdx.x * 128;
#define SEL(f) (half ? a1.f : a0.f)
  const float* mxv = SEL(mxv);
  bool expm = (mxv != nullptr);
  int trans = SEL(trans);

  const hf* Ah = SEL(Ah) + (size_t)b * sA + (size_t)i0 * lda;
  const hf* Al = SEL(Al) + (size_t)b * sA + (size_t)i0 * lda;
  const hf* Bh = expm ? nullptr : SEL(Bh) + (size_t)b * sB + (size_t)n0 * ldb;
  const hf* Bl = expm ? nullptr : SEL(Bl) + (size_t)b * sB + (size_t)n0 * ldb;
  const float* Bf = nullptr;
  if (expm) {
    Bf = SEL(Bf) + (size_t)b * sB;
    if (trans) Bf += n0;
    else Bf += (size_t)n0 * ldb;
  }

  float mxe = 0.f, ive = 1.f;
  if (expm) {
    const float* sumv = SEL(sumv);
    int mrow = trans ? (tid & 127) : (tid >> 1);
    mxe = mxv[b * KN + n0 + mrow];
    ive = 1.0f / sumv[b * KN + n0 + mrow];
  }

  int aRow = lane & 15, aCb = (lane >> 4) * 16;
  int bRow = ((lane >> 4) & 1) * 8 + (lane & 7);
  int bCb = ((lane >> 3) & 1) * 16;

  float acc[2][8][4];
#pragma unroll
  for (int mi = 0; mi < 2; mi++)
#pragma unroll
    for (int ni = 0; ni < 8; ni++)
#pragma unroll
      for (int e = 0; e < 4; e++) acc[mi][ni][e] = 0.f;

  int NC = K >> 5;
  stage32(u_sb, 0, Ah, Al, lda, Bh, Bl, Bf, ldb, tid, 0, expm, trans);
  CP_COMMIT();
  stage32(u_sb, 1, Ah, Al, lda, Bh, Bl, Bf, ldb, tid, 32, expm, trans);
  CP_COMMIT();

  int sl = 0;   // slot of current chunk
  int sl2 = 2;  // slot of chunk ch+2
  for (int ch = 0; ch < NC; ch++) {
    CP_WAIT1();
    __syncthreads();  // chunk ch staged; all prior MMA/convert reads done
    if (ch + 2 < NC)
      stage32(u_sb, sl2, Ah, Al, lda, Bh, Bl, Bf, ldb, tid, (ch + 2) << 5,
              expm, trans);
    CP_COMMIT();
    uint32_t sbase = u_sb + (uint32_t)sl * STG_STRIDE;
    uint32_t bh_base, bl_base = 0;
    if (expm) {
      uint32_t pb = u_sb + OFF_PAIR;
      if (trans) convert128T(sbase + OFF_B, pb, tid, mxe, ive);
      else convert128(sbase + OFF_B, pb, tid, mxe, ive);
      __syncthreads();  // P ready
      bh_base = pb;
    } else {
      bh_base = sbase + OFF_B;
      bl_base = sbase + OFF_B_LO;
    }
#pragma unroll
    for (int ks = 0; ks < 2; ks++) {
      int kb = ks << 5;
      uint32_t ah[2][4], al[2][4];
#pragma unroll
      for (int mi = 0; mi < 2; mi++) {
        int r = wr * 32 + mi * 16 + aRow;
        uint32_t o = fold_off(r, kb + aCb);
        ldm_x4(sbase + o, ah[mi][0], ah[mi][1], ah[mi][2], ah[mi][3]);
        ldm_x4(sbase + OFF_A_LO + o, al[mi][0], al[mi][1], al[mi][2],
               al[mi][3]);
      }
#pragma unroll
      for (int ng = 0; ng < 4; ng++) {
        uint32_t bh2[4];
        int r = wc * 64 + ng * 16 + bRow;
        uint32_t o = fold_off(r, kb + bCb);
        ldm_x4(bh_base + o, bh2[0], bh2[1], bh2[2], bh2[3]);
        if (expm) {
#pragma unroll
          for (int mi = 0; mi < 2; mi++)
#pragma unroll
            for (int ns = 0; ns < 2; ns++) {
              float* d = acc[mi][ng * 2 + ns];
              mma_f16(d, ah[mi], &bh2[ns * 2]);
              mma_f16(d, al[mi], &bh2[ns * 2]);
            }
        } else {
          uint32_t bl2[4];
          ldm_x4(bl_base + o, bl2[0], bl2[1], bl2[2], bl2[3]);
#pragma unroll
          for (int mi = 0; mi < 2; mi++)
#pragma unroll
            for (int ns = 0; ns < 2; ns++) {
              float* d = acc[mi][ng * 2 + ns];
              mma_f16(d, ah[mi], &bh2[ns * 2]);
              mma_f16(d, ah[mi], &bl2[ns * 2]);
              mma_f16(d, al[mi], &bh2[ns * 2]);
            }
        }
      }
    }
    sl = (sl == 2) ? 0 : sl + 1;
    sl2 = (sl2 == 2) ? 0 : sl2 + 1;
  }
  CP_WAIT0();
  __syncthreads();

  // --------------------------- epilogue --------------------------------------
  const float* bias = SEL(bias);
#pragma unroll
  for (int mi = 0; mi < 2; mi++) {
    int rl = wr * 32 + mi * 16 + (lane >> 2);
    float bv0 = bias ? __ldg(bias + i0 + rl) : 0.f;
    float bv1 = bias ? __ldg(bias + i0 + rl + 8) : 0.f;
#pragma unroll
    for (int ni = 0; ni < 8; ni++) {
      int c = wc * 64 + ni * 8 + 2 * (lane & 3);
      s_f32[rl * PITCH + c] = acc[mi][ni][0] + bv0;
      s_f32[rl * PITCH + c + 1] = acc[mi][ni][1] + bv0;
      s_f32[(rl + 8) * PITCH + c] = acc[mi][ni][2] + bv1;
      s_f32[(rl + 8) * PITCH + c + 1] = acc[mi][ni][3] + bv1;
    }
  }
  __syncthreads();

  if (float* oNf = SEL(oNf)) {
    float* on = oNf + (size_t)b * soNf;
#pragma unroll
    for (int t = 0; t < 16; t++) {
      int idx = tid + (t << 8);
      int rr = idx >> 5, q = idx & 31;
      float4 v;
      v.x = s_f32[rr * PITCH + q * 4 + 0];
      v.y = s_f32[rr * PITCH + q * 4 + 1];
      v.z = s_f32[rr * PITCH + q * 4 + 2];
      v.w = s_f32[rr * PITCH + q * 4 + 3];
      *(float4*)(on + (size_t)(i0 + rr) * ldoNf + n0 + (q << 2)) = v;
    }
  }
  if (hf* oNh = SEL(oNh)) {
    hf* oh = oNh + (size_t)b * soN;
    hf* ol = SEL(oNl) + (size_t)b * soN;
#pragma unroll
    for (int t = 0; t < 16; t++) {
      int idx = tid + (t << 8);
      int rr = idx >> 5, q = idx & 31;
      uint32_t h0, l0, h1, l1;
      split2(s_f32[rr * PITCH + q * 4 + 0], s_f32[rr * PITCH + q * 4 + 1], h0,
             l0);
      split2(s_f32[rr * PITCH + q * 4 + 2], s_f32[rr * PITCH + q * 4 + 3], h1,
             l1);
      size_t base = (size_t)(i0 + rr) * ldoN + n0 + (q << 2);
      *(uint32_t*)(oh + base) = h0;
      *(uint32_t*)(oh + base + 2) = h1;
      *(uint32_t*)(ol + base) = l0;
      *(uint32_t*)(ol + base + 2) = l1;
    }
  }
  if (hf* oTh = SEL(oTh)) {
    hf* oh = oTh + (size_t)b * soT;
    hf* ol = SEL(oTl) + (size_t)b * soT;
#pragma unroll
    for (int t = 0; t < 16; t++) {
      int idx = tid + (t << 8);
      int c = idx >> 5, rq = (idx & 31) << 2;
      uint32_t h0, l0, h1, l1;
      split2(s_f32[(rq + 0) * PITCH + c], s_f32[(rq + 1) * PITCH + c], h0, l0);
      split2(s_f32[(rq + 2) * PITCH + c], s_f32[(rq + 3) * PITCH + c], h1, l1);
      size_t base = (size_t)(n0 + c) * ldoT + i0 + rq;
      *(uint32_t*)(oh + base) = h0;
      *(uint32_t*)(oh + base + 2) = h1;
      *(uint32_t*)(ol + base) = l0;
      *(uint32_t*)(ol + base + 2) = l1;
    }
  }
  if (float* prm = SEL(prm)) {
    {  // row partials: 2 threads per row, 64 cols each
      int r = tid >> 1, hh = tid & 1;
      float pm = -1e30f;
#pragma unroll 8
      for (int j = 0; j < 64; j++) {
        int c = hh * 64 + ((j + 16 * hh) & 63);
        pm = fmaxf(pm, s_f32[r * PITCH + c]);
      }
      pm = fmaxf(pm, __shfl_xor_sync(0xffffffffu, pm, 1));
      float ps = 0.f;
#pragma unroll 8
      for (int j = 0; j < 64; j++) {
        int c = hh * 64 + ((j + 16 * hh) & 63);
        ps += __expf(s_f32[r * PITCH + c] - pm);
      }
      ps += __shfl_xor_sync(0xffffffffu, ps, 1);
      if (hh == 0) {
        size_t o = (size_t)(b * KN + i0 + r) * gridDim.x + blockIdx.x;
        prm[o] = pm;
        SEL(prs)[o] = ps;
      }
    }
    {  // col partials: 2 threads per col, 64 rows each
      int c = tid >> 1, hh = tid & 1;
      float pm = -1e30f;
#pragma unroll 8
      for (int j = 0; j < 64; j++) {
        int r = hh * 64 + ((j + (c & 31)) & 63);
        pm = fmaxf(pm, s_f32[r * PITCH + c]);
      }
      pm = fmaxf(pm, __shfl_xor_sync(0xffffffffu, pm, 1));
      float ps = 0.f;
#pragma unroll 8
      for (int j = 0; j < 64; j++) {
        int r = hh * 64 + ((j + (c & 31)) & 63);
        ps += __expf(s_f32[r * PITCH + c] - pm);
      }
      ps += __shfl_xor_sync(0xffffffffu, ps, 1);
      if (hh == 0) {
        size_t o = (size_t)(b * KN + n0 + c) * gridDim.y + blockIdx.y;
        SEL(pcm)[o] = pm;
        SEL(pcs)[o] = ps;
      }
    }
  }
  if (float* pbs = SEL(pbs)) {  // BN partials: 2 threads per row
    int r = tid >> 1, hh = tid & 1;
    float s = 0.f, s2 = 0.f;
#pragma unroll 8
    for (int j = 0; j < 64; j++) {
      int c = hh * 64 + ((j + 16 * hh) & 63);
      float v = s_f32[r * PITCH + c];
      s += v;
      s2 += v * v;
    }
    s += __shfl_xor_sync(0xffffffffu, s, 1);
    s2 += __shfl_xor_sync(0xffffffffu, s2, 1);
    if (hh == 0) {
      size_t o = ((size_t)(i0 + r) * KB + b) * gridDim.x + blockIdx.x;
      pbs[o] = s;
      SEL(pbs2)[o] = s2;
    }
  }
#undef SEL
}

// =============================================================================
// merged transpose + split: [C][N] fp32 -> [N][C] fp16 hi/lo, both halves
// =============================================================================
__global__ __launch_bounds__(256) void transpose_split(
    const float* __restrict__ in0, const float* __restrict__ in1,
    hf* __restrict__ oh0, hf* __restrict__ ol0, hf* __restrict__ oh1,
    hf* __restrict__ ol1) {
  __shared__ float t[32][33];
  int z = blockIdx.z;
  int half = z >> 4, b = z & (KB - 1);
  const float* ib = (half ? in1 : in0) + (size_t)b * KC * KN;
  hf* ohb = (half ? oh1 : oh0) + (size_t)b * KC * KN;
  hf* olb = (half ? ol1 : ol0) + (size_t)b * KC * KN;
  int n0 = blockIdx.x * 32, c0 = blockIdx.y * 32;
  int x = threadIdx.x, y = threadIdx.y;
#pragma unroll
  for (int j = 0; j < 4; j++)
    t[y + 8 * j][x] = ib[(size_t)(c0 + y + 8 * j) * KN + n0 + x];
  __syncthreads();
#pragma unroll
  for (int j = 0; j < 4; j++) {
    float v = t[x][y + 8 * j];
    hf h = __float2half_rn(v);
    size_t o = (size_t)(n0 + y + 8 * j) * KC + c0 + x;
    ohb[o] = h;
    olb[o] = __float2half_rn(v - __half2float(h));
  }
}

// =============================================================================
// convert 4 weight matrices (each 131072 elems) to hi/lo
// =============================================================================
__global__ __launch_bounds__(256) void convert_w(
    const float* __restrict__ s0, const float* __restrict__ s1,
    const float* __restrict__ s2, const float* __restrict__ s3) {
  int idx = blockIdx.x * 256 + threadIdx.x;
  int sel = idx >> 17, w = idx & 131071;
  const float* s = sel == 0 ? s0 : sel == 1 ? s1 : sel == 2 ? s2 : s3;
  hf* h = sel == 0 ? g_wgr_h : sel == 1 ? g_wgf_h : sel == 2 ? g_wwr_h
                                                             : g_wwf_h;
  hf* l = sel == 0 ? g_wgr_l : sel == 1 ? g_wgf_l : sel == 2 ? g_wwr_l
                                                             : g_wwf_l;
  float v = s[w];
  hf hh = __float2half_rn(v);
  h[w] = hh;
  l[w] = __float2half_rn(v - __half2float(hh));
}

// =============================================================================
// combine softmax partials (8 per row, 8 per col)
// =============================================================================
__global__ __launch_bounds__(256) void softmax_combine() {
  int t = blockIdx.x * 256 + threadIdx.x;
  const int total = KB * KN;
  if (t < total) {
    float m = -1e30f;
#pragma unroll
    for (int j = 0; j < 8; j++) m = fmaxf(m, g_prm[t * 8 + j]);
    float s = 0.f;
#pragma unroll
    for (int j = 0; j < 8; j++)
      s += g_prs[t * 8 + j] * __expf(g_prm[t * 8 + j] - m);
    g_rmax[t] = m;
    g_rsum[t] = s;
  } else if (t < 2 * total) {
    int u = t - total;
    float m = -1e30f;
#pragma unroll
    for (int j = 0; j < 8; j++) m = fmaxf(m, g_pcm[u * 8 + j]);
    float s = 0.f;
#pragma unroll
    for (int j = 0; j < 8; j++)
      s += g_pcs[u * 8 + j] * __expf(g_pcm[u * 8 + j] - m);
    g_cmax[u] = m;
    g_csum[u] = s;
  }
}

// =============================================================================
// BN combine + merged finalize
// =============================================================================
__global__ __launch_bounds__(256) void bnfinal_kernel() {
  int t = blockIdx.x * 256 + threadIdx.x;
  if (t >= 2 * KC) return;
  float s = 0.f, s2 = 0.f;
  for (int j = 0; j < KB * 8; j++) {
    s += g_pbs[(size_t)t * (KB * 8) + j];
    s2 += g_pbs2[(size_t)t * (KB * 8) + j];
  }
  float m = s / (float)(KB * KN);
  float var = s2 / (float)(KB * KN) - m * m;
  g_mean[t] = m;
  g_rstd[t] = rsqrtf(var + 1e-5f);
}

__global__ __launch_bounds__(256) void finalize_kernel(
    const float* __restrict__ X0, const float* __restrict__ X1,
    const float* __restrict__ gamma0, const float* __restrict__ beta0,
    const float* __restrict__ gamma1, const float* __restrict__ beta1,
    float* __restrict__ Z) {
  size_t idx = (size_t)blockIdx.x * 256 + threadIdx.x;
  int sel = (int)(idx >> 23);
  size_t li = idx & ((1ull << 23) - 1);
  int c = (int)((idx >> 10) & (KC - 1));
  float m = g_mean[sel * KC + c];
  float r = g_rstd[sel * KC + c];
  float g = sel ? gamma1[c] : gamma0[c];
  float be = sel ? beta1[c] : beta0[c];
  float x = sel ? X1[li] : X0[li];
  Z[idx] = (g_t[idx] - m) * r * g + be + x;
}

// =============================================================================
extern "C" void kernel_launch(void* const* d_in, const int* in_sizes, int n_in,
                              void* d_out, int out_size) {
  const float* rgb        = (const float*)d_in[0];
  const float* flow       = (const float*)d_in[1];
  const float* wg_rgb     = (const float*)d_in[2];
  const float* bg_rgb     = (const float*)d_in[3];
  const float* wg_flow    = (const float*)d_in[4];
  const float* bg_flow    = (const float*)d_in[5];
  const float* ww_rgb     = (const float*)d_in[6];
  const float* bw_rgb     = (const float*)d_in[7];
  const float* gamma_rgb  = (const float*)d_in[8];
  const float* beta_rgb   = (const float*)d_in[9];
  const float* ww_flow    = (const float*)d_in[10];
  const float* bw_flow    = (const float*)d_in[11];
  const float* gamma_flow = (const float*)d_in[12];
  const float* beta_flow  = (const float*)d_in[13];
  float* out = (float*)d_out;

#define SYM(p, g) cudaGetSymbolAddress((void**)&p, g)
  hf *rgbT_h, *rgbT_l, *flowT_h, *flowT_l;
  hf *wgr_h, *wgr_l, *wgf_h, *wgf_l, *wwr_h, *wwr_l, *wwf_h, *wwf_l;
  hf *re_h, *re_l, *fe_h, *fe_l, *reT_h, *reT_l, *feT_h, *feT_l;
  hf *yrT_h, *yrT_l, *yfT_h, *yfT_l;
  float *pS, *prmax, *prsum, *pcmax, *pcsum, *pt;
  float *pprm, *pprs, *ppcm, *ppcs, *ppbs, *ppbs2;
  SYM(rgbT_h, g_rgbT_h); SYM(rgbT_l, g_rgbT_l);
  SYM(flowT_h, g_flowT_h); SYM(flowT_l, g_flowT_l);
  SYM(wgr_h, g_wgr_h); SYM(wgr_l, g_wgr_l);
  SYM(wgf_h, g_wgf_h); SYM(wgf_l, g_wgf_l);
  SYM(wwr_h, g_wwr_h); SYM(wwr_l, g_wwr_l);
  SYM(wwf_h, g_wwf_h); SYM(wwf_l, g_wwf_l);
  SYM(re_h, g_re_h); SYM(re_l, g_re_l);
  SYM(fe_h, g_fe_h); SYM(fe_l, g_fe_l);
  SYM(reT_h, g_reT_h); SYM(reT_l, g_reT_l);
  SYM(feT_h, g_feT_h); SYM(feT_l, g_feT_l);
  SYM(yrT_h, g_yrT_h); SYM(yrT_l, g_yrT_l);
  SYM(yfT_h, g_yfT_h); SYM(yfT_l, g_yfT_l);
  SYM(pS, g_S);
  SYM(prmax, g_rmax); SYM(prsum, g_rsum);
  SYM(pcmax, g_cmax); SYM(pcsum, g_csum);
  SYM(pt, g_t);
  SYM(pprm, g_prm); SYM(pprs, g_prs);
  SYM(ppcm, g_pcm); SYM(ppcs, g_pcs);
  SYM(ppbs, g_pbs); SYM(ppbs2, g_pbs2);
#undef SYM

  cudaFuncSetAttribute(gemm_f16, cudaFuncAttributeMaxDynamicSharedMemorySize,
                       SMEM_DYN);
  dim3 thr(256);
  const unsigned long long sEN = (unsigned long long)KCI * KN;
  const unsigned long long sET = (unsigned long long)KN * KCI;
  const unsigned long long sXT = (unsigned long long)KN * KC;
  const unsigned long long sSS = (unsigned long long)KN * KN;
  const unsigned long long sT = (unsigned long long)KC * KN;

  GArg z{};

  // 1) merged input transpose+split; weight conversion
  transpose_split<<<dim3(KN / 32, KC / 32, 2 * KB), dim3(32, 8)>>>(
      rgb, flow, rgbT_h, rgbT_l, flowT_h, flowT_l);
  convert_w<<<2048, thr>>>(wg_rgb, wg_flow, ww_rgb, ww_flow);

  // 2) merged embeds: E = W @ XT^T -> normal pair + transposed pair
  {
    GArg a0 = z, a1 = z;
    a0.Ah = wgr_h; a0.Al = wgr_l; a0.Bh = rgbT_h; a0.Bl = rgbT_l;
    a0.bias = bg_rgb; a0.oNh = re_h; a0.oNl = re_l; a0.oTh = reT_h;
    a0.oTl = reT_l;
    a1.Ah = wgf_h; a1.Al = wgf_l; a1.Bh = flowT_h; a1.Bl = flowT_l;
    a1.bias = bg_flow; a1.oNh = fe_h; a1.oNl = fe_l; a1.oTh = feT_h;
    a1.oTl = feT_l;
    gemm_f16<<<dim3(8, 2, 2 * KB), thr, SMEM_DYN>>>(
        a0, a1, 0ull, KC, sXT, KC, 0ull, 0, sEN, KN, sET, KCI, KC);
  }

  // 3) scores: S fp32 + both softmax partial sets
  {
    GArg a0 = z;
    a0.Ah = reT_h; a0.Al = reT_l; a0.Bh = feT_h; a0.Bl = feT_l;
    a0.oNf = pS;
    a0.prm = pprm; a0.prs = pprs; a0.pcm = ppcm; a0.pcs = ppcs;
    gemm_f16<<<dim3(8, 8, KB), thr, SMEM_DYN>>>(
        a0, a0, sET, KCI, sET, KCI, sSS, KN, 0ull, 0, 0ull, 0, KCI);
  }

  // 4) stats combine
  softmax_combine<<<(2 * KB * KN) / 256, thr>>>();

  // 5) merged applies: rgb reads S row-wise; flow reads S transposed in-smem
  {
    GArg a0 = z, a1 = z;
    a0.Ah = fe_h; a0.Al = fe_l; a0.Bf = pS; a0.mxv = prmax; a0.sumv = prsum;
    a0.oTh = yrT_h; a0.oTl = yrT_l; a0.trans = 0;
    a1.Ah = re_h; a1.Al = re_l; a1.Bf = pS; a1.mxv = pcmax; a1.sumv = pcsum;
    a1.oTh = yfT_h; a1.oTl = yfT_l; a1.trans = 1;
    gemm_f16<<<dim3(8, 2, 2 * KB), thr, SMEM_DYN>>>(
        a0, a1, sEN, KN, sSS, KN, 0ull, 0, 0ull, 0, sET, KCI, KN);
  }

  // 6) merged conv2: T = W @ YT^T + bias (fp32 out) + BN partials
  {
    GArg a0 = z, a1 = z;
    a0.Ah = wwr_h; a0.Al = wwr_l; a0.Bh = yrT_h; a0.Bl = yrT_l;
    a0.bias = bw_rgb; a0.oNf = pt; a0.pbs = ppbs; a0.pbs2 = ppbs2;
    a1.Ah = wwf_h; a1.Al = wwf_l; a1.Bh = yfT_h; a1.Bl = yfT_l;
    a1.bias = bw_flow; a1.oNf = pt + (size_t)KB * KC * KN;
    a1.pbs = ppbs + (size_t)KC * KB * 8;
    a1.pbs2 = ppbs2 + (size_t)KC * KB * 8;
    gemm_f16<<<dim3(8, 4, 2 * KB), thr, SMEM_DYN>>>(
        a0, a1, 0ull, KCI, sET, KCI, sT, KN, 0ull, 0, 0ull, 0, KCI);
  }

  // 7) BN combine + merged finalize
  bnfinal_kernel<<<4, thr>>>();
  finalize_kernel<<<(2 * KB * KC * KN) / 256, thr>>>(
      rgb, flow, gamma_rgb, beta_rgb, gamma_flow, beta_flow, out);
}

// round 12
// speedup vs baseline: 1.8143x; 1.0448x over previous
#include <cuda_runtime.h>
#include <cuda_fp16.h>
#include <cstdint>

#define KB 16
#define KC 512
#define KCI 256
#define KN 1024

typedef __half hf;

// ---------------- scratch (no allocs allowed -> __device__ globals) ----------
__device__ hf g_wgr_h[KCI * KC], g_wgr_l[KCI * KC];
__device__ hf g_wgf_h[KCI * KC], g_wgf_l[KCI * KC];
__device__ hf g_wwr_h[KC * KCI], g_wwr_l[KC * KCI];
__device__ hf g_wwf_h[KC * KCI], g_wwf_l[KC * KCI];
__device__ hf g_re_h[(size_t)KB * KCI * KN];   // apply A operand (single)
__device__ hf g_fe_h[(size_t)KB * KCI * KN];
__device__ hf g_reT_h[(size_t)KB * KN * KCI], g_reT_l[(size_t)KB * KN * KCI];
__device__ hf g_feT_h[(size_t)KB * KN * KCI], g_feT_l[(size_t)KB * KN * KCI];
__device__ float g_S[(size_t)KB * KN * KN];
__device__ hf g_yrT_h[(size_t)KB * KN * KCI];  // y stored single
__device__ hf g_yfT_h[(size_t)KB * KN * KCI];
__device__ float g_t[2 * (size_t)KB * KC * KN];
__device__ float g_mean[2 * KC];
__device__ float g_rstd[2 * KC];
__device__ float g_rmax[KB * KN], g_rsum[KB * KN];
__device__ float g_cmax[KB * KN], g_csum[KB * KN];
__device__ float g_prm[KB * KN * 8], g_prs[KB * KN * 8];
__device__ float g_pcm[KB * KN * 8], g_pcs[KB * KN * 8];
__device__ float g_pbs[2 * KC * KB * 8], g_pbs2[2 * KC * KB * 8];

// ============================ helpers ========================================
__device__ __forceinline__ uint32_t smem_u32(const void* p) {
  uint32_t a;
  asm("{ .reg .u64 t; cvta.to.shared.u64 t, %1; cvt.u32.u64 %0, t; }"
      : "=r"(a) : "l"(p));
  return a;
}

#define CP16(dst, src)                                                         \
  asm volatile("cp.async.cg.shared.global [%0], [%1], 16;" ::"r"(dst),         \
               "l"(src))
#define CP_COMMIT() asm volatile("cp.async.commit_group;")
#define CP_WAIT1() asm volatile("cp.async.wait_group 1;")
#define CP_WAIT0() asm volatile("cp.async.wait_group 0;")

__device__ __forceinline__ void ldm_x4(uint32_t addr, uint32_t& r0,
                                       uint32_t& r1, uint32_t& r2,
                                       uint32_t& r3) {
  asm volatile(
      "ldmatrix.sync.aligned.m8n8.x4.shared.b16 {%0,%1,%2,%3}, [%4];"
      : "=r"(r0), "=r"(r1), "=r"(r2), "=r"(r3) : "r"(addr));
}

__device__ __forceinline__ void mma_f16(float* d, const uint32_t* a,
                                        const uint32_t* b) {
  asm volatile(
      "mma.sync.aligned.m16n8k16.row.col.f32.f16.f16.f32 "
      "{%0,%1,%2,%3}, {%4,%5,%6,%7}, {%8,%9}, {%0,%1,%2,%3};"
      : "+f"(d[0]), "+f"(d[1]), "+f"(d[2]), "+f"(d[3])
      : "r"(a[0]), "r"(a[1]), "r"(a[2]), "r"(a[3]), "r"(b[0]), "r"(b[1]));
}

__device__ __forceinline__ uint32_t sw128(uint32_t o) {
  return o ^ ((o >> 3) & 0x70);
}
// fold swizzle: two 64B logical rows per 128B phys row, SW128 on phys rows.
__device__ __forceinline__ uint32_t fold_off(int r, int byte) {
  uint32_t off = (uint32_t)(((r >> 1) << 7) + ((r & 1) << 6) + byte);
  return off ^ ((off >> 3) & 0x70);
}

// split two fp32 -> (hi half2, lo half2)
__device__ __forceinline__ void split2(float x, float y, uint32_t& h,
                                       uint32_t& l) {
  __half2 hh = __floats2half2_rn(x, y);
  __half2 ll = __floats2half2_rn(x - __low2float(hh), y - __high2float(hh));
  h = *(uint32_t*)&hh;
  l = *(uint32_t*)&ll;
}
__device__ __forceinline__ uint32_t pack2h(float x, float y) {
  __half2 hh = __floats2half2_rn(x, y);
  return *(uint32_t*)&hh;
}

__device__ __forceinline__ float4 lds128(uint32_t a) {
  float4 v;
  asm volatile("ld.shared.v4.f32 {%0,%1,%2,%3}, [%4];"
               : "=f"(v.x), "=f"(v.y), "=f"(v.z), "=f"(v.w) : "r"(a));
  return v;
}
__device__ __forceinline__ float lds32(uint32_t a) {
  float v;
  asm volatile("ld.shared.f32 %0, [%1];" : "=f"(v) : "r"(a));
  return v;
}
__device__ __forceinline__ void sts128(uint32_t a, uint32_t x, uint32_t y,
                                       uint32_t z, uint32_t w) {
  asm volatile("st.shared.v4.b32 [%0], {%1,%2,%3,%4};" ::"r"(a), "r"(x),
               "r"(y), "r"(z), "r"(w));
}

// smem: 3 stages x 32KB (A hi 8K, A lo 8K, B up to 16K), convert-out 16KB
#define STG_STRIDE 32768
#define OFF_A_LO 8192
#define OFF_B 16384
#define OFF_PAIR 98304
#define SMEM_DYN (114688 + 1024)
#define PITCH 129

// bmode: 0 = B pair (fp16 hi/lo from global), 1 = B single (fp16 from global),
//        2 = B exp-single (fp32 src, exp(x-mx)/sum), 3 = B ident-pair
//            (fp32 src, transposed staging, hi/lo out)
struct GArg {
  const hf *Ah, *Al, *Bh;
  const float *Bf, *mxv, *sumv, *bias;
  float *oNf;
  hf *oNh, *oTh, *oTl;
  float *prm, *prs, *pcm, *pcs, *pbs, *pbs2;
  int bmode, trans, as;  // as = A single (skip lo operand)
};

// stage one K=32 chunk into stage slot s
__device__ __forceinline__ void stage32(uint32_t u_sb, int s, const hf* Ah,
                                        const hf* Al, int lda, const hf* Bh,
                                        const float* Bf, int ldb, int tid,
                                        int k0, int bmode, int trans,
                                        int as) {
  uint32_t abase = u_sb + (uint32_t)s * STG_STRIDE;
  uint32_t bbase = abase + OFF_B;
#pragma unroll
  for (int t = 0; t < 2; t++) {
    int idx = tid + (t << 8);
    int r = idx >> 2, q = idx & 3;
    uint32_t o = fold_off(r, q << 4);
    CP16(abase + o, Ah + (size_t)r * lda + k0 + (q << 3));
    if (!as) CP16(abase + OFF_A_LO + o, Al + (size_t)r * lda + k0 + (q << 3));
  }
  if (bmode >= 2) {
    if (bmode == 3 || trans) {
      // rows = k (32 x 512B), cols = 128 m floats
#pragma unroll
      for (int t = 0; t < 4; t++) {
        int idx = tid + (t << 8);
        int r = idx >> 5, q = idx & 31;
        CP16(bbase + (r << 9) + (q << 4),
             Bf + (size_t)(k0 + r) * ldb + (q << 2));
      }
    } else {
      // rows = m (128 x 128B fp32, SW128)
#pragma unroll
      for (int t = 0; t < 4; t++) {
        int idx = tid + (t << 8);
        int r = idx >> 3, q = idx & 7;
        CP16(bbase + sw128((r << 7) + (q << 4)),
             Bf + (size_t)r * ldb + k0 + (q << 2));
      }
    }
  } else if (bmode == 1) {  // B single fp16
#pragma unroll
    for (int t = 0; t < 2; t++) {
      int idx = tid + (t << 8);
      int r = idx >> 2, q = idx & 3;
      CP16(bbase + fold_off(r, q << 4), Bh + (size_t)r * ldb + k0 + (q << 3));
    }
  } else {  // B pair fp16 (Bh with lo at +sB half offset handled by caller)
#pragma unroll
    for (int t = 0; t < 2; t++) {
      int idx = tid + (t << 8);
      int r = idx >> 2, q = idx & 3;
      uint32_t o = fold_off(r, q << 4);
      CP16(bbase + o, Bh + (size_t)r * ldb + k0 + (q << 3));
      CP16(bbase + 8192 + o,
           Bh + (size_t)KB * KN * KCI + (size_t)r * ldb + k0 + (q << 3));
    }
  }
}

// exp convert, row-major source (m rows x 128B): -> single fp16
__device__ __forceinline__ void convert_exp(uint32_t srcb, uint32_t pb,
                                            int tid, float mx, float iv) {
  int m = tid >> 1, h = tid & 1;
  float v[16];
#pragma unroll
  for (int j = 0; j < 4; j++) {
    float4 x = lds128(srcb + sw128((m << 7) + (h << 6) + (j << 4)));
    v[4 * j] = x.x; v[4 * j + 1] = x.y; v[4 * j + 2] = x.z; v[4 * j + 3] = x.w;
  }
#pragma unroll
  for (int j = 0; j < 16; j++) v[j] = __expf(v[j] - mx) * iv;
  uint32_t w[8];
#pragma unroll
  for (int j = 0; j < 8; j++) w[j] = pack2h(v[2 * j], v[2 * j + 1]);
  sts128(pb + fold_off(m, h << 5), w[0], w[1], w[2], w[3]);
  sts128(pb + fold_off(m, (h << 5) + 16), w[4], w[5], w[6], w[7]);
}

// exp convert, transposed source (k rows x 512B) -> single fp16, rows = m
__device__ __forceinline__ void convert_expT(uint32_t srcb, uint32_t pb,
                                             int tid, float mx, float iv) {
  int m = tid & 127;
  int kg = (tid >> 7) << 4;
  float v[16];
#pragma unroll
  for (int j = 0; j < 16; j++)
    v[j] = lds32(srcb + (uint32_t)((kg + j) << 9) + (uint32_t)(m << 2));
#pragma unroll
  for (int j = 0; j < 16; j++) v[j] = __expf(v[j] - mx) * iv;
  uint32_t w[8];
#pragma unroll
  for (int j = 0; j < 8; j++) w[j] = pack2h(v[2 * j], v[2 * j + 1]);
  sts128(pb + fold_off(m, kg << 1), w[0], w[1], w[2], w[3]);
  sts128(pb + fold_off(m, (kg << 1) + 16), w[4], w[5], w[6], w[7]);
}

// identity convert, transposed source -> fp16 PAIR (hi at pb, lo at pb+8192)
__device__ __forceinline__ void convert_idT(uint32_t srcb, uint32_t pb,
                                            int tid) {
  int m = tid & 127;
  int kg = (tid >> 7) << 4;
  float v[16];
#pragma unroll
  for (int j = 0; j < 16; j++)
    v[j] = lds32(srcb + (uint32_t)((kg + j) << 9) + (uint32_t)(m << 2));
  uint32_t hw[8], lw[8];
#pragma unroll
  for (int j = 0; j < 8; j++) split2(v[2 * j], v[2 * j + 1], hw[j], lw[j]);
  uint32_t o0 = fold_off(m, kg << 1);
  uint32_t o1 = fold_off(m, (kg << 1) + 16);
  sts128(pb + o0, hw[0], hw[1], hw[2], hw[3]);
  sts128(pb + o1, hw[4], hw[5], hw[6], hw[7]);
  sts128(pb + 8192 + o0, lw[0], lw[1], lw[2], lw[3]);
  sts128(pb + 8192 + o1, lw[4], lw[5], lw[6], lw[7]);
}

// =============================================================================
// fp16 HMMA GEMM: block 128x128, warp 32x64, K=32 chunks, 3-stage pipeline.
// =============================================================================
__global__ __launch_bounds__(256, 2) void gemm_f16(
    GArg a0, GArg a1,
    unsigned long long sA, int lda, unsigned long long sB, int ldb,
    unsigned long long soNf, int ldoNf,
    unsigned long long soN, int ldoN, unsigned long long soT, int ldoT,
    int K) {
  extern __shared__ __align__(1024) char s_dyn[];
  char* sb = (char*)(((uintptr_t)s_dyn + 1023) & ~(uintptr_t)1023);
  float* s_f32 = (float*)sb;  // epilogue staging [128][PITCH]
  uint32_t u_sb = smem_u32(sb);

  int tid = threadIdx.x;
  int wid = tid >> 5, lane = tid & 31;
  int wr = wid & 3, wc = wid >> 2;
  int half = blockIdx.z >> 4;
  int b = blockIdx.z & (KB - 1);
  int i0 = blockIdx.y * 128;
  int n0 = blockIdx.x * 128;
#define SEL(f) (half ? a1.f : a0.f)
  int bmode = SEL(bmode);
  int trans = SEL(trans);
  int as = SEL(as);

  const hf* Ah = SEL(Ah) + (size_t)b * sA + (size_t)i0 * lda;
  const hf* Al = as ? nullptr : SEL(Al) + (size_t)b * sA + (size_t)i0 * lda;
  const hf* Bh = nullptr;
  const float* Bf = nullptr;
  if (bmode >= 2) {
    Bf = SEL(Bf) + (size_t)b * sB;
    if (bmode == 3 || trans) Bf += n0;
    else Bf += (size_t)n0 * ldb;
  } else {
    Bh = SEL(Bh) + (size_t)b * sB + (size_t)n0 * ldb;
  }

  float mxe = 0.f, ive = 1.f;
  if (bmode == 2) {
    const float* mxv = SEL(mxv);
    const float* sumv = SEL(sumv);
    int mrow = trans ? (tid & 127) : (tid >> 1);
    mxe = mxv[b * KN + n0 + mrow];
    ive = 1.0f / sumv[b * KN + n0 + mrow];
  }

  int aRow = lane & 15, aCb = (lane >> 4) * 16;
  int bRow = ((lane >> 4) & 1) * 8 + (lane & 7);
  int bCb = ((lane >> 3) & 1) * 16;

  float acc[2][8][4];
#pragma unroll
  for (int mi = 0; mi < 2; mi++)
#pragma unroll
    for (int ni = 0; ni < 8; ni++)
#pragma unroll
      for (int e = 0; e < 4; e++) acc[mi][ni][e] = 0.f;

  int NC = K >> 5;
  stage32(u_sb, 0, Ah, Al, lda, Bh, Bf, ldb, tid, 0, bmode, trans, as);
  CP_COMMIT();
  stage32(u_sb, 1, Ah, Al, lda, Bh, Bf, ldb, tid, 32, bmode, trans, as);
  CP_COMMIT();

  int sl = 0, sl2 = 2;
  for (int ch = 0; ch < NC; ch++) {
    CP_WAIT1();
    __syncthreads();
    if (ch + 2 < NC)
      stage32(u_sb, sl2, Ah, Al, lda, Bh, Bf, ldb, tid, (ch + 2) << 5, bmode,
              trans, as);
    CP_COMMIT();
    uint32_t sbase = u_sb + (uint32_t)sl * STG_STRIDE;
    uint32_t bh_base, bl_base = 0;
    bool bpair = (bmode == 0 || bmode == 3);
    if (bmode >= 2) {
      uint32_t pb = u_sb + OFF_PAIR;
      if (bmode == 3) convert_idT(sbase + OFF_B, pb, tid);
      else if (trans) convert_expT(sbase + OFF_B, pb, tid, mxe, ive);
      else convert_exp(sbase + OFF_B, pb, tid, mxe, ive);
      __syncthreads();
      bh_base = pb;
      bl_base = pb + 8192;
    } else {
      bh_base = sbase + OFF_B;
      bl_base = sbase + OFF_B + 8192;
    }
#pragma unroll
    for (int ks = 0; ks < 2; ks++) {
      int kb = ks << 5;
      uint32_t ah[2][4], al[2][4];
#pragma unroll
      for (int mi = 0; mi < 2; mi++) {
        int r = wr * 32 + mi * 16 + aRow;
        uint32_t o = fold_off(r, kb + aCb);
        ldm_x4(sbase + o, ah[mi][0], ah[mi][1], ah[mi][2], ah[mi][3]);
        if (!as)
          ldm_x4(sbase + OFF_A_LO + o, al[mi][0], al[mi][1], al[mi][2],
                 al[mi][3]);
      }
#pragma unroll
      for (int ng = 0; ng < 4; ng++) {
        uint32_t bh2[4], bl2[4];
        int r = wc * 64 + ng * 16 + bRow;
        uint32_t o = fold_off(r, kb + bCb);
        ldm_x4(bh_base + o, bh2[0], bh2[1], bh2[2], bh2[3]);
        if (bpair) ldm_x4(bl_base + o, bl2[0], bl2[1], bl2[2], bl2[3]);
#pragma unroll
        for (int mi = 0; mi < 2; mi++)
#pragma unroll
          for (int ns = 0; ns < 2; ns++) {
            float* d = acc[mi][ng * 2 + ns];
            mma_f16(d, ah[mi], &bh2[ns * 2]);
            if (bpair) mma_f16(d, ah[mi], &bl2[ns * 2]);
            if (!as) mma_f16(d, al[mi], &bh2[ns * 2]);
          }
      }
    }
    sl = (sl == 2) ? 0 : sl + 1;
    sl2 = (sl2 == 2) ? 0 : sl2 + 1;
  }
  CP_WAIT0();
  __syncthreads();

  // --------------------------- epilogue --------------------------------------
  const float* bias = SEL(bias);
#pragma unroll
  for (int mi = 0; mi < 2; mi++) {
    int rl = wr * 32 + mi * 16 + (lane >> 2);
    float bv0 = bias ? __ldg(bias + i0 + rl) : 0.f;
    float bv1 = bias ? __ldg(bias + i0 + rl + 8) : 0.f;
#pragma unroll
    for (int ni = 0; ni < 8; ni++) {
      int c = wc * 64 + ni * 8 + 2 * (lane & 3);
      s_f32[rl * PITCH + c] = acc[mi][ni][0] + bv0;
      s_f32[rl * PITCH + c + 1] = acc[mi][ni][1] + bv0;
      s_f32[(rl + 8) * PITCH + c] = acc[mi][ni][2] + bv1;
      s_f32[(rl + 8) * PITCH + c + 1] = acc[mi][ni][3] + bv1;
    }
  }
  __syncthreads();

  if (float* oNf = SEL(oNf)) {
    float* on = oNf + (size_t)b * soNf;
#pragma unroll
    for (int t = 0; t < 16; t++) {
      int idx = tid + (t << 8);
      int rr = idx >> 5, q = idx & 31;
      float4 v;
      v.x = s_f32[rr * PITCH + q * 4 + 0];
      v.y = s_f32[rr * PITCH + q * 4 + 1];
      v.z = s_f32[rr * PITCH + q * 4 + 2];
      v.w = s_f32[rr * PITCH + q * 4 + 3];
      *(float4*)(on + (size_t)(i0 + rr) * ldoNf + n0 + (q << 2)) = v;
    }
  }
  if (hf* oNh = SEL(oNh)) {  // single fp16 normal-layout output
    hf* oh = oNh + (size_t)b * soN;
#pragma unroll
    for (int t = 0; t < 16; t++) {
      int idx = tid + (t << 8);
      int rr = idx >> 5, q = idx & 31;
      uint32_t h0 = pack2h(s_f32[rr * PITCH + q * 4 + 0],
                           s_f32[rr * PITCH + q * 4 + 1]);
      uint32_t h1 = pack2h(s_f32[rr * PITCH + q * 4 + 2],
                           s_f32[rr * PITCH + q * 4 + 3]);
      size_t base = (size_t)(i0 + rr) * ldoN + n0 + (q << 2);
      *(uint32_t*)(oh + base) = h0;
      *(uint32_t*)(oh + base + 2) = h1;
    }
  }
  if (hf* oTh = SEL(oTh)) {  // transposed output: pair if oTl, else single
    hf* oh = oTh + (size_t)b * soT;
    hf* ol = SEL(oTl);
    if (ol) ol += (size_t)b * soT;
#pragma unroll
    for (int t = 0; t < 16; t++) {
      int idx = tid + (t << 8);
      int c = idx >> 5, rq = (idx & 31) << 2;
      size_t base = (size_t)(n0 + c) * ldoT + i0 + rq;
      if (ol) {
        uint32_t h0, l0, h1, l1;
        split2(s_f32[(rq + 0) * PITCH + c], s_f32[(rq + 1) * PITCH + c], h0,
               l0);
        split2(s_f32[(rq + 2) * PITCH + c], s_f32[(rq + 3) * PITCH + c], h1,
               l1);
        *(uint32_t*)(oh + base) = h0;
        *(uint32_t*)(oh + base + 2) = h1;
        *(uint32_t*)(ol + base) = l0;
        *(uint32_t*)(ol + base + 2) = l1;
      } else {
        uint32_t h0 = pack2h(s_f32[(rq + 0) * PITCH + c],
                             s_f32[(rq + 1) * PITCH + c]);
        uint32_t h1 = pack2h(s_f32[(rq + 2) * PITCH + c],
                             s_f32[(rq + 3) * PITCH + c]);
        *(uint32_t*)(oh + base) = h0;
        *(uint32_t*)(oh + base + 2) = h1;
      }
    }
  }
  if (float* prm = SEL(prm)) {
    {  // row partials: 2 threads per row
      int r = tid >> 1, hh = tid & 1;
      float pm = -1e30f;
#pragma unroll 8
      for (int j = 0; j < 64; j++) {
        int c = hh * 64 + ((j + 16 * hh) & 63);
        pm = fmaxf(pm, s_f32[r * PITCH + c]);
      }
      pm = fmaxf(pm, __shfl_xor_sync(0xffffffffu, pm, 1));
      float ps = 0.f;
#pragma unroll 8
      for (int j = 0; j < 64; j++) {
        int c = hh * 64 + ((j + 16 * hh) & 63);
        ps += __expf(s_f32[r * PITCH + c] - pm);
      }
      ps += __shfl_xor_sync(0xffffffffu, ps, 1);
      if (hh == 0) {
        size_t o = (size_t)(b * KN + i0 + r) * gridDim.x + blockIdx.x;
        prm[o] = pm;
        SEL(prs)[o] = ps;
      }
    }
    {  // col partials: 2 threads per col
      int c = tid >> 1, hh = tid & 1;
      float pm = -1e30f;
#pragma unroll 8
      for (int j = 0; j < 64; j++) {
        int r = hh * 64 + ((j + (c & 31)) & 63);
        pm = fmaxf(pm, s_f32[r * PITCH + c]);
      }
      pm = fmaxf(pm, __shfl_xor_sync(0xffffffffu, pm, 1));
      float ps = 0.f;
#pragma unroll 8
      for (int j = 0; j < 64; j++) {
        int r = hh * 64 + ((j + (c & 31)) & 63);
        ps += __expf(s_f32[r * PITCH + c] - pm);
      }
      ps += __shfl_xor_sync(0xffffffffu, ps, 1);
      if (hh == 0) {
        size_t o = (size_t)(b * KN + n0 + c) * gridDim.y + blockIdx.y;
        SEL(pcm)[o] = pm;
        SEL(pcs)[o] = ps;
      }
    }
  }
  if (float* pbs = SEL(pbs)) {  // BN partials: 2 threads per row
    int r = tid >> 1, hh = tid & 1;
    float s = 0.f, s2 = 0.f;
#pragma unroll 8
    for (int j = 0; j < 64; j++) {
      int c = hh * 64 + ((j + 16 * hh) & 63);
      float v = s_f32[r * PITCH + c];
      s += v;
      s2 += v * v;
    }
    s += __shfl_xor_sync(0xffffffffu, s, 1);
    s2 += __shfl_xor_sync(0xffffffffu, s2, 1);
    if (hh == 0) {
      size_t o = ((size_t)(i0 + r) * KB + b) * gridDim.x + blockIdx.x;
      pbs[o] = s;
      SEL(pbs2)[o] = s2;
    }
  }
#undef SEL
}

// =============================================================================
// convert 4 weight matrices (each 131072 elems) to hi/lo
// =============================================================================
__global__ __launch_bounds__(256) void convert_w(
    const float* __restrict__ s0, const float* __restrict__ s1,
    const float* __restrict__ s2, const float* __restrict__ s3) {
  int idx = blockIdx.x * 256 + threadIdx.x;
  int sel = idx >> 17, w = idx & 131071;
  const float* s = sel == 0 ? s0 : sel == 1 ? s1 : sel == 2 ? s2 : s3;
  hf* h = sel == 0 ? g_wgr_h : sel == 1 ? g_wgf_h : sel == 2 ? g_wwr_h
                                                             : g_wwf_h;
  hf* l = sel == 0 ? g_wgr_l : sel == 1 ? g_wgf_l : sel == 2 ? g_wwr_l
                                                             : g_wwf_l;
  float v = s[w];
  hf hh = __float2half_rn(v);
  h[w] = hh;
  l[w] = __float2half_rn(v - __half2float(hh));
}

// =============================================================================
// combine softmax partials (8 per row, 8 per col)
// =============================================================================
__global__ __launch_bounds__(256) void softmax_combine() {
  int t = blockIdx.x * 256 + threadIdx.x;
  const int total = KB * KN;
  if (t < total) {
    float m = -1e30f;
#pragma unroll
    for (int j = 0; j < 8; j++) m = fmaxf(m, g_prm[t * 8 + j]);
    float s = 0.f;
#pragma unroll
    for (int j = 0; j < 8; j++)
      s += g_prs[t * 8 + j] * __expf(g_prm[t * 8 + j] - m);
    g_rmax[t] = m;
    g_rsum[t] = s;
  } else if (t < 2 * total) {
    int u = t - total;
    float m = -1e30f;
#pragma unroll
    for (int j = 0; j < 8; j++) m = fmaxf(m, g_pcm[u * 8 + j]);
    float s = 0.f;
#pragma unroll
    for (int j = 0; j < 8; j++)
      s += g_pcs[u * 8 + j] * __expf(g_pcm[u * 8 + j] - m);
    g_cmax[u] = m;
    g_csum[u] = s;
  }
}

// =============================================================================
// BN combine + merged finalize
// =============================================================================
__global__ __launch_bounds__(256) void bnfinal_kernel() {
  int t = blockIdx.x * 256 + threadIdx.x;
  if (t >= 2 * KC) return;
  float s = 0.f, s2 = 0.f;
  for (int j = 0; j < KB * 8; j++) {
    s += g_pbs[(size_t)t * (KB * 8) + j];
    s2 += g_pbs2[(size_t)t * (KB * 8) + j];
  }
  float m = s / (float)(KB * KN);
  float var = s2 / (float)(KB * KN) - m * m;
  g_mean[t] = m;
  g_rstd[t] = rsqrtf(var + 1e-5f);
}

__global__ __launch_bounds__(256) void finalize_kernel(
    const float* __restrict__ X0, const float* __restrict__ X1,
    const float* __restrict__ gamma0, const float* __restrict__ beta0,
    const float* __restrict__ gamma1, const float* __restrict__ beta1,
    float* __restrict__ Z) {
  size_t idx = (size_t)blockIdx.x * 256 + threadIdx.x;
  int sel = (int)(idx >> 23);
  size_t li = idx & ((1ull << 23) - 1);
  int c = (int)((idx >> 10) & (KC - 1));
  float m = g_mean[sel * KC + c];
  float r = g_rstd[sel * KC + c];
  float g = sel ? gamma1[c] : gamma0[c];
  float be = sel ? beta1[c] : beta0[c];
  float x = sel ? X1[li] : X0[li];
  Z[idx] = (g_t[idx] - m) * r * g + be + x;
}

// =============================================================================
extern "C" void kernel_launch(void* const* d_in, const int* in_sizes, int n_in,
                              void* d_out, int out_size) {
  const float* rgb        = (const float*)d_in[0];
  const float* flow       = (const float*)d_in[1];
  const float* wg_rgb     = (const float*)d_in[2];
  const float* bg_rgb     = (const float*)d_in[3];
  const float* wg_flow    = (const float*)d_in[4];
  const float* bg_flow    = (const float*)d_in[5];
  const float* ww_rgb     = (const float*)d_in[6];
  const float* bw_rgb     = (const float*)d_in[7];
  const float* gamma_rgb  = (const float*)d_in[8];
  const float* beta_rgb   = (const float*)d_in[9];
  const float* ww_flow    = (const float*)d_in[10];
  const float* bw_flow    = (const float*)d_in[11];
  const float* gamma_flow = (const float*)d_in[12];
  const float* beta_flow  = (const float*)d_in[13];
  float* out = (float*)d_out;

#define SYM(p, g) cudaGetSymbolAddress((void**)&p, g)
  hf *wgr_h, *wgr_l, *wgf_h, *wgf_l, *wwr_h, *wwr_l, *wwf_h, *wwf_l;
  hf *re_h, *fe_h, *reT_h, *reT_l, *feT_h, *feT_l, *yrT_h, *yfT_h;
  float *pS, *prmax, *prsum, *pcmax, *pcsum, *pt;
  float *pprm, *pprs, *ppcm, *ppcs, *ppbs, *ppbs2;
  SYM(wgr_h, g_wgr_h); SYM(wgr_l, g_wgr_l);
  SYM(wgf_h, g_wgf_h); SYM(wgf_l, g_wgf_l);
  SYM(wwr_h, g_wwr_h); SYM(wwr_l, g_wwr_l);
  SYM(wwf_h, g_wwf_h); SYM(wwf_l, g_wwf_l);
  SYM(re_h, g_re_h); SYM(fe_h, g_fe_h);
  SYM(reT_h, g_reT_h); SYM(reT_l, g_reT_l);
  SYM(feT_h, g_feT_h); SYM(feT_l, g_feT_l);
  SYM(yrT_h, g_yrT_h); SYM(yfT_h, g_yfT_h);
  SYM(pS, g_S);
  SYM(prmax, g_rmax); SYM(prsum, g_rsum);
  SYM(pcmax, g_cmax); SYM(pcsum, g_csum);
  SYM(pt, g_t);
  SYM(pprm, g_prm); SYM(pprs, g_prs);
  SYM(ppcm, g_pcm); SYM(ppcs, g_pcs);
  SYM(ppbs, g_pbs); SYM(ppbs2, g_pbs2);
#undef SYM

  cudaFuncSetAttribute(gemm_f16, cudaFuncAttributeMaxDynamicSharedMemorySize,
                       SMEM_DYN);
  dim3 thr(256);
  const unsigned long long sEN = (unsigned long long)KCI * KN;
  const unsigned long long sET = (unsigned long long)KN * KCI;
  const unsigned long long sXF = (unsigned long long)KC * KN;  // fp32 input
  const unsigned long long sSS = (unsigned long long)KN * KN;
  const unsigned long long sT = (unsigned long long)KC * KN;

  GArg z{};

  // 1) weight conversion
  convert_w<<<2048, thr>>>(wg_rgb, wg_flow, ww_rgb, ww_flow);

  // 2) merged embeds: B = fp32 input via transposed staging + ident pair
  //    outputs: re/fe single (oNh) + reT/feT pair (oTh/oTl)
  {
    GArg a0 = z, a1 = z;
    a0.Ah = wgr_h; a0.Al = wgr_l; a0.Bf = rgb; a0.bias = bg_rgb;
    a0.oNh = re_h; a0.oTh = reT_h; a0.oTl = reT_l; a0.bmode = 3;
    a1.Ah = wgf_h; a1.Al = wgf_l; a1.Bf = flow; a1.bias = bg_flow;
    a1.oNh = fe_h; a1.oTh = feT_h; a1.oTl = feT_l; a1.bmode = 3;
    gemm_f16<<<dim3(8, 2, 2 * KB), thr, SMEM_DYN>>>(
        a0, a1, 0ull, KC, sXF, KN, 0ull, 0, sEN, KN, sET, KCI, KC);
  }

  // 3) scores: A pair, B pair (3-term); S fp32 + both softmax partial sets
  {
    GArg a0 = z;
    a0.Ah = reT_h; a0.Al = reT_l; a0.Bh = feT_h;  // lo at Bh + KB*KN*KCI
    a0.oNf = pS;
    a0.prm = pprm; a0.prs = pprs; a0.pcm = ppcm; a0.pcs = ppcs;
    a0.bmode = 0;
    gemm_f16<<<dim3(8, 8, KB), thr, SMEM_DYN>>>(
        a0, a0, sET, KCI, sET, KCI, sSS, KN, 0ull, 0, 0ull, 0, KCI);
  }

  // 4) stats combine
  softmax_combine<<<(2 * KB * KN) / 256, thr>>>();

  // 5) merged applies: A single (1-term), B exp-single; y^T single out
  {
    GArg a0 = z, a1 = z;
    a0.Ah = fe_h; a0.Bf = pS; a0.mxv = prmax; a0.sumv = prsum;
    a0.oTh = yrT_h; a0.bmode = 2; a0.trans = 0; a0.as = 1;
    a1.Ah = re_h; a1.Bf = pS; a1.mxv = pcmax; a1.sumv = pcsum;
    a1.oTh = yfT_h; a1.bmode = 2; a1.trans = 1; a1.as = 1;
    gemm_f16<<<dim3(8, 2, 2 * KB), thr, SMEM_DYN>>>(
        a0, a1, sEN, KN, sSS, KN, 0ull, 0, 0ull, 0, sET, KCI, KN);
  }

  // 6) merged conv2: A = W pair, B = yT single (2-term); fp32 out + BN part.
  {
    GArg a0 = z, a1 = z;
    a0.Ah = wwr_h; a0.Al = wwr_l; a0.Bh = yrT_h; a0.bias = bw_rgb;
    a0.oNf = pt; a0.pbs = ppbs; a0.pbs2 = ppbs2; a0.bmode = 1;
    a1.Ah = wwf_h; a1.Al = wwf_l; a1.Bh = yfT_h; a1.bias = bw_flow;
    a1.oNf = pt + (size_t)KB * KC * KN;
    a1.pbs = ppbs + (size_t)KC * KB * 8;
    a1.pbs2 = ppbs2 + (size_t)KC * KB * 8;
    a1.bmode = 1;
    gemm_f16<<<dim3(8, 4, 2 * KB), thr, SMEM_DYN>>>(
        a0, a1, 0ull, KCI, sET, KCI, sT, KN, 0ull, 0, 0ull, 0, KCI);
  }

  // 7) BN combine + merged finalize
  bnfinal_kernel<<<4, thr>>>();
  finalize_kernel<<<(2 * KB * KC * KN) / 256, thr>>>(
      rgb, flow, gamma_rgb, beta_rgb, gamma_flow, beta_flow, out);
}

// round 13
// speedup vs baseline: 2.1093x; 1.1626x over previous
#include <cuda_runtime.h>
#include <cuda_fp16.h>
#include <cstdint>

#define KB 16
#define KC 512
#define KCI 256
#define KN 1024

typedef __half hf;

// ---------------- scratch (no allocs allowed -> __device__ globals) ----------
__device__ hf g_wgr_h[KCI * KC], g_wgr_l[KCI * KC];
__device__ hf g_wgf_h[KCI * KC], g_wgf_l[KCI * KC];
__device__ hf g_wwr_h[KC * KCI], g_wwr_l[KC * KCI];
__device__ hf g_wwf_h[KC * KCI], g_wwf_l[KC * KCI];
__device__ hf g_re_h[(size_t)KB * KCI * KN];   // apply A operand (single)
__device__ hf g_fe_h[(size_t)KB * KCI * KN];
__device__ hf g_reT_h[(size_t)KB * KN * KCI], g_reT_l[(size_t)KB * KN * KCI];
__device__ hf g_feT_h[(size_t)KB * KN * KCI], g_feT_l[(size_t)KB * KN * KCI];
__device__ float g_S[(size_t)KB * KN * KN];
__device__ hf g_yrT_h[(size_t)KB * KN * KCI];  // y stored single
__device__ hf g_yfT_h[(size_t)KB * KN * KCI];
__device__ float g_t[2 * (size_t)KB * KC * KN];
__device__ float g_mean[2 * KC];
__device__ float g_rstd[2 * KC];
__device__ float g_rmax[KB * KN], g_rsum[KB * KN];
__device__ float g_cmax[KB * KN], g_csum[KB * KN];
__device__ float g_prm[KB * KN * 8], g_prs[KB * KN * 8];
__device__ float g_pcm[KB * KN * 8], g_pcs[KB * KN * 8];
__device__ float g_pbs[2 * KC * KB * 8], g_pbs2[2 * KC * KB * 8];

// ============================ helpers ========================================
__device__ __forceinline__ uint32_t smem_u32(const void* p) {
  uint32_t a;
  asm("{ .reg .u64 t; cvta.to.shared.u64 t, %1; cvt.u32.u64 %0, t; }"
      : "=r"(a) : "l"(p));
  return a;
}

#define CP16(dst, src)                                                         \
  asm volatile("cp.async.cg.shared.global [%0], [%1], 16;" ::"r"(dst),         \
               "l"(src))
#define CP_COMMIT() asm volatile("cp.async.commit_group;")
#define CP_WAIT1() asm volatile("cp.async.wait_group 1;")
#define CP_WAIT2() asm volatile("cp.async.wait_group 2;")
#define CP_WAIT0() asm volatile("cp.async.wait_group 0;")

__device__ __forceinline__ void ldm_x4(uint32_t addr, uint32_t& r0,
                                       uint32_t& r1, uint32_t& r2,
                                       uint32_t& r3) {
  asm volatile(
      "ldmatrix.sync.aligned.m8n8.x4.shared.b16 {%0,%1,%2,%3}, [%4];"
      : "=r"(r0), "=r"(r1), "=r"(r2), "=r"(r3) : "r"(addr));
}

__device__ __forceinline__ void mma_f16(float* d, const uint32_t* a,
                                        const uint32_t* b) {
  asm volatile(
      "mma.sync.aligned.m16n8k16.row.col.f32.f16.f16.f32 "
      "{%0,%1,%2,%3}, {%4,%5,%6,%7}, {%8,%9}, {%0,%1,%2,%3};"
      : "+f"(d[0]), "+f"(d[1]), "+f"(d[2]), "+f"(d[3])
      : "r"(a[0]), "r"(a[1]), "r"(a[2]), "r"(a[3]), "r"(b[0]), "r"(b[1]));
}

__device__ __forceinline__ uint32_t sw128(uint32_t o) {
  return o ^ ((o >> 3) & 0x70);
}
// fold swizzle: two 64B logical rows per 128B phys row, SW128 on phys rows.
__device__ __forceinline__ uint32_t fold_off(int r, int byte) {
  uint32_t off = (uint32_t)(((r >> 1) << 7) + ((r & 1) << 6) + byte);
  return off ^ ((off >> 3) & 0x70);
}

// split two fp32 -> (hi half2, lo half2)
__device__ __forceinline__ void split2(float x, float y, uint32_t& h,
                                       uint32_t& l) {
  __half2 hh = __floats2half2_rn(x, y);
  __half2 ll = __floats2half2_rn(x - __low2float(hh), y - __high2float(hh));
  h = *(uint32_t*)&hh;
  l = *(uint32_t*)&ll;
}
__device__ __forceinline__ uint32_t pack2h(float x, float y) {
  __half2 hh = __floats2half2_rn(x, y);
  return *(uint32_t*)&hh;
}

__device__ __forceinline__ float4 lds128(uint32_t a) {
  float4 v;
  asm volatile("ld.shared.v4.f32 {%0,%1,%2,%3}, [%4];"
               : "=f"(v.x), "=f"(v.y), "=f"(v.z), "=f"(v.w) : "r"(a));
  return v;
}
__device__ __forceinline__ float lds32(uint32_t a) {
  float v;
  asm volatile("ld.shared.f32 %0, [%1];" : "=f"(v) : "r"(a));
  return v;
}
__device__ __forceinline__ void sts128(uint32_t a, uint32_t x, uint32_t y,
                                       uint32_t z, uint32_t w) {
  asm volatile("st.shared.v4.b32 [%0], {%1,%2,%3,%4};" ::"r"(a), "r"(x),
               "r"(y), "r"(z), "r"(w));
}

// smem layouts:
//   shallow (bmode 0,1,3): 3 stages x 32KB (A hi 8K, A lo 8K, B 16K)
//   deep    (bmode 2, as=1): 4 stages x 24KB (A hi 8K, B fp32 16K)
// convert-out pair/ping-pong region at 96KB (16KB)
#define OFF_PAIR 98304
#define SMEM_DYN (114688 + 1024)
#define PITCH 129

// bmode: 0 = B pair (fp16 hi/lo from global), 1 = B single (fp16 from global),
//        2 = B exp-single (fp32 src, exp(x-mx)/sum), 3 = B ident-pair
//            (fp32 src, transposed staging, hi/lo out)
struct GArg {
  const hf *Ah, *Al, *Bh;
  const float *Bf, *mxv, *sumv, *bias;
  float *oNf;
  hf *oNh, *oTh, *oTl;
  float *prm, *prs, *pcm, *pcs, *pbs, *pbs2;
  int bmode, trans, as;  // as = A single (skip lo operand)
};

// stage one K=32 chunk into stage slot s (layout params stride/offB/offAlo)
__device__ __forceinline__ void stage32(uint32_t u_sb, int s, uint32_t stride,
                                        uint32_t offB, const hf* Ah,
                                        const hf* Al, int lda, const hf* Bh,
                                        const float* Bf, int ldb, int tid,
                                        int k0, int bmode, int trans,
                                        int as) {
  uint32_t abase = u_sb + (uint32_t)s * stride;
  uint32_t bbase = abase + offB;
#pragma unroll
  for (int t = 0; t < 2; t++) {
    int idx = tid + (t << 8);
    int r = idx >> 2, q = idx & 3;
    uint32_t o = fold_off(r, q << 4);
    CP16(abase + o, Ah + (size_t)r * lda + k0 + (q << 3));
    if (!as) CP16(abase + 8192 + o, Al + (size_t)r * lda + k0 + (q << 3));
  }
  if (bmode >= 2) {
    if (bmode == 3 || trans) {
      // rows = k (32 x 512B), cols = 128 m floats
#pragma unroll
      for (int t = 0; t < 4; t++) {
        int idx = tid + (t << 8);
        int r = idx >> 5, q = idx & 31;
        CP16(bbase + (r << 9) + (q << 4),
             Bf + (size_t)(k0 + r) * ldb + (q << 2));
      }
    } else {
      // rows = m (128 x 128B fp32, SW128)
#pragma unroll
      for (int t = 0; t < 4; t++) {
        int idx = tid + (t << 8);
        int r = idx >> 3, q = idx & 7;
        CP16(bbase + sw128((r << 7) + (q << 4)),
             Bf + (size_t)r * ldb + k0 + (q << 2));
      }
    }
  } else if (bmode == 1) {  // B single fp16
#pragma unroll
    for (int t = 0; t < 2; t++) {
      int idx = tid + (t << 8);
      int r = idx >> 2, q = idx & 3;
      CP16(bbase + fold_off(r, q << 4), Bh + (size_t)r * ldb + k0 + (q << 3));
    }
  } else {  // B pair fp16 (lo at +KB*KN*KCI)
#pragma unroll
    for (int t = 0; t < 2; t++) {
      int idx = tid + (t << 8);
      int r = idx >> 2, q = idx & 3;
      uint32_t o = fold_off(r, q << 4);
      CP16(bbase + o, Bh + (size_t)r * ldb + k0 + (q << 3));
      CP16(bbase + 8192 + o,
           Bh + (size_t)KB * KN * KCI + (size_t)r * ldb + k0 + (q << 3));
    }
  }
}

// exp convert, row-major source (m rows x 128B): -> single fp16
__device__ __forceinline__ void convert_exp(uint32_t srcb, uint32_t pb,
                                            int tid, float mx, float iv) {
  int m = tid >> 1, h = tid & 1;
  float v[16];
#pragma unroll
  for (int j = 0; j < 4; j++) {
    float4 x = lds128(srcb + sw128((m << 7) + (h << 6) + (j << 4)));
    v[4 * j] = x.x; v[4 * j + 1] = x.y; v[4 * j + 2] = x.z; v[4 * j + 3] = x.w;
  }
#pragma unroll
  for (int j = 0; j < 16; j++) v[j] = __expf(v[j] - mx) * iv;
  uint32_t w[8];
#pragma unroll
  for (int j = 0; j < 8; j++) w[j] = pack2h(v[2 * j], v[2 * j + 1]);
  sts128(pb + fold_off(m, h << 5), w[0], w[1], w[2], w[3]);
  sts128(pb + fold_off(m, (h << 5) + 16), w[4], w[5], w[6], w[7]);
}

// exp convert, transposed source (k rows x 512B) -> single fp16, rows = m
__device__ __forceinline__ void convert_expT(uint32_t srcb, uint32_t pb,
                                             int tid, float mx, float iv) {
  int m = tid & 127;
  int kg = (tid >> 7) << 4;
  float v[16];
#pragma unroll
  for (int j = 0; j < 16; j++)
    v[j] = lds32(srcb + (uint32_t)((kg + j) << 9) + (uint32_t)(m << 2));
#pragma unroll
  for (int j = 0; j < 16; j++) v[j] = __expf(v[j] - mx) * iv;
  uint32_t w[8];
#pragma unroll
  for (int j = 0; j < 8; j++) w[j] = pack2h(v[2 * j], v[2 * j + 1]);
  sts128(pb + fold_off(m, kg << 1), w[0], w[1], w[2], w[3]);
  sts128(pb + fold_off(m, (kg << 1) + 16), w[4], w[5], w[6], w[7]);
}

// identity convert, transposed source -> fp16 PAIR (hi at pb, lo at pb+8192)
__device__ __forceinline__ void convert_idT(uint32_t srcb, uint32_t pb,
                                            int tid) {
  int m = tid & 127;
  int kg = (tid >> 7) << 4;
  float v[16];
#pragma unroll
  for (int j = 0; j < 16; j++)
    v[j] = lds32(srcb + (uint32_t)((kg + j) << 9) + (uint32_t)(m << 2));
  uint32_t hw[8], lw[8];
#pragma unroll
  for (int j = 0; j < 8; j++) split2(v[2 * j], v[2 * j + 1], hw[j], lw[j]);
  uint32_t o0 = fold_off(m, kg << 1);
  uint32_t o1 = fold_off(m, (kg << 1) + 16);
  sts128(pb + o0, hw[0], hw[1], hw[2], hw[3]);
  sts128(pb + o1, hw[4], hw[5], hw[6], hw[7]);
  sts128(pb + 8192 + o0, lw[0], lw[1], lw[2], lw[3]);
  sts128(pb + 8192 + o1, lw[4], lw[5], lw[6], lw[7]);
}

// one K=32 chunk of MMAs
__device__ __forceinline__ void mma_chunk(uint32_t abase, uint32_t bh_base,
                                          uint32_t bl_base, bool bpair,
                                          bool asingle, float (*acc)[8][4],
                                          int wr, int wc, int aRow, int aCb,
                                          int bRow, int bCb) {
#pragma unroll
  for (int ks = 0; ks < 2; ks++) {
    int kb = ks << 5;
    uint32_t ah[2][4], al[2][4];
#pragma unroll
    for (int mi = 0; mi < 2; mi++) {
      int r = wr * 32 + mi * 16 + aRow;
      uint32_t o = fold_off(r, kb + aCb);
      ldm_x4(abase + o, ah[mi][0], ah[mi][1], ah[mi][2], ah[mi][3]);
      if (!asingle)
        ldm_x4(abase + 8192 + o, al[mi][0], al[mi][1], al[mi][2], al[mi][3]);
    }
#pragma unroll
    for (int ng = 0; ng < 4; ng++) {
      uint32_t bh2[4], bl2[4];
      int r = wc * 64 + ng * 16 + bRow;
      uint32_t o = fold_off(r, kb + bCb);
      ldm_x4(bh_base + o, bh2[0], bh2[1], bh2[2], bh2[3]);
      if (bpair) ldm_x4(bl_base + o, bl2[0], bl2[1], bl2[2], bl2[3]);
#pragma unroll
      for (int mi = 0; mi < 2; mi++)
#pragma unroll
        for (int ns = 0; ns < 2; ns++) {
          float* d = acc[mi][ng * 2 + ns];
          mma_f16(d, ah[mi], &bh2[ns * 2]);
          if (bpair) mma_f16(d, ah[mi], &bl2[ns * 2]);
          if (!asingle) mma_f16(d, al[mi], &bh2[ns * 2]);
        }
    }
  }
}

// =============================================================================
// fp16 HMMA GEMM: block 128x128, warp 32x64, K=32 chunks.
// bmode 2 (exp, A single): 4-slot deep pipeline, convert-ahead, 1 sync/chunk.
// others: 3-slot pipeline.
// =============================================================================
__global__ __launch_bounds__(256, 2) void gemm_f16(
    GArg a0, GArg a1,
    unsigned long long sA, int lda, unsigned long long sB, int ldb,
    unsigned long long soNf, int ldoNf,
    unsigned long long soN, int ldoN, unsigned long long soT, int ldoT,
    int K) {
  extern __shared__ __align__(1024) char s_dyn[];
  char* sb = (char*)(((uintptr_t)s_dyn + 1023) & ~(uintptr_t)1023);
  float* s_f32 = (float*)sb;  // epilogue staging [128][PITCH]
  uint32_t u_sb = smem_u32(sb);

  int tid = threadIdx.x;
  int wid = tid >> 5, lane = tid & 31;
  int wr = wid & 3, wc = wid >> 2;
  int half = blockIdx.z >> 4;
  int b = blockIdx.z & (KB - 1);
  int i0 = blockIdx.y * 128;
  int n0 = blockIdx.x * 128;
#define SEL(f) (half ? a1.f : a0.f)
  int bmode = SEL(bmode);
  int trans = SEL(trans);
  int as = SEL(as);
  bool deep = (bmode == 2);
  uint32_t stride = deep ? 24576u : 32768u;
  uint32_t offB = deep ? 8192u : 16384u;

  const hf* Ah = SEL(Ah) + (size_t)b * sA + (size_t)i0 * lda;
  const hf* Al = as ? nullptr : SEL(Al) + (size_t)b * sA + (size_t)i0 * lda;
  const hf* Bh = nullptr;
  const float* Bf = nullptr;
  if (bmode >= 2) {
    Bf = SEL(Bf) + (size_t)b * sB;
    if (bmode == 3 || trans) Bf += n0;
    else Bf += (size_t)n0 * ldb;
  } else {
    Bh = SEL(Bh) + (size_t)b * sB + (size_t)n0 * ldb;
  }

  float mxe = 0.f, ive = 1.f;
  if (bmode == 2) {
    const float* mxv = SEL(mxv);
    const float* sumv = SEL(sumv);
    int mrow = trans ? (tid & 127) : (tid >> 1);
    mxe = mxv[b * KN + n0 + mrow];
    ive = 1.0f / sumv[b * KN + n0 + mrow];
  }

  int aRow = lane & 15, aCb = (lane >> 4) * 16;
  int bRow = ((lane >> 4) & 1) * 8 + (lane & 7);
  int bCb = ((lane >> 3) & 1) * 16;

  float acc[2][8][4];
#pragma unroll
  for (int mi = 0; mi < 2; mi++)
#pragma unroll
    for (int ni = 0; ni < 8; ni++)
#pragma unroll
      for (int e = 0; e < 4; e++) acc[mi][ni][e] = 0.f;

  int NC = K >> 5;

  if (deep) {
    // ---- 4-slot deep pipeline, convert-ahead, 1 sync/chunk ----
#pragma unroll
    for (int p = 0; p < 3; p++) {
      stage32(u_sb, p, stride, offB, Ah, Al, lda, Bh, Bf, ldb, tid, p << 5,
              bmode, trans, as);
      CP_COMMIT();
    }
    CP_WAIT2();
    __syncthreads();
    {
      uint32_t pb = u_sb + OFF_PAIR;
      if (trans) convert_expT(u_sb + offB, pb, tid, mxe, ive);
      else convert_exp(u_sb + offB, pb, tid, mxe, ive);
    }
    for (int ch = 0; ch < NC; ch++) {
      CP_WAIT1();
      __syncthreads();
      if (ch + 3 < NC)
        stage32(u_sb, (ch + 3) & 3, stride, offB, Ah, Al, lda, Bh, Bf, ldb,
                tid, (ch + 3) << 5, bmode, trans, as);
      CP_COMMIT();
      if (ch + 1 < NC) {
        uint32_t srcb = u_sb + (uint32_t)((ch + 1) & 3) * stride + offB;
        uint32_t pb = u_sb + OFF_PAIR + (((ch + 1) & 1) << 13);
        if (trans) convert_expT(srcb, pb, tid, mxe, ive);
        else convert_exp(srcb, pb, tid, mxe, ive);
      }
      uint32_t abase = u_sb + (uint32_t)(ch & 3) * stride;
      uint32_t bh_base = u_sb + OFF_PAIR + ((ch & 1) << 13);
      mma_chunk(abase, bh_base, 0u, false, true, acc, wr, wc, aRow, aCb, bRow,
                bCb);
    }
  } else {
    // ---- 3-slot pipeline ----
    stage32(u_sb, 0, stride, offB, Ah, Al, lda, Bh, Bf, ldb, tid, 0, bmode,
            trans, as);
    CP_COMMIT();
    stage32(u_sb, 1, stride, offB, Ah, Al, lda, Bh, Bf, ldb, tid, 32, bmode,
            trans, as);
    CP_COMMIT();
    int sl = 0, sl2 = 2;
    for (int ch = 0; ch < NC; ch++) {
      CP_WAIT1();
      __syncthreads();
      if (ch + 2 < NC)
        stage32(u_sb, sl2, stride, offB, Ah, Al, lda, Bh, Bf, ldb, tid,
                (ch + 2) << 5, bmode, trans, as);
      CP_COMMIT();
      uint32_t sbase = u_sb + (uint32_t)sl * stride;
      uint32_t bh_base, bl_base = 0;
      bool bpair = (bmode == 0 || bmode == 3);
      if (bmode == 3) {
        uint32_t pb = u_sb + OFF_PAIR;
        convert_idT(sbase + offB, pb, tid);
        __syncthreads();
        bh_base = pb;
        bl_base = pb + 8192;
      } else {
        bh_base = sbase + offB;
        bl_base = sbase + offB + 8192;
      }
      mma_chunk(sbase, bh_base, bl_base, bpair, as != 0, acc, wr, wc, aRow,
                aCb, bRow, bCb);
      sl = (sl == 2) ? 0 : sl + 1;
      sl2 = (sl2 == 2) ? 0 : sl2 + 1;
    }
  }
  CP_WAIT0();
  __syncthreads();

  // --------------------------- epilogue --------------------------------------
  const float* bias = SEL(bias);
#pragma unroll
  for (int mi = 0; mi < 2; mi++) {
    int rl = wr * 32 + mi * 16 + (lane >> 2);
    float bv0 = bias ? __ldg(bias + i0 + rl) : 0.f;
    float bv1 = bias ? __ldg(bias + i0 + rl + 8) : 0.f;
#pragma unroll
    for (int ni = 0; ni < 8; ni++) {
      int c = wc * 64 + ni * 8 + 2 * (lane & 3);
      s_f32[rl * PITCH + c] = acc[mi][ni][0] + bv0;
      s_f32[rl * PITCH + c + 1] = acc[mi][ni][1] + bv0;
      s_f32[(rl + 8) * PITCH + c] = acc[mi][ni][2] + bv1;
      s_f32[(rl + 8) * PITCH + c + 1] = acc[mi][ni][3] + bv1;
    }
  }
  __syncthreads();

  if (float* oNf = SEL(oNf)) {
    float* on = oNf + (size_t)b * soNf;
#pragma unroll
    for (int t = 0; t < 16; t++) {
      int idx = tid + (t << 8);
      int rr = idx >> 5, q = idx & 31;
      float4 v;
      v.x = s_f32[rr * PITCH + q * 4 + 0];
      v.y = s_f32[rr * PITCH + q * 4 + 1];
      v.z = s_f32[rr * PITCH + q * 4 + 2];
      v.w = s_f32[rr * PITCH + q * 4 + 3];
      *(float4*)(on + (size_t)(i0 + rr) * ldoNf + n0 + (q << 2)) = v;
    }
  }
  if (hf* oNh = SEL(oNh)) {  // single fp16 normal-layout output
    hf* oh = oNh + (size_t)b * soN;
#pragma unroll
    for (int t = 0; t < 16; t++) {
      int idx = tid + (t << 8);
      int rr = idx >> 5, q = idx & 31;
      uint32_t h0 = pack2h(s_f32[rr * PITCH + q * 4 + 0],
                           s_f32[rr * PITCH + q * 4 + 1]);
      uint32_t h1 = pack2h(s_f32[rr * PITCH + q * 4 + 2],
                           s_f32[rr * PITCH + q * 4 + 3]);
      size_t base = (size_t)(i0 + rr) * ldoN + n0 + (q << 2);
      *(uint32_t*)(oh + base) = h0;
      *(uint32_t*)(oh + base + 2) = h1;
    }
  }
  if (hf* oTh = SEL(oTh)) {  // transposed output: pair if oTl, else single
    hf* oh = oTh + (size_t)b * soT;
    hf* ol = SEL(oTl);
    if (ol) ol += (size_t)b * soT;
#pragma unroll
    for (int t = 0; t < 16; t++) {
      int idx = tid + (t << 8);
      int c = idx >> 5, rq = (idx & 31) << 2;
      size_t base = (size_t)(n0 + c) * ldoT + i0 + rq;
      if (ol) {
        uint32_t h0, l0, h1, l1;
        split2(s_f32[(rq + 0) * PITCH + c], s_f32[(rq + 1) * PITCH + c], h0,
               l0);
        split2(s_f32[(rq + 2) * PITCH + c], s_f32[(rq + 3) * PITCH + c], h1,
               l1);
        *(uint32_t*)(oh + base) = h0;
        *(uint32_t*)(oh + base + 2) = h1;
        *(uint32_t*)(ol + base) = l0;
        *(uint32_t*)(ol + base + 2) = l1;
      } else {
        uint32_t h0 = pack2h(s_f32[(rq + 0) * PITCH + c],
                             s_f32[(rq + 1) * PITCH + c]);
        uint32_t h1 = pack2h(s_f32[(rq + 2) * PITCH + c],
                             s_f32[(rq + 3) * PITCH + c]);
        *(uint32_t*)(oh + base) = h0;
        *(uint32_t*)(oh + base + 2) = h1;
      }
    }
  }
  if (float* prm = SEL(prm)) {
    {  // row partials: 2 threads per row
      int r = tid >> 1, hh = tid & 1;
      float pm = -1e30f;
#pragma unroll 8
      for (int j = 0; j < 64; j++) {
        int c = hh * 64 + ((j + 16 * hh) & 63);
        pm = fmaxf(pm, s_f32[r * PITCH + c]);
      }
      pm = fmaxf(pm, __shfl_xor_sync(0xffffffffu, pm, 1));
      float ps = 0.f;
#pragma unroll 8
      for (int j = 0; j < 64; j++) {
        int c = hh * 64 + ((j + 16 * hh) & 63);
        ps += __expf(s_f32[r * PITCH + c] - pm);
      }
      ps += __shfl_xor_sync(0xffffffffu, ps, 1);
      if (hh == 0) {
        size_t o = (size_t)(b * KN + i0 + r) * gridDim.x + blockIdx.x;
        prm[o] = pm;
        SEL(prs)[o] = ps;
      }
    }
    {  // col partials: 2 threads per col
      int c = tid >> 1, hh = tid & 1;
      float pm = -1e30f;
#pragma unroll 8
      for (int j = 0; j < 64; j++) {
        int r = hh * 64 + ((j + (c & 31)) & 63);
        pm = fmaxf(pm, s_f32[r * PITCH + c]);
      }
      pm = fmaxf(pm, __shfl_xor_sync(0xffffffffu, pm, 1));
      float ps = 0.f;
#pragma unroll 8
      for (int j = 0; j < 64; j++) {
        int r = hh * 64 + ((j + (c & 31)) & 63);
        ps += __expf(s_f32[r * PITCH + c] - pm);
      }
      ps += __shfl_xor_sync(0xffffffffu, ps, 1);
      if (hh == 0) {
        size_t o = (size_t)(b * KN + n0 + c) * gridDim.y + blockIdx.y;
        SEL(pcm)[o] = pm;
        SEL(pcs)[o] = ps;
      }
    }
  }
  if (float* pbs = SEL(pbs)) {  // BN partials: 2 threads per row
    int r = tid >> 1, hh = tid & 1;
    float s = 0.f, s2 = 0.f;
#pragma unroll 8
    for (int j = 0; j < 64; j++) {
      int c = hh * 64 + ((j + 16 * hh) & 63);
      float v = s_f32[r * PITCH + c];
      s += v;
      s2 += v * v;
    }
    s += __shfl_xor_sync(0xffffffffu, s, 1);
    s2 += __shfl_xor_sync(0xffffffffu, s2, 1);
    if (hh == 0) {
      size_t o = ((size_t)(i0 + r) * KB + b) * gridDim.x + blockIdx.x;
      pbs[o] = s;
      SEL(pbs2)[o] = s2;
    }
  }
#undef SEL
}

// =============================================================================
// convert 4 weight matrices (each 131072 elems) to hi/lo
// =============================================================================
__global__ __launch_bounds__(256) void convert_w(
    const float* __restrict__ s0, const float* __restrict__ s1,
    const float* __restrict__ s2, const float* __restrict__ s3) {
  int idx = blockIdx.x * 256 + threadIdx.x;
  int sel = idx >> 17, w = idx & 131071;
  const float* s = sel == 0 ? s0 : sel == 1 ? s1 : sel == 2 ? s2 : s3;
  hf* h = sel == 0 ? g_wgr_h : sel == 1 ? g_wgf_h : sel == 2 ? g_wwr_h
                                                             : g_wwf_h;
  hf* l = sel == 0 ? g_wgr_l : sel == 1 ? g_wgf_l : sel == 2 ? g_wwr_l
                                                             : g_wwf_l;
  float v = s[w];
  hf hh = __float2half_rn(v);
  h[w] = hh;
  l[w] = __float2half_rn(v - __half2float(hh));
}

// =============================================================================
// combine softmax partials (8 per row, 8 per col)
// =============================================================================
__global__ __launch_bounds__(256) void softmax_combine() {
  int t = blockIdx.x * 256 + threadIdx.x;
  const int total = KB * KN;
  if (t < total) {
    float m = -1e30f;
#pragma unroll
    for (int j = 0; j < 8; j++) m = fmaxf(m, g_prm[t * 8 + j]);
    float s = 0.f;
#pragma unroll
    for (int j = 0; j < 8; j++)
      s += g_prs[t * 8 + j] * __expf(g_prm[t * 8 + j] - m);
    g_rmax[t] = m;
    g_rsum[t] = s;
  } else if (t < 2 * total) {
    int u = t - total;
    float m = -1e30f;
#pragma unroll
    for (int j = 0; j < 8; j++) m = fmaxf(m, g_pcm[u * 8 + j]);
    float s = 0.f;
#pragma unroll
    for (int j = 0; j < 8; j++)
      s += g_pcs[u * 8 + j] * __expf(g_pcm[u * 8 + j] - m);
    g_cmax[u] = m;
    g_csum[u] = s;
  }
}

// =============================================================================
// BN combine + merged finalize
// =============================================================================
__global__ __launch_bounds__(256) void bnfinal_kernel() {
  int t = blockIdx.x * 256 + threadIdx.x;
  if (t >= 2 * KC) return;
  float s = 0.f, s2 = 0.f;
  for (int j = 0; j < KB * 8; j++) {
    s += g_pbs[(size_t)t * (KB * 8) + j];
    s2 += g_pbs2[(size_t)t * (KB * 8) + j];
  }
  float m = s / (float)(KB * KN);
  float var = s2 / (float)(KB * KN) - m * m;
  g_mean[t] = m;
  g_rstd[t] = rsqrtf(var + 1e-5f);
}

__global__ __launch_bounds__(256) void finalize_kernel(
    const float* __restrict__ X0, const float* __restrict__ X1,
    const float* __restrict__ gamma0, const float* __restrict__ beta0,
    const float* __restrict__ gamma1, const float* __restrict__ beta1,
    float* __restrict__ Z) {
  size_t idx = (size_t)blockIdx.x * 256 + threadIdx.x;
  int sel = (int)(idx >> 23);
  size_t li = idx & ((1ull << 23) - 1);
  int c = (int)((idx >> 10) & (KC - 1));
  float m = g_mean[sel * KC + c];
  float r = g_rstd[sel * KC + c];
  float g = sel ? gamma1[c] : gamma0[c];
  float be = sel ? beta1[c] : beta0[c];
  float x = sel ? X1[li] : X0[li];
  Z[idx] = (g_t[idx] - m) * r * g + be + x;
}

// =============================================================================
extern "C" void kernel_launch(void* const* d_in, const int* in_sizes, int n_in,
                              void* d_out, int out_size) {
  const float* rgb        = (const float*)d_in[0];
  const float* flow       = (const float*)d_in[1];
  const float* wg_rgb     = (const float*)d_in[2];
  const float* bg_rgb     = (const float*)d_in[3];
  const float* wg_flow    = (const float*)d_in[4];
  const float* bg_flow    = (const float*)d_in[5];
  const float* ww_rgb     = (const float*)d_in[6];
  const float* bw_rgb     = (const float*)d_in[7];
  const float* gamma_rgb  = (const float*)d_in[8];
  const float* beta_rgb   = (const float*)d_in[9];
  const float* ww_flow    = (const float*)d_in[10];
  const float* bw_flow    = (const float*)d_in[11];
  const float* gamma_flow = (const float*)d_in[12];
  const float* beta_flow  = (const float*)d_in[13];
  float* out = (float*)d_out;

#define SYM(p, g) cudaGetSymbolAddress((void**)&p, g)
  hf *wgr_h, *wgr_l, *wgf_h, *wgf_l, *wwr_h, *wwr_l, *wwf_h, *wwf_l;
  hf *re_h, *fe_h, *reT_h, *reT_l, *feT_h, *feT_l, *yrT_h, *yfT_h;
  float *pS, *prmax, *prsum, *pcmax, *pcsum, *pt;
  float *pprm, *pprs, *ppcm, *ppcs, *ppbs, *ppbs2;
  SYM(wgr_h, g_wgr_h); SYM(wgr_l, g_wgr_l);
  SYM(wgf_h, g_wgf_h); SYM(wgf_l, g_wgf_l);
  SYM(wwr_h, g_wwr_h); SYM(wwr_l, g_wwr_l);
  SYM(wwf_h, g_wwf_h); SYM(wwf_l, g_wwf_l);
  SYM(re_h, g_re_h); SYM(fe_h, g_fe_h);
  SYM(reT_h, g_reT_h); SYM(reT_l, g_reT_l);
  SYM(feT_h, g_feT_h); SYM(feT_l, g_feT_l);
  SYM(yrT_h, g_yrT_h); SYM(yfT_h, g_yfT_h);
  SYM(pS, g_S);
  SYM(prmax, g_rmax); SYM(prsum, g_rsum);
  SYM(pcmax, g_cmax); SYM(pcsum, g_csum);
  SYM(pt, g_t);
  SYM(pprm, g_prm); SYM(pprs, g_prs);
  SYM(ppcm, g_pcm); SYM(ppcs, g_pcs);
  SYM(ppbs, g_pbs); SYM(ppbs2, g_pbs2);
#undef SYM

  cudaFuncSetAttribute(gemm_f16, cudaFuncAttributeMaxDynamicSharedMemorySize,
                       SMEM_DYN);
  dim3 thr(256);
  const unsigned long long sEN = (unsigned long long)KCI * KN;
  const unsigned long long sET = (unsigned long long)KN * KCI;
  const unsigned long long sXF = (unsigned long long)KC * KN;  // fp32 input
  const unsigned long long sSS = (unsigned long long)KN * KN;
  const unsigned long long sT = (unsigned long long)KC * KN;

  GArg z{};

  // 1) weight conversion
  convert_w<<<2048, thr>>>(wg_rgb, wg_flow, ww_rgb, ww_flow);

  // 2) merged embeds: B = fp32 input via transposed staging + ident pair
  {
    GArg a0 = z, a1 = z;
    a0.Ah = wgr_h; a0.Al = wgr_l; a0.Bf = rgb; a0.bias = bg_rgb;
    a0.oNh = re_h; a0.oTh = reT_h; a0.oTl = reT_l; a0.bmode = 3;
    a1.Ah = wgf_h; a1.Al = wgf_l; a1.Bf = flow; a1.bias = bg_flow;
    a1.oNh = fe_h; a1.oTh = feT_h; a1.oTl = feT_l; a1.bmode = 3;
    gemm_f16<<<dim3(8, 2, 2 * KB), thr, SMEM_DYN>>>(
        a0, a1, 0ull, KC, sXF, KN, 0ull, 0, sEN, KN, sET, KCI, KC);
  }

  // 3) scores: A pair, B pair (3-term); S fp32 + both softmax partial sets
  {
    GArg a0 = z;
    a0.Ah = reT_h; a0.Al = reT_l; a0.Bh = feT_h;  // lo at Bh + KB*KN*KCI
    a0.oNf = pS;
    a0.prm = pprm; a0.prs = pprs; a0.pcm = ppcm; a0.pcs = ppcs;
    a0.bmode = 0;
    gemm_f16<<<dim3(8, 8, KB), thr, SMEM_DYN>>>(
        a0, a0, sET, KCI, sET, KCI, sSS, KN, 0ull, 0, 0ull, 0, KCI);
  }

  // 4) stats combine
  softmax_combine<<<(2 * KB * KN) / 256, thr>>>();

  // 5) merged applies: A single, B exp-single, DEEP pipeline; y^T single out
  {
    GArg a0 = z, a1 = z;
    a0.Ah = fe_h; a0.Bf = pS; a0.mxv = prmax; a0.sumv = prsum;
    a0.oTh = yrT_h; a0.bmode = 2; a0.trans = 0; a0.as = 1;
    a1.Ah = re_h; a1.Bf = pS; a1.mxv = pcmax; a1.sumv = pcsum;
    a1.oTh = yfT_h; a1.bmode = 2; a1.trans = 1; a1.as = 1;
    gemm_f16<<<dim3(8, 2, 2 * KB), thr, SMEM_DYN>>>(
        a0, a1, sEN, KN, sSS, KN, 0ull, 0, 0ull, 0, sET, KCI, KN);
  }

  // 6) merged conv2: A = W pair, B = yT single (2-term); fp32 out + BN part.
  {
    GArg a0 = z, a1 = z;
    a0.Ah = wwr_h; a0.Al = wwr_l; a0.Bh = yrT_h; a0.bias = bw_rgb;
    a0.oNf = pt; a0.pbs = ppbs; a0.pbs2 = ppbs2; a0.bmode = 1;
    a1.Ah = wwf_h; a1.Al = wwf_l; a1.Bh = yfT_h; a1.bias = bw_flow;
    a1.oNf = pt + (size_t)KB * KC * KN;
    a1.pbs = ppbs + (size_t)KC * KB * 8;
    a1.pbs2 = ppbs2 + (size_t)KC * KB * 8;
    a1.bmode = 1;
    gemm_f16<<<dim3(8, 4, 2 * KB), thr, SMEM_DYN>>>(
        a0, a1, 0ull, KCI, sET, KCI, sT, KN, 0ull, 0, 0ull, 0, KCI);
  }

  // 7) BN combine + merged finalize
  bnfinal_kernel<<<4, thr>>>();
  finalize_kernel<<<(2 * KB * KC * KN) / 256, thr>>>(
      rgb, flow, gamma_rgb, beta_rgb, gamma_flow, beta_flow, out);
}

// round 15
// speedup vs baseline: 2.2065x; 1.0460x over previous
#include <cuda_runtime.h>
#include <cuda_fp16.h>
#include <cstdint>

#define KB 16
#define KC 512
#define KCI 256
#define KN 1024

typedef __half hf;

// ---------------- scratch (no allocs allowed -> __device__ globals) ----------
__device__ hf g_wgr_h[KCI * KC], g_wgr_l[KCI * KC];
__device__ hf g_wgf_h[KCI * KC], g_wgf_l[KCI * KC];
__device__ hf g_wwr_h[KC * KCI], g_wwr_l[KC * KCI];
__device__ hf g_wwf_h[KC * KCI], g_wwf_l[KC * KCI];
__device__ hf g_re_h[(size_t)KB * KCI * KN];   // apply A operand (single)
__device__ hf g_fe_h[(size_t)KB * KCI * KN];
__device__ hf g_reT_h[(size_t)KB * KN * KCI], g_reT_l[(size_t)KB * KN * KCI];
__device__ hf g_feT_h[(size_t)KB * KN * KCI], g_feT_l[(size_t)KB * KN * KCI];
__device__ float g_S[(size_t)KB * KN * KN];
__device__ hf g_yrT_h[(size_t)KB * KN * KCI];  // y stored single
__device__ hf g_yfT_h[(size_t)KB * KN * KCI];
__device__ hf g_t16[2 * (size_t)KB * KC * KN];  // conv2 out, fp16 single
__device__ float g_mean[2 * KC];
__device__ float g_rstd[2 * KC];
__device__ float g_rmax[KB * KN], g_rsum[KB * KN];
__device__ float g_cmax[KB * KN], g_csum[KB * KN];
__device__ float g_prm[KB * KN * 8], g_prs[KB * KN * 8];
__device__ float g_pcm[KB * KN * 8], g_pcs[KB * KN * 8];
__device__ float g_pbs[2 * KC * KB * 8], g_pbs2[2 * KC * KB * 8];

// ============================ helpers ========================================
__device__ __forceinline__ uint32_t smem_u32(const void* p) {
  uint32_t a;
  asm("{ .reg .u64 t; cvta.to.shared.u64 t, %1; cvt.u32.u64 %0, t; }"
      : "=r"(a) : "l"(p));
  return a;
}

#define CP16(dst, src)                                                         \
  asm volatile("cp.async.cg.shared.global [%0], [%1], 16;" ::"r"(dst),         \
               "l"(src))
#define CP_COMMIT() asm volatile("cp.async.commit_group;")
#define CP_WAIT1() asm volatile("cp.async.wait_group 1;")
#define CP_WAIT2() asm volatile("cp.async.wait_group 2;")
#define CP_WAIT0() asm volatile("cp.async.wait_group 0;")

__device__ __forceinline__ void ldm_x4(uint32_t addr, uint32_t& r0,
                                       uint32_t& r1, uint32_t& r2,
                                       uint32_t& r3) {
  asm volatile(
      "ldmatrix.sync.aligned.m8n8.x4.shared.b16 {%0,%1,%2,%3}, [%4];"
      : "=r"(r0), "=r"(r1), "=r"(r2), "=r"(r3) : "r"(addr));
}

__device__ __forceinline__ void mma_f16(float* d, const uint32_t* a,
                                        const uint32_t* b) {
  asm volatile(
      "mma.sync.aligned.m16n8k16.row.col.f32.f16.f16.f32 "
      "{%0,%1,%2,%3}, {%4,%5,%6,%7}, {%8,%9}, {%0,%1,%2,%3};"
      : "+f"(d[0]), "+f"(d[1]), "+f"(d[2]), "+f"(d[3])
      : "r"(a[0]), "r"(a[1]), "r"(a[2]), "r"(a[3]), "r"(b[0]), "r"(b[1]));
}

__device__ __forceinline__ uint32_t sw128(uint32_t o) {
  return o ^ ((o >> 3) & 0x70);
}
// fold swizzle: two 64B logical rows per 128B phys row, SW128 on phys rows.
__device__ __forceinline__ uint32_t fold_off(int r, int byte) {
  uint32_t off = (uint32_t)(((r >> 1) << 7) + ((r & 1) << 6) + byte);
  return off ^ ((off >> 3) & 0x70);
}

// split two fp32 -> (hi half2, lo half2)
__device__ __forceinline__ void split2(float x, float y, uint32_t& h,
                                       uint32_t& l) {
  __half2 hh = __floats2half2_rn(x, y);
  __half2 ll = __floats2half2_rn(x - __low2float(hh), y - __high2float(hh));
  h = *(uint32_t*)&hh;
  l = *(uint32_t*)&ll;
}
__device__ __forceinline__ uint32_t pack2h(float x, float y) {
  __half2 hh = __floats2half2_rn(x, y);
  return *(uint32_t*)&hh;
}

__device__ __forceinline__ float4 lds128(uint32_t a) {
  float4 v;
  asm volatile("ld.shared.v4.f32 {%0,%1,%2,%3}, [%4];"
               : "=f"(v.x), "=f"(v.y), "=f"(v.z), "=f"(v.w) : "r"(a));
  return v;
}
__device__ __forceinline__ float lds32(uint32_t a) {
  float v;
  asm volatile("ld.shared.f32 %0, [%1];" : "=f"(v) : "r"(a));
  return v;
}
__device__ __forceinline__ void sts128(uint32_t a, uint32_t x, uint32_t y,
                                       uint32_t z, uint32_t w) {
  asm volatile("st.shared.v4.b32 [%0], {%1,%2,%3,%4};" ::"r"(a), "r"(x),
               "r"(y), "r"(z), "r"(w));
}

// smem layouts:
//   shallow (bmode 0,1): 3 stages x 32KB (A hi 8K, A lo 8K, B 16K)
//   deep exp (bmode 2):  4 stages x 24KB (A hi 8K, B fp32 16K), pair @96K
//   deep id  (bmode 3):  A-pair 3 slots @0/16K/32K, B-fp32 2 slots @48K/64K,
//                        pair ping-pong @80K (p*16K: hi, +8192 lo)
#define OFF_PAIR 98304
#define OFF_ID_B 49152
#define OFF_ID_P 81920
#define SMEM_DYN (114688 + 1024)
#define PITCH 129

// bmode: 0 = B pair (fp16 hi/lo from global), 1 = B single (fp16 from global),
//        2 = B exp-single (fp32 src), 3 = B ident-pair (fp32 src, transposed)
struct GArg {
  const hf *Ah, *Al, *Bh;
  const float *Bf, *mxv, *sumv, *bias;
  float *oNf;
  hf *oNh, *oTh, *oTl;
  float *prm, *prs, *pcm, *pcs, *pbs, *pbs2;
  int bmode, trans, as;  // as = A single (skip lo operand)
};

// stage one K=32 chunk into stage slot s (modes 0,1,2)
__device__ __forceinline__ void stage32(uint32_t u_sb, int s, uint32_t stride,
                                        uint32_t offB, const hf* Ah,
                                        const hf* Al, int lda, const hf* Bh,
                                        const float* Bf, int ldb, int tid,
                                        int k0, int bmode, int trans,
                                        int as) {
  uint32_t abase = u_sb + (uint32_t)s * stride;
  uint32_t bbase = abase + offB;
#pragma unroll
  for (int t = 0; t < 2; t++) {
    int idx = tid + (t << 8);
    int r = idx >> 2, q = idx & 3;
    uint32_t o = fold_off(r, q << 4);
    CP16(abase + o, Ah + (size_t)r * lda + k0 + (q << 3));
    if (!as) CP16(abase + 8192 + o, Al + (size_t)r * lda + k0 + (q << 3));
  }
  if (bmode == 2) {
    if (trans) {
#pragma unroll
      for (int t = 0; t < 4; t++) {
        int idx = tid + (t << 8);
        int r = idx >> 5, q = idx & 31;
        CP16(bbase + (r << 9) + (q << 4),
             Bf + (size_t)(k0 + r) * ldb + (q << 2));
      }
    } else {
#pragma unroll
      for (int t = 0; t < 4; t++) {
        int idx = tid + (t << 8);
        int r = idx >> 3, q = idx & 7;
        CP16(bbase + sw128((r << 7) + (q << 4)),
             Bf + (size_t)r * ldb + k0 + (q << 2));
      }
    }
  } else if (bmode == 1) {  // B single fp16
#pragma unroll
    for (int t = 0; t < 2; t++) {
      int idx = tid + (t << 8);
      int r = idx >> 2, q = idx & 3;
      CP16(bbase + fold_off(r, q << 4), Bh + (size_t)r * ldb + k0 + (q << 3));
    }
  } else {  // B pair fp16 (lo at +KB*KN*KCI)
#pragma unroll
    for (int t = 0; t < 2; t++) {
      int idx = tid + (t << 8);
      int r = idx >> 2, q = idx & 3;
      uint32_t o = fold_off(r, q << 4);
      CP16(bbase + o, Bh + (size_t)r * ldb + k0 + (q << 3));
      CP16(bbase + 8192 + o,
           Bh + (size_t)KB * KN * KCI + (size_t)r * ldb + k0 + (q << 3));
    }
  }
}

// embed deep-id staging: A pair -> slot s%3 (16KB slots), B fp32 transposed
// -> slot s&1 (16KB slots at OFF_ID_B)
__device__ __forceinline__ void stage_id(uint32_t u_sb, int s, const hf* Ah,
                                         const hf* Al, int lda,
                                         const float* Bf, int ldb, int tid,
                                         int k0) {
  uint32_t abase = u_sb + (uint32_t)(s % 3) * 16384u;
  uint32_t bbase = u_sb + OFF_ID_B + (uint32_t)(s & 1) * 16384u;
#pragma unroll
  for (int t = 0; t < 2; t++) {
    int idx = tid + (t << 8);
    int r = idx >> 2, q = idx & 3;
    uint32_t o = fold_off(r, q << 4);
    CP16(abase + o, Ah + (size_t)r * lda + k0 + (q << 3));
    CP16(abase + 8192 + o, Al + (size_t)r * lda + k0 + (q << 3));
  }
#pragma unroll
  for (int t = 0; t < 4; t++) {
    int idx = tid + (t << 8);
    int r = idx >> 5, q = idx & 31;
    CP16(bbase + (r << 9) + (q << 4), Bf + (size_t)(k0 + r) * ldb + (q << 2));
  }
}

// exp convert, row-major source (m rows x 128B): -> single fp16
__device__ __forceinline__ void convert_exp(uint32_t srcb, uint32_t pb,
                                            int tid, float mx, float iv) {
  int m = tid >> 1, h = tid & 1;
  float v[16];
#pragma unroll
  for (int j = 0; j < 4; j++) {
    float4 x = lds128(srcb + sw128((m << 7) + (h << 6) + (j << 4)));
    v[4 * j] = x.x; v[4 * j + 1] = x.y; v[4 * j + 2] = x.z; v[4 * j + 3] = x.w;
  }
#pragma unroll
  for (int j = 0; j < 16; j++) v[j] = __expf(v[j] - mx) * iv;
  uint32_t w[8];
#pragma unroll
  for (int j = 0; j < 8; j++) w[j] = pack2h(v[2 * j], v[2 * j + 1]);
  sts128(pb + fold_off(m, h << 5), w[0], w[1], w[2], w[3]);
  sts128(pb + fold_off(m, (h << 5) + 16), w[4], w[5], w[6], w[7]);
}

// exp convert, transposed source (k rows x 512B) -> single fp16, rows = m
__device__ __forceinline__ void convert_expT(uint32_t srcb, uint32_t pb,
                                             int tid, float mx, float iv) {
  int m = tid & 127;
  int kg = (tid >> 7) << 4;
  float v[16];
#pragma unroll
  for (int j = 0; j < 16; j++)
    v[j] = lds32(srcb + (uint32_t)((kg + j) << 9) + (uint32_t)(m << 2));
#pragma unroll
  for (int j = 0; j < 16; j++) v[j] = __expf(v[j] - mx) * iv;
  uint32_t w[8];
#pragma unroll
  for (int j = 0; j < 8; j++) w[j] = pack2h(v[2 * j], v[2 * j + 1]);
  sts128(pb + fold_off(m, kg << 1), w[0], w[1], w[2], w[3]);
  sts128(pb + fold_off(m, (kg << 1) + 16), w[4], w[5], w[6], w[7]);
}

// identity convert, transposed source -> fp16 PAIR (hi at pb, lo at pb+8192)
__device__ __forceinline__ void convert_idT(uint32_t srcb, uint32_t pb,
                                            int tid) {
  int m = tid & 127;
  int kg = (tid >> 7) << 4;
  float v[16];
#pragma unroll
  for (int j = 0; j < 16; j++)
    v[j] = lds32(srcb + (uint32_t)((kg + j) << 9) + (uint32_t)(m << 2));
  uint32_t hw[8], lw[8];
#pragma unroll
  for (int j = 0; j < 8; j++) split2(v[2 * j], v[2 * j + 1], hw[j], lw[j]);
  uint32_t o0 = fold_off(m, kg << 1);
  uint32_t o1 = fold_off(m, (kg << 1) + 16);
  sts128(pb + o0, hw[0], hw[1], hw[2], hw[3]);
  sts128(pb + o1, hw[4], hw[5], hw[6], hw[7]);
  sts128(pb + 8192 + o0, lw[0], lw[1], lw[2], lw[3]);
  sts128(pb + 8192 + o1, lw[4], lw[5], lw[6], lw[7]);
}

// one K=32 chunk of MMAs
__device__ __forceinline__ void mma_chunk(uint32_t abase, uint32_t bh_base,
                                          uint32_t bl_base, bool bpair,
                                          bool asingle, float (*acc)[8][4],
                                          int wr, int wc, int aRow, int aCb,
                                          int bRow, int bCb) {
#pragma unroll
  for (int ks = 0; ks < 2; ks++) {
    int kb = ks << 5;
    uint32_t ah[2][4], al[2][4];
#pragma unroll
    for (int mi = 0; mi < 2; mi++) {
      int r = wr * 32 + mi * 16 + aRow;
      uint32_t o = fold_off(r, kb + aCb);
      ldm_x4(abase + o, ah[mi][0], ah[mi][1], ah[mi][2], ah[mi][3]);
      if (!asingle)
        ldm_x4(abase + 8192 + o, al[mi][0], al[mi][1], al[mi][2], al[mi][3]);
    }
#pragma unroll
    for (int ng = 0; ng < 4; ng++) {
      uint32_t bh2[4], bl2[4];
      int r = wc * 64 + ng * 16 + bRow;
      uint32_t o = fold_off(r, kb + bCb);
      ldm_x4(bh_base + o, bh2[0], bh2[1], bh2[2], bh2[3]);
      if (bpair) ldm_x4(bl_base + o, bl2[0], bl2[1], bl2[2], bl2[3]);
#pragma unroll
      for (int mi = 0; mi < 2; mi++)
#pragma unroll
        for (int ns = 0; ns < 2; ns++) {
          float* d = acc[mi][ng * 2 + ns];
          mma_f16(d, ah[mi], &bh2[ns * 2]);
          if (bpair) mma_f16(d, ah[mi], &bl2[ns * 2]);
          if (!asingle) mma_f16(d, al[mi], &bh2[ns * 2]);
        }
    }
  }
}

// =============================================================================
// fp16 HMMA GEMM: block 128x128, warp 32x64, K=32 chunks.
// bmode 2: 4-slot deep pipeline (convert-ahead, exp). bmode 3: asymmetric
// deep pipeline (A 3 slots, B 2 slots, ident pair convert-ahead). 1 sync/chunk
// for all modes.
// =============================================================================
__global__ __launch_bounds__(256, 2) void gemm_f16(
    GArg a0, GArg a1,
    unsigned long long sA, int lda, unsigned long long sB, int ldb,
    unsigned long long soNf, int ldoNf,
    unsigned long long soN, int ldoN, unsigned long long soT, int ldoT,
    int K) {
  extern __shared__ __align__(1024) char s_dyn[];
  char* sb = (char*)(((uintptr_t)s_dyn + 1023) & ~(uintptr_t)1023);
  float* s_f32 = (float*)sb;  // epilogue staging [128][PITCH]
  uint32_t u_sb = smem_u32(sb);

  int tid = threadIdx.x;
  int wid = tid >> 5, lane = tid & 31;
  int wr = wid & 3, wc = wid >> 2;
  int half = blockIdx.z >> 4;
  int b = blockIdx.z & (KB - 1);
  int i0 = blockIdx.y * 128;
  int n0 = blockIdx.x * 128;
#define SEL(f) (half ? a1.f : a0.f)
  int bmode = SEL(bmode);
  int trans = SEL(trans);
  int as = SEL(as);

  const hf* Ah = SEL(Ah) + (size_t)b * sA + (size_t)i0 * lda;
  const hf* Al = as ? nullptr : SEL(Al) + (size_t)b * sA + (size_t)i0 * lda;
  const hf* Bh = nullptr;
  const float* Bf = nullptr;
  if (bmode >= 2) {
    Bf = SEL(Bf) + (size_t)b * sB;
    if (bmode == 3 || trans) Bf += n0;
    else Bf += (size_t)n0 * ldb;
  } else {
    Bh = SEL(Bh) + (size_t)b * sB + (size_t)n0 * ldb;
  }

  float mxe = 0.f, ive = 1.f;
  if (bmode == 2) {
    const float* mxv = SEL(mxv);
    const float* sumv = SEL(sumv);
    int mrow = trans ? (tid & 127) : (tid >> 1);
    mxe = mxv[b * KN + n0 + mrow];
    ive = 1.0f / sumv[b * KN + n0 + mrow];
  }

  int aRow = lane & 15, aCb = (lane >> 4) * 16;
  int bRow = ((lane >> 4) & 1) * 8 + (lane & 7);
  int bCb = ((lane >> 3) & 1) * 16;

  float acc[2][8][4];
#pragma unroll
  for (int mi = 0; mi < 2; mi++)
#pragma unroll
    for (int ni = 0; ni < 8; ni++)
#pragma unroll
      for (int e = 0; e < 4; e++) acc[mi][ni][e] = 0.f;

  int NC = K >> 5;

  if (bmode == 2) {
    // ---- 4-slot deep pipeline, exp convert-ahead, 1 sync/chunk ----
    const uint32_t stride = 24576u, offB = 8192u;
#pragma unroll
    for (int p = 0; p < 3; p++) {
      stage32(u_sb, p, stride, offB, Ah, Al, lda, Bh, Bf, ldb, tid, p << 5,
              bmode, trans, as);
      CP_COMMIT();
    }
    CP_WAIT2();
    __syncthreads();
    {
      uint32_t pb = u_sb + OFF_PAIR;
      if (trans) convert_expT(u_sb + offB, pb, tid, mxe, ive);
      else convert_exp(u_sb + offB, pb, tid, mxe, ive);
    }
    for (int ch = 0; ch < NC; ch++) {
      CP_WAIT1();
      __syncthreads();
      if (ch + 3 < NC)
        stage32(u_sb, (ch + 3) & 3, stride, offB, Ah, Al, lda, Bh, Bf, ldb,
                tid, (ch + 3) << 5, bmode, trans, as);
      CP_COMMIT();
      if (ch + 1 < NC) {
        uint32_t srcb = u_sb + (uint32_t)((ch + 1) & 3) * stride + offB;
        uint32_t pb = u_sb + OFF_PAIR + (((ch + 1) & 1) << 13);
        if (trans) convert_expT(srcb, pb, tid, mxe, ive);
        else convert_exp(srcb, pb, tid, mxe, ive);
      }
      uint32_t abase = u_sb + (uint32_t)(ch & 3) * stride;
      uint32_t bh_base = u_sb + OFF_PAIR + ((ch & 1) << 13);
      mma_chunk(abase, bh_base, 0u, false, true, acc, wr, wc, aRow, aCb, bRow,
                bCb);
    }
  } else if (bmode == 3) {
    // ---- asymmetric deep pipeline (A x3, B x2), ident pair, 1 sync/chunk ---
    stage_id(u_sb, 0, Ah, Al, lda, Bf, ldb, tid, 0);
    CP_COMMIT();
    stage_id(u_sb, 1, Ah, Al, lda, Bf, ldb, tid, 32);
    CP_COMMIT();
    CP_WAIT1();
    __syncthreads();
    convert_idT(u_sb + OFF_ID_B, u_sb + OFF_ID_P, tid);  // chunk 0 -> pair 0
    for (int ch = 0; ch < NC; ch++) {
      CP_WAIT0();
      __syncthreads();
      if (ch + 2 < NC)
        stage_id(u_sb, ch + 2, Ah, Al, lda, Bf, ldb, tid, (ch + 2) << 5);
      CP_COMMIT();
      if (ch + 1 < NC) {
        uint32_t srcb = u_sb + OFF_ID_B + (uint32_t)((ch + 1) & 1) * 16384u;
        uint32_t pb = u_sb + OFF_ID_P + (uint32_t)((ch + 1) & 1) * 16384u;
        convert_idT(srcb, pb, tid);
      }
      uint32_t abase = u_sb + (uint32_t)(ch % 3) * 16384u;
      uint32_t pb = u_sb + OFF_ID_P + (uint32_t)(ch & 1) * 16384u;
      mma_chunk(abase, pb, pb + 8192, true, false, acc, wr, wc, aRow, aCb,
                bRow, bCb);
    }
  } else {
    // ---- 3-slot pipeline (bmode 0/1) ----
    const uint32_t stride = 32768u, offB = 16384u;
    stage32(u_sb, 0, stride, offB, Ah, Al, lda, Bh, Bf, ldb, tid, 0, bmode,
            trans, as);
    CP_COMMIT();
    stage32(u_sb, 1, stride, offB, Ah, Al, lda, Bh, Bf, ldb, tid, 32, bmode,
            trans, as);
    CP_COMMIT();
    int sl = 0, sl2 = 2;
    for (int ch = 0; ch < NC; ch++) {
      CP_WAIT1();
      __syncthreads();
      if (ch + 2 < NC)
        stage32(u_sb, sl2, stride, offB, Ah, Al, lda, Bh, Bf, ldb, tid,
                (ch + 2) << 5, bmode, trans, as);
      CP_COMMIT();
      uint32_t sbase = u_sb + (uint32_t)sl * stride;
      mma_chunk(sbase, sbase + offB, sbase + offB + 8192, bmode == 0,
                as != 0, acc, wr, wc, aRow, aCb, bRow, bCb);
      sl = (sl == 2) ? 0 : sl + 1;
      sl2 = (sl2 == 2) ? 0 : sl2 + 1;
    }
  }
  CP_WAIT0();
  __syncthreads();

  // --------------------------- epilogue --------------------------------------
  const float* bias = SEL(bias);
#pragma unroll
  for (int mi = 0; mi < 2; mi++) {
    int rl = wr * 32 + mi * 16 + (lane >> 2);
    float bv0 = bias ? __ldg(bias + i0 + rl) : 0.f;
    float bv1 = bias ? __ldg(bias + i0 + rl + 8) : 0.f;
#pragma unroll
    for (int ni = 0; ni < 8; ni++) {
      int c = wc * 64 + ni * 8 + 2 * (lane & 3);
      s_f32[rl * PITCH + c] = acc[mi][ni][0] + bv0;
      s_f32[rl * PITCH + c + 1] = acc[mi][ni][1] + bv0;
      s_f32[(rl + 8) * PITCH + c] = acc[mi][ni][2] + bv1;
      s_f32[(rl + 8) * PITCH + c + 1] = acc[mi][ni][3] + bv1;
    }
  }
  __syncthreads();

  if (float* oNf = SEL(oNf)) {
    float* on = oNf + (size_t)b * soNf;
#pragma unroll
    for (int t = 0; t < 16; t++) {
      int idx = tid + (t << 8);
      int rr = idx >> 5, q = idx & 31;
      float4 v;
      v.x = s_f32[rr * PITCH + q * 4 + 0];
      v.y = s_f32[rr * PITCH + q * 4 + 1];
      v.z = s_f32[rr * PITCH + q * 4 + 2];
      v.w = s_f32[rr * PITCH + q * 4 + 3];
      *(float4*)(on + (size_t)(i0 + rr) * ldoNf + n0 + (q << 2)) = v;
    }
  }
  if (hf* oNh = SEL(oNh)) {  // single fp16 normal-layout output
    hf* oh = oNh + (size_t)b * soN;
#pragma unroll
    for (int t = 0; t < 16; t++) {
      int idx = tid + (t << 8);
      int rr = idx >> 5, q = idx & 31;
      uint32_t h0 = pack2h(s_f32[rr * PITCH + q * 4 + 0],
                           s_f32[rr * PITCH + q * 4 + 1]);
      uint32_t h1 = pack2h(s_f32[rr * PITCH + q * 4 + 2],
                           s_f32[rr * PITCH + q * 4 + 3]);
      size_t base = (size_t)(i0 + rr) * ldoN + n0 + (q << 2);
      *(uint32_t*)(oh + base) = h0;
      *(uint32_t*)(oh + base + 2) = h1;
    }
  }
  if (hf* oTh = SEL(oTh)) {  // transposed output: pair if oTl, else single
    hf* oh = oTh + (size_t)b * soT;
    hf* ol = SEL(oTl);
    if (ol) ol += (size_t)b * soT;
#pragma unroll
    for (int t = 0; t < 16; t++) {
      int idx = tid + (t << 8);
      int c = idx >> 5, rq = (idx & 31) << 2;
      size_t base = (size_t)(n0 + c) * ldoT + i0 + rq;
      if (ol) {
        uint32_t h0, l0, h1, l1;
        split2(s_f32[(rq + 0) * PITCH + c], s_f32[(rq + 1) * PITCH + c], h0,
               l0);
        split2(s_f32[(rq + 2) * PITCH + c], s_f32[(rq + 3) * PITCH + c], h1,
               l1);
        *(uint32_t*)(oh + base) = h0;
        *(uint32_t*)(oh + base + 2) = h1;
        *(uint32_t*)(ol + base) = l0;
        *(uint32_t*)(ol + base + 2) = l1;
      } else {
        uint32_t h0 = pack2h(s_f32[(rq + 0) * PITCH + c],
                             s_f32[(rq + 1) * PITCH + c]);
        uint32_t h1 = pack2h(s_f32[(rq + 2) * PITCH + c],
                             s_f32[(rq + 3) * PITCH + c]);
        *(uint32_t*)(oh + base) = h0;
        *(uint32_t*)(oh + base + 2) = h1;
      }
    }
  }
  if (float* prm = SEL(prm)) {
    {  // row partials: 2 threads per row
      int r = tid >> 1, hh = tid & 1;
      float pm = -1e30f;
#pragma unroll 8
      for (int j = 0; j < 64; j++) {
        int c = hh * 64 + ((j + 16 * hh) & 63);
        pm = fmaxf(pm, s_f32[r * PITCH + c]);
      }
      pm = fmaxf(pm, __shfl_xor_sync(0xffffffffu, pm, 1));
      float ps = 0.f;
#pragma unroll 8
      for (int j = 0; j < 64; j++) {
        int c = hh * 64 + ((j + 16 * hh) & 63);
        ps += __expf(s_f32[r * PITCH + c] - pm);
      }
      ps += __shfl_xor_sync(0xffffffffu, ps, 1);
      if (hh == 0) {
        size_t o = (size_t)(b * KN + i0 + r) * gridDim.x + blockIdx.x;
        prm[o] = pm;
        SEL(prs)[o] = ps;
      }
    }
    {  // col partials: 2 threads per col
      int c = tid >> 1, hh = tid & 1;
      float pm = -1e30f;
#pragma unroll 8
      for (int j = 0; j < 64; j++) {
        int r = hh * 64 + ((j + (c & 31)) & 63);
        pm = fmaxf(pm, s_f32[r * PITCH + c]);
      }
      pm = fmaxf(pm, __shfl_xor_sync(0xffffffffu, pm, 1));
      float ps = 0.f;
#pragma unroll 8
      for (int j = 0; j < 64; j++) {
        int r = hh * 64 + ((j + (c & 31)) & 63);
        ps += __expf(s_f32[r * PITCH + c] - pm);
      }
      ps += __shfl_xor_sync(0xffffffffu, ps, 1);
      if (hh == 0) {
        size_t o = (size_t)(b * KN + n0 + c) * gridDim.y + blockIdx.y;
        SEL(pcm)[o] = pm;
        SEL(pcs)[o] = ps;
      }
    }
  }
  if (float* pbs = SEL(pbs)) {  // BN partials: 2 threads per row
    int r = tid >> 1, hh = tid & 1;
    float s = 0.f, s2 = 0.f;
#pragma unroll 8
    for (int j = 0; j < 64; j++) {
      int c = hh * 64 + ((j + 16 * hh) & 63);
      float v = s_f32[r * PITCH + c];
      s += v;
      s2 += v * v;
    }
    s += __shfl_xor_sync(0xffffffffu, s, 1);
    s2 += __shfl_xor_sync(0xffffffffu, s2, 1);
    if (hh == 0) {
      size_t o = ((size_t)(i0 + r) * KB + b) * gridDim.x + blockIdx.x;
      pbs[o] = s;
      SEL(pbs2)[o] = s2;
    }
  }
#undef SEL
}

// =============================================================================
// convert 4 weight matrices (each 131072 elems) to hi/lo
// =============================================================================
__global__ __launch_bounds__(256) void convert_w(
    const float* __restrict__ s0, const float* __restrict__ s1,
    const float* __restrict__ s2, const float* __restrict__ s3) {
  int idx = blockIdx.x * 256 + threadIdx.x;
  int sel = idx >> 17, w = idx & 131071;
  const float* s = sel == 0 ? s0 : sel == 1 ? s1 : sel == 2 ? s2 : s3;
  hf* h = sel == 0 ? g_wgr_h : sel == 1 ? g_wgf_h : sel == 2 ? g_wwr_h
                                                             : g_wwf_h;
  hf* l = sel == 0 ? g_wgr_l : sel == 1 ? g_wgf_l : sel == 2 ? g_wwr_l
                                                             : g_wwf_l;
  float v = s[w];
  hf hh = __float2half_rn(v);
  h[w] = hh;
  l[w] = __float2half_rn(v - __half2float(hh));
}

// =============================================================================
// combine softmax partials (8 per row, 8 per col)
// =============================================================================
__global__ __launch_bounds__(256) void softmax_combine() {
  int t = blockIdx.x * 256 + threadIdx.x;
  const int total = KB * KN;
  if (t < total) {
    float m = -1e30f;
#pragma unroll
    for (int j = 0; j < 8; j++) m = fmaxf(m, g_prm[t * 8 + j]);
    float s = 0.f;
#pragma unroll
    for (int j = 0; j < 8; j++)
      s += g_prs[t * 8 + j] * __expf(g_prm[t * 8 + j] - m);
    g_rmax[t] = m;
    g_rsum[t] = s;
  } else if (t < 2 * total) {
    int u = t - total;
    float m = -1e30f;
#pragma unroll
    for (int j = 0; j < 8; j++) m = fmaxf(m, g_pcm[u * 8 + j]);
    float s = 0.f;
#pragma unroll
    for (int j = 0; j < 8; j++)
      s += g_pcs[u * 8 + j] * __expf(g_pcm[u * 8 + j] - m);
    g_cmax[u] = m;
    g_csum[u] = s;
  }
}

// =============================================================================
// BN combine + merged finalize (fp16 g_t16, 2 elems/thread)
// =============================================================================
__global__ __launch_bounds__(256) void bnfinal_kernel() {
  int t = blockIdx.x * 256 + threadIdx.x;
  if (t >= 2 * KC) return;
  float s = 0.f, s2 = 0.f;
  for (int j = 0; j < KB * 8; j++) {
    s += g_pbs[(size_t)t * (KB * 8) + j];
    s2 += g_pbs2[(size_t)t * (KB * 8) + j];
  }
  float m = s / (float)(KB * KN);
  float var = s2 / (float)(KB * KN) - m * m;
  g_mean[t] = m;
  g_rstd[t] = rsqrtf(var + 1e-5f);
}

__global__ __launch_bounds__(256) void finalize_kernel(
    const float* __restrict__ X0, const float* __restrict__ X1,
    const float* __restrict__ gamma0, const float* __restrict__ beta0,
    const float* __restrict__ gamma1, const float* __restrict__ beta1,
    float* __restrict__ Z) {
  size_t i2 = (size_t)blockIdx.x * 256 + threadIdx.x;
  size_t e = i2 * 2;
  int sel = (int)(e >> 23);
  size_t li = e & ((1ull << 23) - 1);
  int c = (int)((e >> 10) & (KC - 1));
  float m = g_mean[sel * KC + c];
  float r = g_rstd[sel * KC + c];
  float g = sel ? gamma1[c] : gamma0[c];
  float be = sel ? beta1[c] : beta0[c];
  __half2 t2 = *(__half2*)(g_t16 + e);
  float2 x2 = *(const float2*)((sel ? X1 : X0) + li);
  float2 o;
  o.x = (__low2float(t2) - m) * r * g + be + x2.x;
  o.y = (__high2float(t2) - m) * r * g + be + x2.y;
  *(float2*)(Z + e) = o;
}

// =============================================================================
extern "C" void kernel_launch(void* const* d_in, const int* in_sizes, int n_in,
                              void* d_out, int out_size) {
  const float* rgb        = (const float*)d_in[0];
  const float* flow       = (const float*)d_in[1];
  const float* wg_rgb     = (const float*)d_in[2];
  const float* bg_rgb     = (const float*)d_in[3];
  const float* wg_flow    = (const float*)d_in[4];
  const float* bg_flow    = (const float*)d_in[5];
  const float* ww_rgb     = (const float*)d_in[6];
  const float* bw_rgb     = (const float*)d_in[7];
  const float* gamma_rgb  = (const float*)d_in[8];
  const float* beta_rgb   = (const float*)d_in[9];
  const float* ww_flow    = (const float*)d_in[10];
  const float* bw_flow    = (const float*)d_in[11];
  const float* gamma_flow = (const float*)d_in[12];
  const float* beta_flow  = (const float*)d_in[13];
  float* out = (float*)d_out;

#define SYM(p, g) cudaGetSymbolAddress((void**)&p, g)
  hf *wgr_h, *wgr_l, *wgf_h, *wgf_l, *wwr_h, *wwr_l, *wwf_h, *wwf_l;
  hf *re_h, *fe_h, *reT_h, *reT_l, *feT_h, *feT_l, *yrT_h, *yfT_h, *pt16;
  float *pS, *prmax, *prsum, *pcmax, *pcsum;
  float *pprm, *pprs, *ppcm, *ppcs, *ppbs, *ppbs2;
  SYM(wgr_h, g_wgr_h); SYM(wgr_l, g_wgr_l);
  SYM(wgf_h, g_wgf_h); SYM(wgf_l, g_wgf_l);
  SYM(wwr_h, g_wwr_h); SYM(wwr_l, g_wwr_l);
  SYM(wwf_h, g_wwf_h); SYM(wwf_l, g_wwf_l);
  SYM(re_h, g_re_h); SYM(fe_h, g_fe_h);
  SYM(reT_h, g_reT_h); SYM(reT_l, g_reT_l);
  SYM(feT_h, g_feT_h); SYM(feT_l, g_feT_l);
  SYM(yrT_h, g_yrT_h); SYM(yfT_h, g_yfT_h);
  SYM(pt16, g_t16);
  SYM(pS, g_S);
  SYM(prmax, g_rmax); SYM(prsum, g_rsum);
  SYM(pcmax, g_cmax); SYM(pcsum, g_csum);
  SYM(pprm, g_prm); SYM(pprs, g_prs);
  SYM(ppcm, g_pcm); SYM(ppcs, g_pcs);
  SYM(ppbs, g_pbs); SYM(ppbs2, g_pbs2);
#undef SYM

  cudaFuncSetAttribute(gemm_f16, cudaFuncAttributeMaxDynamicSharedMemorySize,
                       SMEM_DYN);
  dim3 thr(256);
  const unsigned long long sEN = (unsigned long long)KCI * KN;
  const unsigned long long sET = (unsigned long long)KN * KCI;
  const unsigned long long sXF = (unsigned long long)KC * KN;  // fp32 input
  const unsigned long long sSS = (unsigned long long)KN * KN;
  const unsigned long long sT = (unsigned long long)KC * KN;

  GArg z{};

  // 1) weight conversion
  convert_w<<<2048, thr>>>(wg_rgb, wg_flow, ww_rgb, ww_flow);

  // 2) merged embeds: B = fp32 input, asymmetric deep ident pipeline
  {
    GArg a0 = z, a1 = z;
    a0.Ah = wgr_h; a0.Al = wgr_l; a0.Bf = rgb; a0.bias = bg_rgb;
    a0.oNh = re_h; a0.oTh = reT_h; a0.oTl = reT_l; a0.bmode = 3;
    a1.Ah = wgf_h; a1.Al = wgf_l; a1.Bf = flow; a1.bias = bg_flow;
    a1.oNh = fe_h; a1.oTh = feT_h; a1.oTl = feT_l; a1.bmode = 3;
    gemm_f16<<<dim3(8, 2, 2 * KB), thr, SMEM_DYN>>>(
        a0, a1, 0ull, KC, sXF, KN, 0ull, 0, sEN, KN, sET, KCI, KC);
  }

  // 3) scores: A pair, B pair (3-term); S fp32 + both softmax partial sets
  {
    GArg a0 = z;
    a0.Ah = reT_h; a0.Al = reT_l; a0.Bh = feT_h;  // lo at Bh + KB*KN*KCI
    a0.oNf = pS;
    a0.prm = pprm; a0.prs = pprs; a0.pcm = ppcm; a0.pcs = ppcs;
    a0.bmode = 0;
    gemm_f16<<<dim3(8, 8, KB), thr, SMEM_DYN>>>(
        a0, a0, sET, KCI, sET, KCI, sSS, KN, 0ull, 0, 0ull, 0, KCI);
  }

  // 4) stats combine
  softmax_combine<<<(2 * KB * KN) / 256, thr>>>();

  // 5) merged applies: A single, B exp-single, deep pipeline; y^T single out
  {
    GArg a0 = z, a1 = z;
    a0.Ah = fe_h; a0.Bf = pS; a0.mxv = prmax; a0.sumv = prsum;
    a0.oTh = yrT_h; a0.bmode = 2; a0.trans = 0; a0.as = 1;
    a1.Ah = re_h; a1.Bf = pS; a1.mxv = pcmax; a1.sumv = pcsum;
    a1.oTh = yfT_h; a1.bmode = 2; a1.trans = 1; a1.as = 1;
    gemm_f16<<<dim3(8, 2, 2 * KB), thr, SMEM_DYN>>>(
        a0, a1, sEN, KN, sSS, KN, 0ull, 0, 0ull, 0, sET, KCI, KN);
  }

  // 6) merged conv2: A = W pair, B = yT single (2-term); fp16 out + BN part.
  //    NOTE: oNh strides go in the soN/ldoN slots (R14 bug was soN=0).
  {
    GArg a0 = z, a1 = z;
    a0.Ah = wwr_h; a0.Al = wwr_l; a0.Bh = yrT_h; a0.bias = bw_rgb;
    a0.oNh = pt16; a0.pbs = ppbs; a0.pbs2 = ppbs2; a0.bmode = 1;
    a1.Ah = wwf_h; a1.Al = wwf_l; a1.Bh = yfT_h; a1.bias = bw_flow;
    a1.oNh = pt16 + (size_t)KB * KC * KN;
    a1.pbs = ppbs + (size_t)KC * KB * 8;
    a1.pbs2 = ppbs2 + (size_t)KC * KB * 8;
    a1.bmode = 1;
    gemm_f16<<<dim3(8, 4, 2 * KB), thr, SMEM_DYN>>>(
        a0, a1, 0ull, KCI, sET, KCI, 0ull, 0, sT, KN, 0ull, 0, KCI);
  }

  // 7) BN combine + merged finalize (2 elems/thread)
  bnfinal_kernel<<<4, thr>>>();
  finalize_kernel<<<(KB * KC * KN) / 256, thr>>>(
      rgb, flow, gamma_rgb, beta_rgb, gamma_flow, beta_flow, out);
}

// round 17
// speedup vs baseline: 2.2369x; 1.0138x over previous
#include <cuda_runtime.h>
#include <cuda_fp16.h>
#include <cstdint>

#define KB 16
#define KC 512
#define KCI 256
#define KN 1024

typedef __half hf;

// ---------------- scratch (no allocs allowed -> __device__ globals) ----------
__device__ hf g_wgr_h[KCI * KC], g_wgr_l[KCI * KC];
__device__ hf g_wgf_h[KCI * KC], g_wgf_l[KCI * KC];
__device__ hf g_wwr_h[KC * KCI], g_wwr_l[KC * KCI];
__device__ hf g_wwf_h[KC * KCI], g_wwf_l[KC * KCI];
__device__ hf g_re_h[(size_t)KB * KCI * KN];   // apply A operand (single)
__device__ hf g_fe_h[(size_t)KB * KCI * KN];
__device__ hf g_reT_h[(size_t)KB * KN * KCI];  // scores A (single)
__device__ hf g_feT_h[(size_t)KB * KN * KCI];
__device__ hf g_feT_l[(size_t)KB * KN * KCI];
__device__ float g_S[(size_t)KB * KN * KN];
__device__ hf g_yrT_h[(size_t)KB * KN * KCI];  // y stored single
__device__ hf g_yfT_h[(size_t)KB * KN * KCI];
__device__ hf g_t16[2 * (size_t)KB * KC * KN];  // conv2 out, fp16 single
__device__ float g_mean[2 * KC];
__device__ float g_rstd[2 * KC];
__device__ float g_rmax[KB * KN], g_rsum[KB * KN];
__device__ float g_cmax[KB * KN], g_csum[KB * KN];
__device__ float g_prm[KB * KN * 8], g_prs[KB * KN * 8];
__device__ float g_pcm[KB * KN * 8], g_pcs[KB * KN * 8];
__device__ float g_pbs[2 * KC * KB * 8], g_pbs2[2 * KC * KB * 8];

// ============================ helpers ========================================
__device__ __forceinline__ uint32_t smem_u32(const void* p) {
  uint32_t a;
  asm("{ .reg .u64 t; cvta.to.shared.u64 t, %1; cvt.u32.u64 %0, t; }"
      : "=r"(a) : "l"(p));
  return a;
}

#define CP16(dst, src)                                                         \
  asm volatile("cp.async.cg.shared.global [%0], [%1], 16;" ::"r"(dst),         \
               "l"(src))
#define CP_COMMIT() asm volatile("cp.async.commit_group;")
#define CP_WAIT1() asm volatile("cp.async.wait_group 1;")
#define CP_WAIT2() asm volatile("cp.async.wait_group 2;")
#define CP_WAIT0() asm volatile("cp.async.wait_group 0;")

__device__ __forceinline__ void ldm_x4(uint32_t addr, uint32_t& r0,
                                       uint32_t& r1, uint32_t& r2,
                                       uint32_t& r3) {
  asm volatile(
      "ldmatrix.sync.aligned.m8n8.x4.shared.b16 {%0,%1,%2,%3}, [%4];"
      : "=r"(r0), "=r"(r1), "=r"(r2), "=r"(r3) : "r"(addr));
}

__device__ __forceinline__ void mma_f16(float* d, const uint32_t* a,
                                        const uint32_t* b) {
  asm volatile(
      "mma.sync.aligned.m16n8k16.row.col.f32.f16.f16.f32 "
      "{%0,%1,%2,%3}, {%4,%5,%6,%7}, {%8,%9}, {%0,%1,%2,%3};"
      : "+f"(d[0]), "+f"(d[1]), "+f"(d[2]), "+f"(d[3])
      : "r"(a[0]), "r"(a[1]), "r"(a[2]), "r"(a[3]), "r"(b[0]), "r"(b[1]));
}

__device__ __forceinline__ uint32_t sw128(uint32_t o) {
  return o ^ ((o >> 3) & 0x70);
}
// fold swizzle: two 64B logical rows per 128B phys row, SW128 on phys rows.
__device__ __forceinline__ uint32_t fold_off(int r, int byte) {
  uint32_t off = (uint32_t)(((r >> 1) << 7) + ((r & 1) << 6) + byte);
  return off ^ ((off >> 3) & 0x70);
}

// split two fp32 -> (hi half2, lo half2)
__device__ __forceinline__ void split2(float x, float y, uint32_t& h,
                                       uint32_t& l) {
  __half2 hh = __floats2half2_rn(x, y);
  __half2 ll = __floats2half2_rn(x - __low2float(hh), y - __high2float(hh));
  h = *(uint32_t*)&hh;
  l = *(uint32_t*)&ll;
}
__device__ __forceinline__ uint32_t pack2h(float x, float y) {
  __half2 hh = __floats2half2_rn(x, y);
  return *(uint32_t*)&hh;
}

__device__ __forceinline__ float4 lds128(uint32_t a) {
  float4 v;
  asm volatile("ld.shared.v4.f32 {%0,%1,%2,%3}, [%4];"
               : "=f"(v.x), "=f"(v.y), "=f"(v.z), "=f"(v.w) : "r"(a));
  return v;
}
__device__ __forceinline__ float lds32(uint32_t a) {
  float v;
  asm volatile("ld.shared.f32 %0, [%1];" : "=f"(v) : "r"(a));
  return v;
}
__device__ __forceinline__ void sts128(uint32_t a, uint32_t x, uint32_t y,
                                       uint32_t z, uint32_t w) {
  asm volatile("st.shared.v4.b32 [%0], {%1,%2,%3,%4};" ::"r"(a), "r"(x),
               "r"(y), "r"(z), "r"(w));
}

// smem layouts:
//   shallow (bmode 0/1): 3 stages; stride 24KB when (as || bmode==1)
//     bmode 0 + as: A 8K @0, B pair 16K @8K (hi) / @16K (lo)
//     bmode 1:      A pair 16K @0, B single 8K @16K
//   deep exp (bmode 2):  4 stages x 24KB (A hi 8K, B fp32 16K), pair @96K
//   deep id  (bmode 3):  A-pair 3 slots @0/16K/32K, B-fp32 2 slots @48K/64K,
//                        pair ping-pong @80K (p*16K: hi, +8192 lo)
#define OFF_PAIR 98304
#define OFF_ID_B 49152
#define OFF_ID_P 81920
#define SMEM_DYN (114688 + 1024)
#define PITCH 129

// bmode: 0 = B pair (fp16 hi/lo from global, explicit Bl), 1 = B single,
//        2 = B exp-single (fp32 src), 3 = B ident-pair (fp32 src, transposed)
struct GArg {
  const hf *Ah, *Al, *Bh, *Bl;
  const float *Bf, *mxv, *sumv, *bias;
  float *oNf;
  hf *oNh, *oTh, *oTl;
  float *prm, *prs, *pcm, *pcs, *pbs, *pbs2;
  int bmode, trans, as;  // as = A single (skip lo operand)
};

// stage one K=32 chunk into stage slot s (modes 0,1,2)
__device__ __forceinline__ void stage32(uint32_t u_sb, int s, uint32_t stride,
                                        uint32_t offB, const hf* Ah,
                                        const hf* Al, int lda, const hf* Bh,
                                        const hf* Bl, const float* Bf,
                                        int ldb, int tid, int k0, int bmode,
                                        int trans, int as) {
  uint32_t abase = u_sb + (uint32_t)s * stride;
  uint32_t bbase = abase + offB;
#pragma unroll
  for (int t = 0; t < 2; t++) {
    int idx = tid + (t << 8);
    int r = idx >> 2, q = idx & 3;
    uint32_t o = fold_off(r, q << 4);
    CP16(abase + o, Ah + (size_t)r * lda + k0 + (q << 3));
    if (!as) CP16(abase + 8192 + o, Al + (size_t)r * lda + k0 + (q << 3));
  }
  if (bmode == 2) {
    if (trans) {
#pragma unroll
      for (int t = 0; t < 4; t++) {
        int idx = tid + (t << 8);
        int r = idx >> 5, q = idx & 31;
        CP16(bbase + (r << 9) + (q << 4),
             Bf + (size_t)(k0 + r) * ldb + (q << 2));
      }
    } else {
#pragma unroll
      for (int t = 0; t < 4; t++) {
        int idx = tid + (t << 8);
        int r = idx >> 3, q = idx & 7;
        CP16(bbase + sw128((r << 7) + (q << 4)),
             Bf + (size_t)r * ldb + k0 + (q << 2));
      }
    }
  } else if (bmode == 1) {  // B single fp16
#pragma unroll
    for (int t = 0; t < 2; t++) {
      int idx = tid + (t << 8);
      int r = idx >> 2, q = idx & 3;
      CP16(bbase + fold_off(r, q << 4), Bh + (size_t)r * ldb + k0 + (q << 3));
    }
  } else {  // B pair fp16 (explicit Bl pointer)
#pragma unroll
    for (int t = 0; t < 2; t++) {
      int idx = tid + (t << 8);
      int r = idx >> 2, q = idx & 3;
      uint32_t o = fold_off(r, q << 4);
      CP16(bbase + o, Bh + (size_t)r * ldb + k0 + (q << 3));
      CP16(bbase + 8192 + o, Bl + (size_t)r * ldb + k0 + (q << 3));
    }
  }
}

// embed deep-id staging: A pair -> slot s%3 (16KB slots), B fp32 transposed
// -> slot s&1 (16KB slots at OFF_ID_B)
__device__ __forceinline__ void stage_id(uint32_t u_sb, int s, const hf* Ah,
                                         const hf* Al, int lda,
                                         const float* Bf, int ldb, int tid,
                                         int k0) {
  uint32_t abase = u_sb + (uint32_t)(s % 3) * 16384u;
  uint32_t bbase = u_sb + OFF_ID_B + (uint32_t)(s & 1) * 16384u;
#pragma unroll
  for (int t = 0; t < 2; t++) {
    int idx = tid + (t << 8);
    int r = idx >> 2, q = idx & 3;
    uint32_t o = fold_off(r, q << 4);
    CP16(abase + o, Ah + (size_t)r * lda + k0 + (q << 3));
    CP16(abase + 8192 + o, Al + (size_t)r * lda + k0 + (q << 3));
  }
#pragma unroll
  for (int t = 0; t < 4; t++) {
    int idx = tid + (t << 8);
    int r = idx >> 5, q = idx & 31;
    CP16(bbase + (r << 9) + (q << 4), Bf + (size_t)(k0 + r) * ldb + (q << 2));
  }
}

// exp convert, row-major source (m rows x 128B): -> single fp16
__device__ __forceinline__ void convert_exp(uint32_t srcb, uint32_t pb,
                                            int tid, float mx, float iv) {
  int m = tid >> 1, h = tid & 1;
  float v[16];
#pragma unroll
  for (int j = 0; j < 4; j++) {
    float4 x = lds128(srcb + sw128((m << 7) + (h << 6) + (j << 4)));
    v[4 * j] = x.x; v[4 * j + 1] = x.y; v[4 * j + 2] = x.z; v[4 * j + 3] = x.w;
  }
#pragma unroll
  for (int j = 0; j < 16; j++) v[j] = __expf(v[j] - mx) * iv;
  uint32_t w[8];
#pragma unroll
  for (int j = 0; j < 8; j++) w[j] = pack2h(v[2 * j], v[2 * j + 1]);
  sts128(pb + fold_off(m, h << 5), w[0], w[1], w[2], w[3]);
  sts128(pb + fold_off(m, (h << 5) + 16), w[4], w[5], w[6], w[7]);
}

// exp convert, transposed source (k rows x 512B) -> single fp16, rows = m
__device__ __forceinline__ void convert_expT(uint32_t srcb, uint32_t pb,
                                             int tid, float mx, float iv) {
  int m = tid & 127;
  int kg = (tid >> 7) << 4;
  float v[16];
#pragma unroll
  for (int j = 0; j < 16; j++)
    v[j] = lds32(srcb + (uint32_t)((kg + j) << 9) + (uint32_t)(m << 2));
#pragma unroll
  for (int j = 0; j < 16; j++) v[j] = __expf(v[j] - mx) * iv;
  uint32_t w[8];
#pragma unroll
  for (int j = 0; j < 8; j++) w[j] = pack2h(v[2 * j], v[2 * j + 1]);
  sts128(pb + fold_off(m, kg << 1), w[0], w[1], w[2], w[3]);
  sts128(pb + fold_off(m, (kg << 1) + 16), w[4], w[5], w[6], w[7]);
}

// identity convert, transposed source -> fp16 PAIR (hi at pb, lo at pb+8192)
__device__ __forceinline__ void convert_idT(uint32_t srcb, uint32_t pb,
                                            int tid) {
  int m = tid & 127;
  int kg = (tid >> 7) << 4;
  float v[16];
#pragma unroll
  for (int j = 0; j < 16; j++)
    v[j] = lds32(srcb + (uint32_t)((kg + j) << 9) + (uint32_t)(m << 2));
  uint32_t hw[8], lw[8];
#pragma unroll
  for (int j = 0; j < 8; j++) split2(v[2 * j], v[2 * j + 1], hw[j], lw[j]);
  uint32_t o0 = fold_off(m, kg << 1);
  uint32_t o1 = fold_off(m, (kg << 1) + 16);
  sts128(pb + o0, hw[0], hw[1], hw[2], hw[3]);
  sts128(pb + o1, hw[4], hw[5], hw[6], hw[7]);
  sts128(pb + 8192 + o0, lw[0], lw[1], lw[2], lw[3]);
  sts128(pb + 8192 + o1, lw[4], lw[5], lw[6], lw[7]);
}

// one K=32 chunk of MMAs
__device__ __forceinline__ void mma_chunk(uint32_t abase, uint32_t bh_base,
                                          uint32_t bl_base, bool bpair,
                                          bool asingle, float (*acc)[8][4],
                                          int wr, int wc, int aRow, int aCb,
                                          int bRow, int bCb) {
#pragma unroll
  for (int ks = 0; ks < 2; ks++) {
    int kb = ks << 5;
    uint32_t ah[2][4], al[2][4];
#pragma unroll
    for (int mi = 0; mi < 2; mi++) {
      int r = wr * 32 + mi * 16 + aRow;
      uint32_t o = fold_off(r, kb + aCb);
      ldm_x4(abase + o, ah[mi][0], ah[mi][1], ah[mi][2], ah[mi][3]);
      if (!asingle)
        ldm_x4(abase + 8192 + o, al[mi][0], al[mi][1], al[mi][2], al[mi][3]);
    }
#pragma unroll
    for (int ng = 0; ng < 4; ng++) {
      uint32_t bh2[4], bl2[4];
      int r = wc * 64 + ng * 16 + bRow;
      uint32_t o = fold_off(r, kb + bCb);
      ldm_x4(bh_base + o, bh2[0], bh2[1], bh2[2], bh2[3]);
      if (bpair) ldm_x4(bl_base + o, bl2[0], bl2[1], bl2[2], bl2[3]);
#pragma unroll
      for (int mi = 0; mi < 2; mi++)
#pragma unroll
        for (int ns = 0; ns < 2; ns++) {
          float* d = acc[mi][ng * 2 + ns];
          mma_f16(d, ah[mi], &bh2[ns * 2]);
          if (bpair) mma_f16(d, ah[mi], &bl2[ns * 2]);
          if (!asingle) mma_f16(d, al[mi], &bh2[ns * 2]);
        }
    }
  }
}

// =============================================================================
// fp16 HMMA GEMM: block 128x128, warp 32x64, K=32 chunks, 1 sync/chunk.
// =============================================================================
__global__ __launch_bounds__(256, 2) void gemm_f16(
    GArg a0, GArg a1,
    unsigned long long sA, int lda, unsigned long long sB, int ldb,
    unsigned long long soNf, int ldoNf,
    unsigned long long soN, int ldoN, unsigned long long soT, int ldoT,
    int K) {
  extern __shared__ __align__(1024) char s_dyn[];
  char* sb = (char*)(((uintptr_t)s_dyn + 1023) & ~(uintptr_t)1023);
  float* s_f32 = (float*)sb;  // epilogue staging [128][PITCH]
  uint32_t u_sb = smem_u32(sb);

  int tid = threadIdx.x;
  int wid = tid >> 5, lane = tid & 31;
  int wr = wid & 3, wc = wid >> 2;
  int half = blockIdx.z >> 4;
  int b = blockIdx.z & (KB - 1);
  int i0 = blockIdx.y * 128;
  int n0 = blockIdx.x * 128;
#define SEL(f) (half ? a1.f : a0.f)
  int bmode = SEL(bmode);
  int trans = SEL(trans);
  int as = SEL(as);

  const hf* Ah = SEL(Ah) + (size_t)b * sA + (size_t)i0 * lda;
  const hf* Al = as ? nullptr : SEL(Al) + (size_t)b * sA + (size_t)i0 * lda;
  const hf* Bh = nullptr;
  const hf* Bl = nullptr;
  const float* Bf = nullptr;
  if (bmode >= 2) {
    Bf = SEL(Bf) + (size_t)b * sB;
    if (bmode == 3 || trans) Bf += n0;
    else Bf += (size_t)n0 * ldb;
  } else {
    Bh = SEL(Bh) + (size_t)b * sB + (size_t)n0 * ldb;
    if (bmode == 0) Bl = SEL(Bl) + (size_t)b * sB + (size_t)n0 * ldb;
  }

  float mxe = 0.f, ive = 1.f;
  if (bmode == 2) {
    const float* mxv = SEL(mxv);
    const float* sumv = SEL(sumv);
    int mrow = trans ? (tid & 127) : (tid >> 1);
    mxe = mxv[b * KN + n0 + mrow];
    ive = 1.0f / sumv[b * KN + n0 + mrow];
  }

  int aRow = lane & 15, aCb = (lane >> 4) * 16;
  int bRow = ((lane >> 4) & 1) * 8 + (lane & 7);
  int bCb = ((lane >> 3) & 1) * 16;

  float acc[2][8][4];
#pragma unroll
  for (int mi = 0; mi < 2; mi++)
#pragma unroll
    for (int ni = 0; ni < 8; ni++)
#pragma unroll
      for (int e = 0; e < 4; e++) acc[mi][ni][e] = 0.f;

  int NC = K >> 5;

  if (bmode == 2) {
    // ---- 4-slot deep pipeline, exp convert-ahead, 1 sync/chunk ----
    const uint32_t stride = 24576u, offB = 8192u;
#pragma unroll
    for (int p = 0; p < 3; p++) {
      stage32(u_sb, p, stride, offB, Ah, Al, lda, Bh, Bl, Bf, ldb, tid,
              p << 5, bmode, trans, as);
      CP_COMMIT();
    }
    CP_WAIT2();
    __syncthreads();
    {
      uint32_t pb = u_sb + OFF_PAIR;
      if (trans) convert_expT(u_sb + offB, pb, tid, mxe, ive);
      else convert_exp(u_sb + offB, pb, tid, mxe, ive);
    }
    for (int ch = 0; ch < NC; ch++) {
      CP_WAIT1();
      __syncthreads();
      if (ch + 3 < NC)
        stage32(u_sb, (ch + 3) & 3, stride, offB, Ah, Al, lda, Bh, Bl, Bf,
                ldb, tid, (ch + 3) << 5, bmode, trans, as);
      CP_COMMIT();
      if (ch + 1 < NC) {
        uint32_t srcb = u_sb + (uint32_t)((ch + 1) & 3) * stride + offB;
        uint32_t pb = u_sb + OFF_PAIR + (((ch + 1) & 1) << 13);
        if (trans) convert_expT(srcb, pb, tid, mxe, ive);
        else convert_exp(srcb, pb, tid, mxe, ive);
      }
      uint32_t abase = u_sb + (uint32_t)(ch & 3) * stride;
      uint32_t bh_base = u_sb + OFF_PAIR + ((ch & 1) << 13);
      mma_chunk(abase, bh_base, 0u, false, true, acc, wr, wc, aRow, aCb, bRow,
                bCb);
    }
  } else if (bmode == 3) {
    // ---- asymmetric deep pipeline (A x3, B x2), ident pair, 1 sync/chunk ---
    stage_id(u_sb, 0, Ah, Al, lda, Bf, ldb, tid, 0);
    CP_COMMIT();
    stage_id(u_sb, 1, Ah, Al, lda, Bf, ldb, tid, 32);
    CP_COMMIT();
    CP_WAIT1();
    __syncthreads();
    convert_idT(u_sb + OFF_ID_B, u_sb + OFF_ID_P, tid);  // chunk 0 -> pair 0
    for (int ch = 0; ch < NC; ch++) {
      CP_WAIT0();
      __syncthreads();
      if (ch + 2 < NC)
        stage_id(u_sb, ch + 2, Ah, Al, lda, Bf, ldb, tid, (ch + 2) << 5);
      CP_COMMIT();
      if (ch + 1 < NC) {
        uint32_t srcb = u_sb + OFF_ID_B + (uint32_t)((ch + 1) & 1) * 16384u;
        uint32_t pb = u_sb + OFF_ID_P + (uint32_t)((ch + 1) & 1) * 16384u;
        convert_idT(srcb, pb, tid);
      }
      uint32_t abase = u_sb + (uint32_t)(ch % 3) * 16384u;
      uint32_t pb = u_sb + OFF_ID_P + (uint32_t)(ch & 1) * 16384u;
      mma_chunk(abase, pb, pb + 8192, true, false, acc, wr, wc, aRow, aCb,
                bRow, bCb);
    }
  } else {
    // ---- 3-slot pipeline (bmode 0/1); compact 24KB stride when possible ----
    const uint32_t stride = (as || bmode == 1) ? 24576u : 32768u;
    const uint32_t offB = as ? 8192u : 16384u;
    stage32(u_sb, 0, stride, offB, Ah, Al, lda, Bh, Bl, Bf, ldb, tid, 0,
            bmode, trans, as);
    CP_COMMIT();
    stage32(u_sb, 1, stride, offB, Ah, Al, lda, Bh, Bl, Bf, ldb, tid, 32,
            bmode, trans, as);
    CP_COMMIT();
    int sl = 0, sl2 = 2;
    for (int ch = 0; ch < NC; ch++) {
      CP_WAIT1();
      __syncthreads();
      if (ch + 2 < NC)
        stage32(u_sb, sl2, stride, offB, Ah, Al, lda, Bh, Bl, Bf, ldb, tid,
                (ch + 2) << 5, bmode, trans, as);
      CP_COMMIT();
      uint32_t sbase = u_sb + (uint32_t)sl * stride;
      mma_chunk(sbase, sbase + offB, sbase + offB + 8192, bmode == 0,
                as != 0, acc, wr, wc, aRow, aCb, bRow, bCb);
      sl = (sl == 2) ? 0 : sl + 1;
      sl2 = (sl2 == 2) ? 0 : sl2 + 1;
    }
  }
  CP_WAIT0();
  __syncthreads();

  // --------------------------- epilogue --------------------------------------
  const float* bias = SEL(bias);
#pragma unroll
  for (int mi = 0; mi < 2; mi++) {
    int rl = wr * 32 + mi * 16 + (lane >> 2);
    float bv0 = bias ? __ldg(bias + i0 + rl) : 0.f;
    float bv1 = bias ? __ldg(bias + i0 + rl + 8) : 0.f;
#pragma unroll
    for (int ni = 0; ni < 8; ni++) {
      int c = wc * 64 + ni * 8 + 2 * (lane & 3);
      s_f32[rl * PITCH + c] = acc[mi][ni][0] + bv0;
      s_f32[rl * PITCH + c + 1] = acc[mi][ni][1] + bv0;
      s_f32[(rl + 8) * PITCH + c] = acc[mi][ni][2] + bv1;
      s_f32[(rl + 8) * PITCH + c + 1] = acc[mi][ni][3] + bv1;
    }
  }
  __syncthreads();

  if (float* oNf = SEL(oNf)) {
    float* on = oNf + (size_t)b * soNf;
#pragma unroll
    for (int t = 0; t < 16; t++) {
      int idx = tid + (t << 8);
      int rr = idx >> 5, q = idx & 31;
      float4 v;
      v.x = s_f32[rr * PITCH + q * 4 + 0];
      v.y = s_f32[rr * PITCH + q * 4 + 1];
      v.z = s_f32[rr * PITCH + q * 4 + 2];
      v.w = s_f32[rr * PITCH + q * 4 + 3];
      *(float4*)(on + (size_t)(i0 + rr) * ldoNf + n0 + (q << 2)) = v;
    }
  }
  if (hf* oNh = SEL(oNh)) {  // single fp16 normal-layout output
    hf* oh = oNh + (size_t)b * soN;
#pragma unroll
    for (int t = 0; t < 16; t++) {
      int idx = tid + (t << 8);
      int rr = idx >> 5, q = idx & 31;
      uint32_t h0 = pack2h(s_f32[rr * PITCH + q * 4 + 0],
                           s_f32[rr * PITCH + q * 4 + 1]);
      uint32_t h1 = pack2h(s_f32[rr * PITCH + q * 4 + 2],
                           s_f32[rr * PITCH + q * 4 + 3]);
      size_t base = (size_t)(i0 + rr) * ldoN + n0 + (q << 2);
      *(uint32_t*)(oh + base) = h0;
      *(uint32_t*)(oh + base + 2) = h1;
    }
  }
  if (hf* oTh = SEL(oTh)) {  // transposed output: pair if oTl, else single
    hf* oh = oTh + (size_t)b * soT;
    hf* ol = SEL(oTl);
    if (ol) ol += (size_t)b * soT;
#pragma unroll
    for (int t = 0; t < 16; t++) {
      int idx = tid + (t << 8);
      int c = idx >> 5, rq = (idx & 31) << 2;
      size_t base = (size_t)(n0 + c) * ldoT + i0 + rq;
      if (ol) {
        uint32_t h0, l0, h1, l1;
        split2(s_f32[(rq + 0) * PITCH + c], s_f32[(rq + 1) * PITCH + c], h0,
               l0);
        split2(s_f32[(rq + 2) * PITCH + c], s_f32[(rq + 3) * PITCH + c], h1,
               l1);
        *(uint32_t*)(oh + base) = h0;
        *(uint32_t*)(oh + base + 2) = h1;
        *(uint32_t*)(ol + base) = l0;
        *(uint32_t*)(ol + base + 2) = l1;
      } else {
        uint32_t h0 = pack2h(s_f32[(rq + 0) * PITCH + c],
                             s_f32[(rq + 1) * PITCH + c]);
        uint32_t h1 = pack2h(s_f32[(rq + 2) * PITCH + c],
                             s_f32[(rq + 3) * PITCH + c]);
        *(uint32_t*)(oh + base) = h0;
        *(uint32_t*)(oh + base + 2) = h1;
      }
    }
  }
  if (float* prm = SEL(prm)) {
    {  // row partials: 2 threads per row
      int r = tid >> 1, hh = tid & 1;
      float pm = -1e30f;
#pragma unroll 8
      for (int j = 0; j < 64; j++) {
        int c = hh * 64 + ((j + 16 * hh) & 63);
        pm = fmaxf(pm, s_f32[r * PITCH + c]);
      }
      pm = fmaxf(pm, __shfl_xor_sync(0xffffffffu, pm, 1));
      float ps = 0.f;
#pragma unroll 8
      for (int j = 0; j < 64; j++) {
        int c = hh * 64 + ((j + 16 * hh) & 63);
        ps += __expf(s_f32[r * PITCH + c] - pm);
      }
      ps += __shfl_xor_sync(0xffffffffu, ps, 1);
      if (hh == 0) {
        size_t o = (size_t)(b * KN + i0 + r) * gridDim.x + blockIdx.x;
        prm[o] = pm;
        SEL(prs)[o] = ps;
      }
    }
    {  // col partials: 2 threads per col
      int c = tid >> 1, hh = tid & 1;
      float pm = -1e30f;
#pragma unroll 8
      for (int j = 0; j < 64; j++) {
        int r = hh * 64 + ((j + (c & 31)) & 63);
        pm = fmaxf(pm, s_f32[r * PITCH + c]);
      }
      pm = fmaxf(pm, __shfl_xor_sync(0xffffffffu, pm, 1));
      float ps = 0.f;
#pragma unroll 8
      for (int j = 0; j < 64; j++) {
        int r = hh * 64 + ((j + (c & 31)) & 63);
        ps += __expf(s_f32[r * PITCH + c] - pm);
      }
      ps += __shfl_xor_sync(0xffffffffu, ps, 1);
      if (hh == 0) {
        size_t o = (size_t)(b * KN + n0 + c) * gridDim.y + blockIdx.y;
        SEL(pcm)[o] = pm;
        SEL(pcs)[o] = ps;
      }
    }
  }
  if (float* pbs = SEL(pbs)) {  // BN partials: 2 threads per row
    int r = tid >> 1, hh = tid & 1;
    float s = 0.f, s2 = 0.f;
#pragma unroll 8
    for (int j = 0; j < 64; j++) {
      int c = hh * 64 + ((j + 16 * hh) & 63);
      float v = s_f32[r * PITCH + c];
      s += v;
      s2 += v * v;
    }
    s += __shfl_xor_sync(0xffffffffu, s, 1);
    s2 += __shfl_xor_sync(0xffffffffu, s2, 1);
    if (hh == 0) {
      size_t o = ((size_t)(i0 + r) * KB + b) * gridDim.x + blockIdx.x;
      pbs[o] = s;
      SEL(pbs2)[o] = s2;
    }
  }
#undef SEL
}

// =============================================================================
// convert 4 weight matrices (each 131072 elems) to hi/lo
// =============================================================================
__global__ __launch_bounds__(256) void convert_w(
    const float* __restrict__ s0, const float* __restrict__ s1,
    const float* __restrict__ s2, const float* __restrict__ s3) {
  int idx = blockIdx.x * 256 + threadIdx.x;
  int sel = idx >> 17, w = idx & 131071;
  const float* s = sel == 0 ? s0 : sel == 1 ? s1 : sel == 2 ? s2 : s3;
  hf* h = sel == 0 ? g_wgr_h : sel == 1 ? g_wgf_h : sel == 2 ? g_wwr_h
                                                             : g_wwf_h;
  hf* l = sel == 0 ? g_wgr_l : sel == 1 ? g_wgf_l : sel == 2 ? g_wwr_l
                                                             : g_wwf_l;
  float v = s[w];
  hf hh = __float2half_rn(v);
  h[w] = hh;
  l[w] = __float2half_rn(v - __half2float(hh));
}

// =============================================================================
// combine softmax partials (8 per row, 8 per col)
// =============================================================================
__global__ __launch_bounds__(256) void softmax_combine() {
  int t = blockIdx.x * 256 + threadIdx.x;
  const int total = KB * KN;
  if (t < total) {
    float m = -1e30f;
#pragma unroll
    for (int j = 0; j < 8; j++) m = fmaxf(m, g_prm[t * 8 + j]);
    float s = 0.f;
#pragma unroll
    for (int j = 0; j < 8; j++)
      s += g_prs[t * 8 + j] * __expf(g_prm[t * 8 + j] - m);
    g_rmax[t] = m;
    g_rsum[t] = s;
  } else if (t < 2 * total) {
    int u = t - total;
    float m = -1e30f;
#pragma unroll
    for (int j = 0; j < 8; j++) m = fmaxf(m, g_pcm[u * 8 + j]);
    float s = 0.f;
#pragma unroll
    for (int j = 0; j < 8; j++)
      s += g_pcs[u * 8 + j] * __expf(g_pcm[u * 8 + j] - m);
    g_cmax[u] = m;
    g_csum[u] = s;
  }
}

// =============================================================================
// BN combine + merged finalize (fp16 g_t16, 2 elems/thread)
// =============================================================================
__global__ __launch_bounds__(256) void bnfinal_kernel() {
  int t = blockIdx.x * 256 + threadIdx.x;
  if (t >= 2 * KC) return;
  float s = 0.f, s2 = 0.f;
  for (int j = 0; j < KB * 8; j++) {
    s += g_pbs[(size_t)t * (KB * 8) + j];
    s2 += g_pbs2[(size_t)t * (KB * 8) + j];
  }
  float m = s / (float)(KB * KN);
  float var = s2 / (float)(KB * KN) - m * m;
  g_mean[t] = m;
  g_rstd[t] = rsqrtf(var + 1e-5f);
}

__global__ __launch_bounds__(256) void finalize_kernel(
    const float* __restrict__ X0, const float* __restrict__ X1,
    const float* __restrict__ gamma0, const float* __restrict__ beta0,
    const float* __restrict__ gamma1, const float* __restrict__ beta1,
    float* __restrict__ Z) {
  size_t i2 = (size_t)blockIdx.x * 256 + threadIdx.x;
  size_t e = i2 * 2;
  int sel = (int)(e >> 23);
  size_t li = e & ((1ull << 23) - 1);
  int c = (int)((e >> 10) & (KC - 1));
  float m = g_mean[sel * KC + c];
  float r = g_rstd[sel * KC + c];
  float g = sel ? gamma1[c] : gamma0[c];
  float be = sel ? beta1[c] : beta0[c];
  __half2 t2 = *(__half2*)(g_t16 + e);
  float2 x2 = *(const float2*)((sel ? X1 : X0) + li);
  float2 o;
  o.x = (__low2float(t2) - m) * r * g + be + x2.x;
  o.y = (__high2float(t2) - m) * r * g + be + x2.y;
  *(float2*)(Z + e) = o;
}

// =============================================================================
extern "C" void kernel_launch(void* const* d_in, const int* in_sizes, int n_in,
                              void* d_out, int out_size) {
  const float* rgb        = (const float*)d_in[0];
  const float* flow       = (const float*)d_in[1];
  const float* wg_rgb     = (const float*)d_in[2];
  const float* bg_rgb     = (const float*)d_in[3];
  const float* wg_flow    = (const float*)d_in[4];
  const float* bg_flow    = (const float*)d_in[5];
  const float* ww_rgb     = (const float*)d_in[6];
  const float* bw_rgb     = (const float*)d_in[7];
  const float* gamma_rgb  = (const float*)d_in[8];
  const float* beta_rgb   = (const float*)d_in[9];
  const float* ww_flow    = (const float*)d_in[10];
  const float* bw_flow    = (const float*)d_in[11];
  const float* gamma_flow = (const float*)d_in[12];
  const float* beta_flow  = (const float*)d_in[13];
  float* out = (float*)d_out;

#define SYM(p, g) cudaGetSymbolAddress((void**)&p, g)
  hf *wgr_h, *wgr_l, *wgf_h, *wgf_l, *wwr_h, *wwr_l, *wwf_h, *wwf_l;
  hf *re_h, *fe_h, *reT_h, *feT_h, *feT_l, *yrT_h, *yfT_h, *pt16;
  float *pS, *prmax, *prsum, *pcmax, *pcsum;
  float *pprm, *pprs, *ppcm, *ppcs, *ppbs, *ppbs2;
  SYM(wgr_h, g_wgr_h); SYM(wgr_l, g_wgr_l);
  SYM(wgf_h, g_wgf_h); SYM(wgf_l, g_wgf_l);
  SYM(wwr_h, g_wwr_h); SYM(wwr_l, g_wwr_l);
  SYM(wwf_h, g_wwf_h); SYM(wwf_l, g_wwf_l);
  SYM(re_h, g_re_h); SYM(fe_h, g_fe_h);
  SYM(reT_h, g_reT_h);
  SYM(feT_h, g_feT_h); SYM(feT_l, g_feT_l);
  SYM(yrT_h, g_yrT_h); SYM(yfT_h, g_yfT_h);
  SYM(pt16, g_t16);
  SYM(pS, g_S);
  SYM(prmax, g_rmax); SYM(prsum, g_rsum);
  SYM(pcmax, g_cmax); SYM(pcsum, g_csum);
  SYM(pprm, g_prm); SYM(pprs, g_prs);
  SYM(ppcm, g_pcm); SYM(ppcs, g_pcs);
  SYM(ppbs, g_pbs); SYM(ppbs2, g_pbs2);
#undef SYM

  cudaFuncSetAttribute(gemm_f16, cudaFuncAttributeMaxDynamicSharedMemorySize,
                       SMEM_DYN);
  dim3 thr(256);
  const unsigned long long sEN = (unsigned long long)KCI * KN;
  const unsigned long long sET = (unsigned long long)KN * KCI;
  const unsigned long long sXF = (unsigned long long)KC * KN;  // fp32 input
  const unsigned long long sSS = (unsigned long long)KN * KN;
  const unsigned long long sT = (unsigned long long)KC * KN;

  GArg z{};

  // 1) weight conversion
  convert_w<<<2048, thr>>>(wg_rgb, wg_flow, ww_rgb, ww_flow);

  // 2) merged embeds: B = fp32 input, asymmetric deep ident pipeline.
  //    rgb half: reT stored SINGLE (scores A is single); flow half: pair.
  {
    GArg a0 = z, a1 = z;
    a0.Ah = wgr_h; a0.Al = wgr_l; a0.Bf = rgb; a0.bias = bg_rgb;
    a0.oNh = re_h; a0.oTh = reT_h; a0.oTl = nullptr; a0.bmode = 3;
    a1.Ah = wgf_h; a1.Al = wgf_l; a1.Bf = flow; a1.bias = bg_flow;
    a1.oNh = fe_h; a1.oTh = feT_h; a1.oTl = feT_l; a1.bmode = 3;
    gemm_f16<<<dim3(8, 2, 2 * KB), thr, SMEM_DYN>>>(
        a0, a1, 0ull, KC, sXF, KN, 0ull, 0, sEN, KN, sET, KCI, KC);
  }

  // 3) scores: A SINGLE (reT_h), B pair w/ explicit Bl (2-term); S fp32 +
  //    softmax partials
  {
    GArg a0 = z;
    a0.Ah = reT_h; a0.Bh = feT_h; a0.Bl = feT_l;
    a0.oNf = pS;
    a0.prm = pprm; a0.prs = pprs; a0.pcm = ppcm; a0.pcs = ppcs;
    a0.bmode = 0; a0.as = 1;
    gemm_f16<<<dim3(8, 8, KB), thr, SMEM_DYN>>>(
        a0, a0, sET, KCI, sET, KCI, sSS, KN, 0ull, 0, 0ull, 0, KCI);
  }

  // 4) stats combine
  softmax_combine<<<(2 * KB * KN) / 256, thr>>>();

  // 5) merged applies: A single, B exp-single, deep pipeline; y^T single out
  {
    GArg a0 = z, a1 = z;
    a0.Ah = fe_h; a0.Bf = pS; a0.mxv = prmax; a0.sumv = prsum;
    a0.oTh = yrT_h; a0.bmode = 2; a0.trans = 0; a0.as = 1;
    a1.Ah = re_h; a1.Bf = pS; a1.mxv = pcmax; a1.sumv = pcsum;
    a1.oTh = yfT_h; a1.bmode = 2; a1.trans = 1; a1.as = 1;
    gemm_f16<<<dim3(8, 2, 2 * KB), thr, SMEM_DYN>>>(
        a0, a1, sEN, KN, sSS, KN, 0ull, 0, 0ull, 0, sET, KCI, KN);
  }

  // 6) merged conv2: A = W pair, B = yT single (2-term); fp16 out + BN part.
  {
    GArg a0 = z, a1 = z;
    a0.Ah = wwr_h; a0.Al = wwr_l; a0.Bh = yrT_h; a0.bias = bw_rgb;
    a0.oNh = pt16; a0.pbs = ppbs; a0.pbs2 = ppbs2; a0.bmode = 1;
    a1.Ah = wwf_h; a1.Al = wwf_l; a1.Bh = yfT_h; a1.bias = bw_flow;
    a1.oNh = pt16 + (size_t)KB * KC * KN;
    a1.pbs = ppbs + (size_t)KC * KB * 8;
    a1.pbs2 = ppbs2 + (size_t)KC * KB * 8;
    a1.bmode = 1;
    gemm_f16<<<dim3(8, 4, 2 * KB), thr, SMEM_DYN>>>(
        a0, a1, 0ull, KCI, sET, KCI, 0ull, 0, sT, KN, 0ull, 0, KCI);
  }

  // 7) BN combine + merged finalize (2 elems/thread)
  bnfinal_kernel<<<4, thr>>>();
  finalize_kernel<<<(KB * KC * KN) / 256, thr>>>(
      rgb, flow, gamma_rgb, beta_rgb, gamma_flow, beta_flow, out);
}